// round 1
// baseline (speedup 1.0000x reference)
#include <cuda_runtime.h>
#include <cstdint>
#include <cstddef>

// ----------------------------------------------------------------------------
// Problem constants: B=2, T=2048, C=1024, H=16, hs=64
//   M = B*T = 4096 rows everywhere.
// ----------------------------------------------------------------------------

#define MROWS 4096
#define CDIM  1024
#define FDIM  4096
#define TLEN  2048
#define NHEAD 16
#define HS    64

// Scratch (device globals; allocation-free per harness rules)
__device__ float g_h1[MROWS * CDIM];          // LN1 output
__device__ float g_q [MROWS * CDIM];          // [B,H,T,hs]
__device__ float g_kk[MROWS * CDIM];
__device__ float g_v [MROWS * CDIM];
__device__ float g_attn[MROWS * CDIM];        // [B,H,T,hs]
__device__ float g_x1[MROWS * CDIM];          // x + sa
__device__ float g_h2[MROWS * CDIM];          // LN2 output
__device__ float g_ff1[(size_t)MROWS * FDIM]; // relu(h2 @ Wff1 + b)

// ----------------------------------------------------------------------------
// LayerNorm: one block per row (1024 elems, 256 threads x 4)
// mode 0: in = x (param), out = g_h1 ; mode 1: in = g_x1, out = g_h2
// ----------------------------------------------------------------------------
__global__ void __launch_bounds__(256) ln_k(int mode, const float* __restrict__ x_ext,
                                            const float* __restrict__ g,
                                            const float* __restrict__ b)
{
    const float* in = (mode == 0) ? x_ext : g_x1;
    float* out      = (mode == 0) ? g_h1  : g_h2;

    int row = blockIdx.x;
    int tid = threadIdx.x;
    size_t base = (size_t)row * CDIM;

    float v[4];
    float s = 0.f, s2 = 0.f;
#pragma unroll
    for (int i = 0; i < 4; i++) {
        v[i] = in[base + tid + i * 256];
        s  += v[i];
        s2 += v[i] * v[i];
    }
    // warp reduce
#pragma unroll
    for (int off = 16; off; off >>= 1) {
        s  += __shfl_xor_sync(0xffffffffu, s,  off);
        s2 += __shfl_xor_sync(0xffffffffu, s2, off);
    }
    __shared__ float rs[8], rs2[8];
    int warp = tid >> 5, lane = tid & 31;
    if (lane == 0) { rs[warp] = s; rs2[warp] = s2; }
    __syncthreads();
    __shared__ float mu_s, rstd_s;
    if (tid == 0) {
        float ts = 0.f, ts2 = 0.f;
#pragma unroll
        for (int i = 0; i < 8; i++) { ts += rs[i]; ts2 += rs2[i]; }
        float mu  = ts * (1.f / CDIM);
        float var = ts2 * (1.f / CDIM) - mu * mu;
        mu_s = mu;
        rstd_s = rsqrtf(var + 1e-5f);
    }
    __syncthreads();
    float mu = mu_s, rstd = rstd_s;
#pragma unroll
    for (int i = 0; i < 4; i++) {
        int c = tid + i * 256;
        out[base + c] = (v[i] - mu) * rstd * g[c] + b[c];
    }
}

// ----------------------------------------------------------------------------
// Generic tiled SGEMM (128x128 tile, BK=16, 256 threads, 8x8 micro-tile)
// MODE 0: QKV   A=g_h1[4096,1024], B=Wq/Wk/Wv [H,C,hs] (z selects), out=[B,H,T,hs]
// MODE 1: proj  A=g_attn (head-concat remap), B=Wproj[1024,1024],
//               out = g_x1 = acc + bproj + x
// MODE 2: ff1   A=g_h2, B=Wff1[1024,4096], out = g_ff1 = relu(acc + b)
// MODE 3: ff2   A=g_ff1[4096,4096], B=Wff2[4096,1024], out = d_out = acc + b + g_x1
// ----------------------------------------------------------------------------
template <int MODE>
__global__ void __launch_bounds__(256) gemm_k(const float* __restrict__ W0,
                                              const float* __restrict__ W1,
                                              const float* __restrict__ W2,
                                              const float* __restrict__ bias,
                                              const float* __restrict__ resid,
                                              float* __restrict__ outp)
{
    constexpr int K = (MODE == 3) ? 4096 : 1024;
    constexpr int N = (MODE == 2) ? 4096 : 1024;

    __shared__ float As[16][129];  // As[k][m], +1 pad kills write conflicts
    __shared__ float Bs[16][128];  // Bs[k][n]

    const int tid = threadIdx.x;
    const int tx = tid & 15, ty = tid >> 4;
    const int m0 = blockIdx.y * 128;
    const int n0 = blockIdx.x * 128;

    const float* A;
    if      (MODE == 0) A = g_h1;
    else if (MODE == 1) A = g_attn;
    else if (MODE == 2) A = g_h2;
    else                A = g_ff1;

    const float* Bmat;
    if (MODE == 0)
        Bmat = (blockIdx.z == 0) ? W0 : ((blockIdx.z == 1) ? W1 : W2);
    else
        Bmat = W0;

    float acc[8][8] = {};

    for (int k0 = 0; k0 < K; k0 += 16) {
        // A tile: As[k][m] = A(m0+m, k0+k)
#pragma unroll
        for (int i = 0; i < 8; i++) {
            int idx = tid + i * 256;
            int m = idx >> 4, k = idx & 15;
            float val;
            if (MODE == 1) {
                int gm = m0 + m, gk = k0 + k;
                int b = gm >> 11, t = gm & 2047;
                int h = gk >> 6, d = gk & 63;
                val = A[(size_t)(((b << 4) + h) << 17) + (t << 6) + d];
            } else {
                val = A[(size_t)(m0 + m) * K + (k0 + k)];
            }
            As[k][m] = val;
        }
        // B tile: Bs[k][n] = B(k0+k, n0+n)
#pragma unroll
        for (int i = 0; i < 8; i++) {
            int idx = tid + i * 256;
            int k = idx >> 7, n = idx & 127;
            float val;
            if (MODE == 0) {
                int gn = n0 + n, gk = k0 + k;
                int h = gn >> 6, d = gn & 63;
                val = Bmat[(size_t)((h << 10) + gk) * 64 + d];
            } else {
                val = Bmat[(size_t)(k0 + k) * N + (n0 + n)];
            }
            Bs[k][n] = val;
        }
        __syncthreads();
#pragma unroll
        for (int k = 0; k < 16; k++) {
            float a[8], bb[8];
#pragma unroll
            for (int i = 0; i < 4; i++) {
                a[i]     = As[k][ty * 4 + i];
                a[i + 4] = As[k][64 + ty * 4 + i];
            }
#pragma unroll
            for (int j = 0; j < 4; j++) {
                bb[j]     = Bs[k][tx * 4 + j];
                bb[j + 4] = Bs[k][64 + tx * 4 + j];
            }
#pragma unroll
            for (int i = 0; i < 8; i++)
#pragma unroll
                for (int j = 0; j < 8; j++)
                    acc[i][j] += a[i] * bb[j];
        }
        __syncthreads();
    }

    // epilogue
#pragma unroll
    for (int i = 0; i < 8; i++) {
        int m = m0 + ((i < 4) ? (ty * 4 + i) : (64 + ty * 4 + (i - 4)));
#pragma unroll
        for (int j = 0; j < 8; j++) {
            int n = n0 + ((j < 4) ? (tx * 4 + j) : (64 + tx * 4 + (j - 4)));
            float v = acc[i][j];
            if (MODE == 0) {
                int b = m >> 11, t = m & 2047;
                int h = n >> 6, d = n & 63;
                float* o = (blockIdx.z == 0) ? g_q : ((blockIdx.z == 1) ? g_kk : g_v);
                o[(size_t)(((b << 4) + h) << 17) + (t << 6) + d] = v;
            } else if (MODE == 1) {
                v += bias[n] + resid[(size_t)m * 1024 + n];
                g_x1[(size_t)m * 1024 + n] = v;
            } else if (MODE == 2) {
                v = fmaxf(v + bias[n], 0.f);
                g_ff1[(size_t)m * 4096 + n] = v;
            } else {
                v += bias[n] + g_x1[(size_t)m * 1024 + n];
                outp[(size_t)m * 1024 + n] = v;
            }
        }
    }
}

// ----------------------------------------------------------------------------
// Causal flash attention.
// Grid: (T/128, H, B). Block: 128 threads; thread t owns query row R0+t.
// q[64], acc[64] in registers; 32-key K/V tiles + score buffer in smem (32KB).
// ----------------------------------------------------------------------------
__global__ void __launch_bounds__(128) attn_k()
{
    __shared__ float Ks[32][64];
    __shared__ float Vs[32][64];
    __shared__ float Ss[32][128];

    const int tid = threadIdx.x;
    const int bh = blockIdx.z * NHEAD + blockIdx.y;
    const int R0 = blockIdx.x * 128;
    const int r = R0 + tid;
    const size_t base = (size_t)bh * TLEN * HS;

    float q[64], acc[64];
#pragma unroll
    for (int d = 0; d < 64; d++) {
        q[d] = g_q[base + (size_t)r * 64 + d];
        acc[d] = 0.f;
    }

    float m = -1e30f, l = 0.f;
    const int ktmax = (R0 + 127) >> 5;  // inclusive last 32-key tile

    for (int kt = 0; kt <= ktmax; kt++) {
        __syncthreads();
        const float* kp = &g_kk[base + (size_t)kt * 32 * 64];
        const float* vp = &g_v [base + (size_t)kt * 32 * 64];
#pragma unroll
        for (int i = 0; i < 16; i++) {
            ((float*)Ks)[tid + i * 128] = kp[tid + i * 128];
            ((float*)Vs)[tid + i * 128] = vp[tid + i * 128];
        }
        __syncthreads();

        float tmax = -1e30f;
#pragma unroll 1
        for (int j = 0; j < 32; j++) {
            float s = 0.f;
#pragma unroll
            for (int d = 0; d < 64; d++) s += q[d] * Ks[j][d];
            s *= 0.125f;  // hs^-0.5
            if (kt * 32 + j > r) s = -1e30f;
            Ss[j][tid] = s;
            tmax = fmaxf(tmax, s);
        }

        float mnew = fmaxf(m, tmax);
        float corr = __expf(m - mnew);
        l *= corr;
#pragma unroll
        for (int d = 0; d < 64; d++) acc[d] *= corr;

#pragma unroll 1
        for (int j = 0; j < 32; j++) {
            float p = __expf(Ss[j][tid] - mnew);
            l += p;
#pragma unroll
            for (int d = 0; d < 64; d++) acc[d] += p * Vs[j][d];
        }
        m = mnew;
    }

    float inv = 1.f / l;
#pragma unroll
    for (int d = 0; d < 64; d++)
        g_attn[base + (size_t)r * 64 + d] = acc[d] * inv;
}

// ----------------------------------------------------------------------------
// Launch
// Inputs: 0:x 1:Wq 2:Wk 3:Wv 4:Wproj 5:bproj 6:g1 7:b1 8:g2 9:b2
//         10:W_ff1 11:b_ff1 12:W_ff2 13:b_ff2
// ----------------------------------------------------------------------------
extern "C" void kernel_launch(void* const* d_in, const int* in_sizes, int n_in,
                              void* d_out, int out_size)
{
    const float* x     = (const float*)d_in[0];
    const float* Wq    = (const float*)d_in[1];
    const float* Wk    = (const float*)d_in[2];
    const float* Wv    = (const float*)d_in[3];
    const float* Wproj = (const float*)d_in[4];
    const float* bproj = (const float*)d_in[5];
    const float* g1    = (const float*)d_in[6];
    const float* b1    = (const float*)d_in[7];
    const float* g2    = (const float*)d_in[8];
    const float* b2    = (const float*)d_in[9];
    const float* Wff1  = (const float*)d_in[10];
    const float* bff1  = (const float*)d_in[11];
    const float* Wff2  = (const float*)d_in[12];
    const float* bff2  = (const float*)d_in[13];
    float* out = (float*)d_out;

    // LN1
    ln_k<<<MROWS, 256>>>(0, x, g1, b1);
    // QKV (z = 0/1/2 -> q/k/v)
    gemm_k<0><<<dim3(CDIM / 128, MROWS / 128, 3), 256>>>(Wq, Wk, Wv, nullptr, nullptr, nullptr);
    // Attention
    attn_k<<<dim3(TLEN / 128, NHEAD, 2), 128>>>();
    // Proj + bias + residual -> g_x1
    gemm_k<1><<<dim3(CDIM / 128, MROWS / 128), 256>>>(Wproj, nullptr, nullptr, bproj, x, nullptr);
    // LN2
    ln_k<<<MROWS, 256>>>(1, nullptr, g2, b2);
    // FFN1 + relu -> g_ff1
    gemm_k<2><<<dim3(FDIM / 128, MROWS / 128), 256>>>(Wff1, nullptr, nullptr, bff1, nullptr, nullptr);
    // FFN2 + bias + residual -> out
    gemm_k<3><<<dim3(CDIM / 128, MROWS / 128), 256>>>(Wff2, nullptr, nullptr, bff2, nullptr, out);
}

// round 3
// speedup vs baseline: 1.2142x; 1.2142x over previous
#include <cuda_runtime.h>
#include <cstdint>
#include <cstddef>

// ----------------------------------------------------------------------------
// B=2, T=2048, C=1024, H=16, hs=64 ; M = B*T = 4096
// ----------------------------------------------------------------------------
#define MROWS 4096
#define CDIM  1024
#define FDIM  4096
#define TLEN  2048
#define NHEAD 16
#define HS    64

// Scratch (device globals; allocation-free per harness rules)
__device__ float g_h1[MROWS * CDIM];
__device__ float g_q [MROWS * CDIM];          // [B,H,T,hs]
__device__ float g_kk[MROWS * CDIM];
__device__ float g_v [MROWS * CDIM];
__device__ float g_attn[MROWS * CDIM];        // row-major [m][c]
__device__ float g_x1[MROWS * CDIM];
__device__ float g_h2[MROWS * CDIM];
__device__ float g_ff1[(size_t)MROWS * FDIM];
// Transposed weights: Bt[n][k] row-major
__device__ float g_wqT[CDIM * CDIM];
__device__ float g_wkT[CDIM * CDIM];
__device__ float g_wvT[CDIM * CDIM];
__device__ float g_wpT[CDIM * CDIM];
__device__ float g_wf1T[(size_t)CDIM * FDIM];
__device__ float g_wf2T[(size_t)CDIM * FDIM];

// ----------------------------------------------------------------------------
// Helpers (baseline sm_80+ instructions only; NO tcgen05 / 'a'-suffix features)
// ----------------------------------------------------------------------------
__device__ __forceinline__ uint32_t smem_u32(const void* p) {
    return (uint32_t)__cvta_generic_to_shared(p);
}
__device__ __forceinline__ void cp16(uint32_t dst, const void* src) {
    asm volatile("cp.async.cg.shared.global [%0], [%1], 16;\n" :: "r"(dst), "l"(src));
}
__device__ __forceinline__ void cp_commit() {
    asm volatile("cp.async.commit_group;\n" ::: "memory");
}
__device__ __forceinline__ void cp_wait2() {
    asm volatile("cp.async.wait_group 2;\n" ::: "memory");
}
__device__ __forceinline__ uint32_t f2tf(float f) {
    uint32_t u;
    asm("cvt.rna.tf32.f32 %0, %1;" : "=r"(u) : "f"(f));
    return u;
}
__device__ __forceinline__ void mma8(float* d, const uint32_t* a, const uint32_t* b) {
    asm volatile(
        "mma.sync.aligned.m16n8k8.row.col.f32.tf32.tf32.f32 "
        "{%0,%1,%2,%3},{%4,%5,%6,%7},{%8,%9},{%0,%1,%2,%3};"
        : "+f"(d[0]), "+f"(d[1]), "+f"(d[2]), "+f"(d[3])
        : "r"(a[0]), "r"(a[1]), "r"(a[2]), "r"(a[3]), "r"(b[0]), "r"(b[1]));
}

// ----------------------------------------------------------------------------
// LayerNorm
// ----------------------------------------------------------------------------
__global__ void __launch_bounds__(256) ln_k(int mode, const float* __restrict__ x_ext,
                                            const float* __restrict__ g,
                                            const float* __restrict__ b)
{
    const float* in = (mode == 0) ? x_ext : g_x1;
    float* out      = (mode == 0) ? g_h1  : g_h2;
    int row = blockIdx.x;
    int tid = threadIdx.x;
    size_t base = (size_t)row * CDIM;

    float v[4];
    float s = 0.f, s2 = 0.f;
#pragma unroll
    for (int i = 0; i < 4; i++) {
        v[i] = in[base + tid + i * 256];
        s += v[i]; s2 += v[i] * v[i];
    }
#pragma unroll
    for (int off = 16; off; off >>= 1) {
        s  += __shfl_xor_sync(0xffffffffu, s,  off);
        s2 += __shfl_xor_sync(0xffffffffu, s2, off);
    }
    __shared__ float rs[8], rs2[8];
    int warp = tid >> 5, lane = tid & 31;
    if (lane == 0) { rs[warp] = s; rs2[warp] = s2; }
    __syncthreads();
    __shared__ float mu_s, rstd_s;
    if (tid == 0) {
        float ts = 0.f, ts2 = 0.f;
#pragma unroll
        for (int i = 0; i < 8; i++) { ts += rs[i]; ts2 += rs2[i]; }
        float mu = ts * (1.f / CDIM);
        float var = ts2 * (1.f / CDIM) - mu * mu;
        mu_s = mu; rstd_s = rsqrtf(var + 1e-5f);
    }
    __syncthreads();
    float mu = mu_s, rstd = rstd_s;
#pragma unroll
    for (int i = 0; i < 4; i++) {
        int c = tid + i * 256;
        out[base + c] = (v[i] - mu) * rstd * g[c] + b[c];
    }
}

// ----------------------------------------------------------------------------
// Batched 32x32 tiled transpose: in [batch][R][Cc] -> out [batch][Cc][R]
// ----------------------------------------------------------------------------
__global__ void __launch_bounds__(256) transpose_k(const float* __restrict__ in,
                                                   int outsel, int R, int Cc)
{
    __shared__ float t[32][33];
    float* outg;
    switch (outsel) {
        case 0: outg = g_wqT; break;
        case 1: outg = g_wkT; break;
        case 2: outg = g_wvT; break;
        case 3: outg = g_wpT; break;
        case 4: outg = g_wf1T; break;
        default: outg = g_wf2T; break;
    }
    int batch = blockIdx.z;
    const float* ip = in + (size_t)batch * R * Cc;
    float* op = outg + (size_t)batch * R * Cc;
    int c0 = blockIdx.x * 32, r0 = blockIdx.y * 32;
    int tx = threadIdx.x & 31, ty = threadIdx.x >> 5;
#pragma unroll
    for (int i = 0; i < 32; i += 8)
        t[ty + i][tx] = ip[(size_t)(r0 + ty + i) * Cc + c0 + tx];
    __syncthreads();
#pragma unroll
    for (int i = 0; i < 32; i += 8)
        op[(size_t)(c0 + ty + i) * R + r0 + tx] = t[tx][ty + i];
}

// ----------------------------------------------------------------------------
// tf32 mma.sync GEMM: C[128,128] tile = A[M,K] (row-major) @ Bt[N,K]^T
// 256 threads = 8 warps (2 x 4): each warp 64x32, m16n8k8 frags, BK=32,
// 4-stage cp.async pipeline. Smem rows padded to 36 floats (conflict-free).
// MODE 0: A=g_h1,  Bt=wq/wk/wvT (z), out -> g_q/g_kk/g_v as [B,H,T,hs]
// MODE 1: A=g_attn,Bt=g_wpT,  out -> g_x1 = acc + bias + resid(x)
// MODE 2: A=g_h2,  Bt=g_wf1T, out -> g_ff1 = relu(acc + bias)    (N=4096)
// MODE 3: A=g_ff1 (K=4096), Bt=g_wf2T, out -> outp = acc + bias + g_x1
// ----------------------------------------------------------------------------
#define STG_FLOATS (128 * 36)             // one operand tile per stage
#define MG_SMEM    (4 * 2 * STG_FLOATS * 4)  // 4 stages * (A+B) * 4B = 147456

template <int MODE>
__global__ void __launch_bounds__(256) mgemm(const float* __restrict__ bias,
                                             const float* __restrict__ resid,
                                             float* __restrict__ outp)
{
    constexpr int K = (MODE == 3) ? 4096 : 1024;
    constexpr int NKIT = K / 32;

    extern __shared__ float sm[];
    const int tid = threadIdx.x, lane = tid & 31, wid = tid >> 5;
    const int wm = wid & 1, wn = wid >> 1;   // warp tile: rows wm*64, cols wn*32
    const int m0 = blockIdx.y * 128;
    const int n0 = blockIdx.x * 128;

    const float* A;
    if      (MODE == 0) A = g_h1;
    else if (MODE == 1) A = g_attn;
    else if (MODE == 2) A = g_h2;
    else                A = g_ff1;

    const float* B;
    if (MODE == 0) B = (blockIdx.z == 0) ? g_wqT : ((blockIdx.z == 1) ? g_wkT : g_wvT);
    else if (MODE == 1) B = g_wpT;
    else if (MODE == 2) B = g_wf1T;
    else                B = g_wf2T;

    float acc[4][4][4] = {};

    auto load_stage = [&](int j, int s) {
        float* As = sm + s * (2 * STG_FLOATS);
        float* Bs = As + STG_FLOATS;
#pragma unroll
        for (int i = 0; i < 4; i++) {
            int c = tid + i * 256;          // 0..1023
            int row = c >> 3, kc = c & 7;   // 8 x 16B chunks per 32-float row
            cp16(smem_u32(As + row * 36 + kc * 4),
                 A + (size_t)(m0 + row) * K + j * 32 + kc * 4);
            cp16(smem_u32(Bs + row * 36 + kc * 4),
                 B + (size_t)(n0 + row) * K + j * 32 + kc * 4);
        }
        cp_commit();
    };

    load_stage(0, 0);
    load_stage(1, 1);
    load_stage(2, 2);

    for (int it = 0; it < NKIT; it++) {
        int s = it & 3;
        cp_wait2();
        __syncthreads();
        if (it + 3 < NKIT) load_stage(it + 3, (it + 3) & 3);
        else cp_commit();   // keep group-count invariant for cp_wait2

        const float* As = sm + s * (2 * STG_FLOATS);
        const float* Bs = As + STG_FLOATS;

#pragma unroll
        for (int ks = 0; ks < 4; ks++) {
            const int k0 = ks * 8 + (lane & 3);
            uint32_t af[4][4], bf[4][2];
#pragma unroll
            for (int mi = 0; mi < 4; mi++) {
                const float* p = As + (wm * 64 + mi * 16 + (lane >> 2)) * 36 + k0;
                af[mi][0] = f2tf(p[0]);
                af[mi][1] = f2tf(p[8 * 36]);
                af[mi][2] = f2tf(p[4]);
                af[mi][3] = f2tf(p[8 * 36 + 4]);
            }
#pragma unroll
            for (int nj = 0; nj < 4; nj++) {
                const float* p = Bs + (wn * 32 + nj * 8 + (lane >> 2)) * 36 + k0;
                bf[nj][0] = f2tf(p[0]);
                bf[nj][1] = f2tf(p[4]);
            }
#pragma unroll
            for (int mi = 0; mi < 4; mi++)
#pragma unroll
                for (int nj = 0; nj < 4; nj++)
                    mma8(acc[mi][nj], af[mi], bf[nj]);
        }
    }

    // epilogue: d0:(r,c) d1:(r,c+1) d2:(r+8,c) d3:(r+8,c+1)
#pragma unroll
    for (int mi = 0; mi < 4; mi++) {
#pragma unroll
        for (int nj = 0; nj < 4; nj++) {
#pragma unroll
            for (int half = 0; half < 2; half++) {
                int gm = m0 + wm * 64 + mi * 16 + (lane >> 2) + half * 8;
                int gn = n0 + wn * 32 + nj * 8 + (lane & 3) * 2;
                float v0 = acc[mi][nj][half * 2 + 0];
                float v1 = acc[mi][nj][half * 2 + 1];
                if (MODE == 0) {
                    float* sel = (blockIdx.z == 0) ? g_q : ((blockIdx.z == 1) ? g_kk : g_v);
                    int bb = gm >> 11, t = gm & 2047;
                    int h = gn >> 6, d0 = gn & 63;
                    float* op = sel + ((size_t)((bb * 16 + h) * 2048 + t)) * 64 + d0;
                    op[0] = v0; op[1] = v1;
                } else if (MODE == 1) {
                    size_t o = (size_t)gm * 1024 + gn;
                    g_x1[o]     = v0 + bias[gn]     + resid[o];
                    g_x1[o + 1] = v1 + bias[gn + 1] + resid[o + 1];
                } else if (MODE == 2) {
                    size_t o = (size_t)gm * 4096 + gn;
                    g_ff1[o]     = fmaxf(v0 + bias[gn],     0.f);
                    g_ff1[o + 1] = fmaxf(v1 + bias[gn + 1], 0.f);
                } else {
                    size_t o = (size_t)gm * 1024 + gn;
                    outp[o]     = v0 + bias[gn]     + g_x1[o];
                    outp[o + 1] = v1 + bias[gn + 1] + g_x1[o + 1];
                }
            }
        }
    }
}

// ----------------------------------------------------------------------------
// Causal flash attention (SIMT; output row-major [m][c])
// ----------------------------------------------------------------------------
__global__ void __launch_bounds__(128) attn_k()
{
    __shared__ float Ks[32][64];
    __shared__ float Vs[32][64];
    __shared__ float Ss[32][128];

    const int tid = threadIdx.x;
    const int bh = blockIdx.z * NHEAD + blockIdx.y;
    const int R0 = blockIdx.x * 128;
    const int r = R0 + tid;
    const size_t base = (size_t)bh * TLEN * HS;

    float q[64], acc[64];
#pragma unroll
    for (int d = 0; d < 64; d++) {
        q[d] = g_q[base + (size_t)r * 64 + d];
        acc[d] = 0.f;
    }

    float m = -1e30f, l = 0.f;
    const int ktmax = (R0 + 127) >> 5;

    for (int kt = 0; kt <= ktmax; kt++) {
        __syncthreads();
        const float* kp = &g_kk[base + (size_t)kt * 32 * 64];
        const float* vp = &g_v [base + (size_t)kt * 32 * 64];
#pragma unroll
        for (int i = 0; i < 16; i++) {
            ((float*)Ks)[tid + i * 128] = kp[tid + i * 128];
            ((float*)Vs)[tid + i * 128] = vp[tid + i * 128];
        }
        __syncthreads();

        float tmax = -1e30f;
#pragma unroll 1
        for (int j = 0; j < 32; j++) {
            float s = 0.f;
#pragma unroll
            for (int d = 0; d < 64; d++) s += q[d] * Ks[j][d];
            s *= 0.125f;
            if (kt * 32 + j > r) s = -1e30f;
            Ss[j][tid] = s;
            tmax = fmaxf(tmax, s);
        }

        float mnew = fmaxf(m, tmax);
        float corr = __expf(m - mnew);
        l *= corr;
#pragma unroll
        for (int d = 0; d < 64; d++) acc[d] *= corr;

#pragma unroll 1
        for (int j = 0; j < 32; j++) {
            float p = __expf(Ss[j][tid] - mnew);
            l += p;
#pragma unroll
            for (int d = 0; d < 64; d++) acc[d] += p * Vs[j][d];
        }
        m = mnew;
    }

    float inv = 1.f / l;
    size_t obase = (size_t)(blockIdx.z * TLEN + r) * CDIM + blockIdx.y * HS;
#pragma unroll
    for (int d = 0; d < 64; d++)
        g_attn[obase + d] = acc[d] * inv;
}

// ----------------------------------------------------------------------------
// Launch
// ----------------------------------------------------------------------------
extern "C" void kernel_launch(void* const* d_in, const int* in_sizes, int n_in,
                              void* d_out, int out_size)
{
    const float* x     = (const float*)d_in[0];
    const float* Wq    = (const float*)d_in[1];
    const float* Wk    = (const float*)d_in[2];
    const float* Wv    = (const float*)d_in[3];
    const float* Wproj = (const float*)d_in[4];
    const float* bproj = (const float*)d_in[5];
    const float* g1    = (const float*)d_in[6];
    const float* b1    = (const float*)d_in[7];
    const float* g2    = (const float*)d_in[8];
    const float* b2    = (const float*)d_in[9];
    const float* Wff1  = (const float*)d_in[10];
    const float* bff1  = (const float*)d_in[11];
    const float* Wff2  = (const float*)d_in[12];
    const float* bff2  = (const float*)d_in[13];
    float* out = (float*)d_out;

    cudaFuncSetAttribute(mgemm<0>, cudaFuncAttributeMaxDynamicSharedMemorySize, MG_SMEM);
    cudaFuncSetAttribute(mgemm<1>, cudaFuncAttributeMaxDynamicSharedMemorySize, MG_SMEM);
    cudaFuncSetAttribute(mgemm<2>, cudaFuncAttributeMaxDynamicSharedMemorySize, MG_SMEM);
    cudaFuncSetAttribute(mgemm<3>, cudaFuncAttributeMaxDynamicSharedMemorySize, MG_SMEM);

    // Weight transposes -> Bt [N,K]
    transpose_k<<<dim3(HS / 32, CDIM / 32, NHEAD), 256>>>(Wq, 0, CDIM, HS);
    transpose_k<<<dim3(HS / 32, CDIM / 32, NHEAD), 256>>>(Wk, 1, CDIM, HS);
    transpose_k<<<dim3(HS / 32, CDIM / 32, NHEAD), 256>>>(Wv, 2, CDIM, HS);
    transpose_k<<<dim3(CDIM / 32, CDIM / 32, 1),   256>>>(Wproj, 3, CDIM, CDIM);
    transpose_k<<<dim3(FDIM / 32, CDIM / 32, 1),   256>>>(Wff1, 4, CDIM, FDIM);
    transpose_k<<<dim3(CDIM / 32, FDIM / 32, 1),   256>>>(Wff2, 5, FDIM, CDIM);

    // LN1
    ln_k<<<MROWS, 256>>>(0, x, g1, b1);
    // QKV (z selects q/k/v)
    mgemm<0><<<dim3(CDIM / 128, MROWS / 128, 3), 256, MG_SMEM>>>(nullptr, nullptr, nullptr);
    // Attention
    attn_k<<<dim3(TLEN / 128, NHEAD, 2), 128>>>();
    // Proj + bias + residual -> g_x1
    mgemm<1><<<dim3(CDIM / 128, MROWS / 128), 256, MG_SMEM>>>(bproj, x, nullptr);
    // LN2
    ln_k<<<MROWS, 256>>>(1, nullptr, g2, b2);
    // FFN1 + relu
    mgemm<2><<<dim3(FDIM / 128, MROWS / 128), 256, MG_SMEM>>>(bff1, nullptr, nullptr);
    // FFN2 + bias + residual -> out
    mgemm<3><<<dim3(CDIM / 128, MROWS / 128), 256, MG_SMEM>>>(bff2, nullptr, out);
}

// round 4
// speedup vs baseline: 2.1637x; 1.7820x over previous
#include <cuda_runtime.h>
#include <cstdint>
#include <cstddef>

// ----------------------------------------------------------------------------
// B=2, T=2048, C=1024, H=16, hs=64 ; M = B*T = 4096
// ----------------------------------------------------------------------------
#define MROWS 4096
#define CDIM  1024
#define FDIM  4096
#define TLEN  2048
#define NHEAD 16
#define HS    64

__device__ float g_h1[MROWS * CDIM];          // tf32-rounded
__device__ float g_q [MROWS * CDIM];          // [B,H,T,hs] fp32
__device__ float g_kk[MROWS * CDIM];
__device__ float g_v [MROWS * CDIM];
__device__ float g_attn[MROWS * CDIM];        // row-major, tf32-rounded
__device__ float g_x1[MROWS * CDIM];          // fp32 (residual path)
__device__ float g_h2[MROWS * CDIM];          // tf32-rounded
__device__ float g_ff1[(size_t)MROWS * FDIM]; // tf32-rounded
__device__ float g_wqT[CDIM * CDIM];          // Bt[n][k], tf32-rounded
__device__ float g_wkT[CDIM * CDIM];
__device__ float g_wvT[CDIM * CDIM];
__device__ float g_wpT[CDIM * CDIM];
__device__ float g_wf1T[(size_t)CDIM * FDIM];
__device__ float g_wf2T[(size_t)CDIM * FDIM];

// ----------------------------------------------------------------------------
// Helpers (baseline sm_80+; NO tcgen05)
// ----------------------------------------------------------------------------
__device__ __forceinline__ uint32_t smem_u32(const void* p) {
    return (uint32_t)__cvta_generic_to_shared(p);
}
__device__ __forceinline__ void cp16(uint32_t dst, const void* src) {
    asm volatile("cp.async.cg.shared.global [%0], [%1], 16;\n" :: "r"(dst), "l"(src));
}
__device__ __forceinline__ void cp_commit() {
    asm volatile("cp.async.commit_group;\n" ::: "memory");
}
__device__ __forceinline__ void cp_wait2() {
    asm volatile("cp.async.wait_group 2;\n" ::: "memory");
}
__device__ __forceinline__ float f2tf_f(float f) {
    uint32_t u;
    asm("cvt.rna.tf32.f32 %0, %1;" : "=r"(u) : "f"(f));
    return __uint_as_float(u);
}
__device__ __forceinline__ void mma8(float* d, const uint32_t* a, const uint32_t* b) {
    asm volatile(
        "mma.sync.aligned.m16n8k8.row.col.f32.tf32.tf32.f32 "
        "{%0,%1,%2,%3},{%4,%5,%6,%7},{%8,%9},{%0,%1,%2,%3};"
        : "+f"(d[0]), "+f"(d[1]), "+f"(d[2]), "+f"(d[3])
        : "r"(a[0]), "r"(a[1]), "r"(a[2]), "r"(a[3]), "r"(b[0]), "r"(b[1]));
}
__device__ __forceinline__ void ldsm_x4(uint32_t* r, uint32_t addr) {
    asm volatile("ldmatrix.sync.aligned.m8n8.x4.shared.b16 {%0,%1,%2,%3}, [%4];"
                 : "=r"(r[0]), "=r"(r[1]), "=r"(r[2]), "=r"(r[3]) : "r"(addr));
}
__device__ __forceinline__ void ldsm_x2(uint32_t* r, uint32_t addr) {
    asm volatile("ldmatrix.sync.aligned.m8n8.x2.shared.b16 {%0,%1}, [%2];"
                 : "=r"(r[0]), "=r"(r[1]) : "r"(addr));
}

// ----------------------------------------------------------------------------
// LayerNorm (writes tf32-rounded output; consumed only by GEMMs)
// ----------------------------------------------------------------------------
__global__ void __launch_bounds__(256) ln_k(int mode, const float* __restrict__ x_ext,
                                            const float* __restrict__ g,
                                            const float* __restrict__ b)
{
    const float* in = (mode == 0) ? x_ext : g_x1;
    float* out      = (mode == 0) ? g_h1  : g_h2;
    int row = blockIdx.x;
    int tid = threadIdx.x;
    size_t base = (size_t)row * CDIM;

    float v[4];
    float s = 0.f, s2 = 0.f;
#pragma unroll
    for (int i = 0; i < 4; i++) {
        v[i] = in[base + tid + i * 256];
        s += v[i]; s2 += v[i] * v[i];
    }
#pragma unroll
    for (int off = 16; off; off >>= 1) {
        s  += __shfl_xor_sync(0xffffffffu, s,  off);
        s2 += __shfl_xor_sync(0xffffffffu, s2, off);
    }
    __shared__ float rs[8], rs2[8];
    int warp = tid >> 5, lane = tid & 31;
    if (lane == 0) { rs[warp] = s; rs2[warp] = s2; }
    __syncthreads();
    __shared__ float mu_s, rstd_s;
    if (tid == 0) {
        float ts = 0.f, ts2 = 0.f;
#pragma unroll
        for (int i = 0; i < 8; i++) { ts += rs[i]; ts2 += rs2[i]; }
        float mu = ts * (1.f / CDIM);
        float var = ts2 * (1.f / CDIM) - mu * mu;
        mu_s = mu; rstd_s = rsqrtf(var + 1e-5f);
    }
    __syncthreads();
    float mu = mu_s, rstd = rstd_s;
#pragma unroll
    for (int i = 0; i < 4; i++) {
        int c = tid + i * 256;
        out[base + c] = f2tf_f((v[i] - mu) * rstd * g[c] + b[c]);
    }
}

// ----------------------------------------------------------------------------
// Batched 32x32 transpose -> Bt[n][k], tf32-rounded
// ----------------------------------------------------------------------------
__global__ void __launch_bounds__(256) transpose_k(const float* __restrict__ in,
                                                   int outsel, int R, int Cc)
{
    __shared__ float t[32][33];
    float* outg;
    switch (outsel) {
        case 0: outg = g_wqT; break;
        case 1: outg = g_wkT; break;
        case 2: outg = g_wvT; break;
        case 3: outg = g_wpT; break;
        case 4: outg = g_wf1T; break;
        default: outg = g_wf2T; break;
    }
    int batch = blockIdx.z;
    const float* ip = in + (size_t)batch * R * Cc;
    float* op = outg + (size_t)batch * R * Cc;
    int c0 = blockIdx.x * 32, r0 = blockIdx.y * 32;
    int tx = threadIdx.x & 31, ty = threadIdx.x >> 5;
#pragma unroll
    for (int i = 0; i < 32; i += 8)
        t[ty + i][tx] = ip[(size_t)(r0 + ty + i) * Cc + c0 + tx];
    __syncthreads();
#pragma unroll
    for (int i = 0; i < 32; i += 8)
        op[(size_t)(c0 + ty + i) * R + r0 + tx] = f2tf_f(t[tx][ty + i]);
}

// ----------------------------------------------------------------------------
// tf32 mma.sync GEMM with ldmatrix fragment loads.
// C[128,128] tile; 256 thr = 8 warps (2x4), warp = 64x32; BK=32; 4-stage cp.async.
// Smem rows padded to 36 floats (144B pitch: LDSM- and STS-conflict-free).
// Operands are pre-rounded to tf32 by producers -> no CVT in hot loop.
// ----------------------------------------------------------------------------
#define STG_FLOATS (128 * 36)
#define MG_SMEM    (4 * 2 * STG_FLOATS * 4)  // 147456 B

template <int MODE>
__global__ void __launch_bounds__(256) mgemm(const float* __restrict__ bias,
                                             const float* __restrict__ resid,
                                             float* __restrict__ outp)
{
    constexpr int K = (MODE == 3) ? 4096 : 1024;
    constexpr int NKIT = K / 32;

    extern __shared__ float sm[];
    const int tid = threadIdx.x, lane = tid & 31, wid = tid >> 5;
    const int wm = wid & 1, wn = wid >> 1;   // warp tile rows wm*64, cols wn*32
    const int m0 = blockIdx.y * 128;
    const int n0 = blockIdx.x * 128;

    const float* A;
    if      (MODE == 0) A = g_h1;
    else if (MODE == 1) A = g_attn;
    else if (MODE == 2) A = g_h2;
    else                A = g_ff1;

    const float* B;
    if (MODE == 0) B = (blockIdx.z == 0) ? g_wqT : ((blockIdx.z == 1) ? g_wkT : g_wvT);
    else if (MODE == 1) B = g_wpT;
    else if (MODE == 2) B = g_wf1T;
    else                B = g_wf2T;

    float acc[4][4][4] = {};

    auto load_stage = [&](int j, int s) {
        float* As = sm + s * (2 * STG_FLOATS);
        float* Bs = As + STG_FLOATS;
#pragma unroll
        for (int i = 0; i < 4; i++) {
            int c = tid + i * 256;
            int row = c >> 3, kc = c & 7;
            cp16(smem_u32(As + row * 36 + kc * 4),
                 A + (size_t)(m0 + row) * K + j * 32 + kc * 4);
            cp16(smem_u32(Bs + row * 36 + kc * 4),
                 B + (size_t)(n0 + row) * K + j * 32 + kc * 4);
        }
        cp_commit();
    };

    // ldmatrix lane->address offsets (in floats, relative to stage A/B base)
    // A x4: m0: rows 0-7 k0-3 | m1: rows 8-15 k0-3 | m2: rows 0-7 k4-7 | m3: rows 8-15 k4-7
    const int arow = (lane & 7) + ((lane >> 3) & 1) * 8;
    const int ahalf = (lane >> 4) & 1;
    uint32_t offA[4], offB[4];
#pragma unroll
    for (int mi = 0; mi < 4; mi++)
        offA[mi] = ((wm * 64 + mi * 16 + arow) * 36 + ahalf * 4) * 4;
    // B x2: m0: rows n0..n7 k0-3 | m1: same rows k4-7
    const int brow = lane & 7;
    const int bhalf = (lane >> 3) & 1;
#pragma unroll
    for (int nj = 0; nj < 4; nj++)
        offB[nj] = ((wn * 32 + nj * 8 + brow) * 36 + bhalf * 4) * 4;

    load_stage(0, 0);
    load_stage(1, 1);
    load_stage(2, 2);

    for (int it = 0; it < NKIT; it++) {
        int s = it & 3;
        cp_wait2();
        __syncthreads();
        if (it + 3 < NKIT) load_stage(it + 3, (it + 3) & 3);
        else cp_commit();

        uint32_t AsU = smem_u32(sm + s * (2 * STG_FLOATS));
        uint32_t BsU = AsU + STG_FLOATS * 4;

#pragma unroll
        for (int ks = 0; ks < 4; ks++) {
            uint32_t af[4][4], bf[4][2];
#pragma unroll
            for (int mi = 0; mi < 4; mi++) ldsm_x4(af[mi], AsU + offA[mi] + ks * 32);
#pragma unroll
            for (int nj = 0; nj < 4; nj++) ldsm_x2(bf[nj], BsU + offB[nj] + ks * 32);
#pragma unroll
            for (int mi = 0; mi < 4; mi++)
#pragma unroll
                for (int nj = 0; nj < 4; nj++)
                    mma8(acc[mi][nj], af[mi], bf[nj]);
        }
    }

    // epilogue: d0:(r,c) d1:(r,c+1) d2:(r+8,c) d3:(r+8,c+1)
#pragma unroll
    for (int mi = 0; mi < 4; mi++) {
#pragma unroll
        for (int nj = 0; nj < 4; nj++) {
#pragma unroll
            for (int half = 0; half < 2; half++) {
                int gm = m0 + wm * 64 + mi * 16 + (lane >> 2) + half * 8;
                int gn = n0 + wn * 32 + nj * 8 + (lane & 3) * 2;
                float v0 = acc[mi][nj][half * 2 + 0];
                float v1 = acc[mi][nj][half * 2 + 1];
                if (MODE == 0) {
                    float* sel = (blockIdx.z == 0) ? g_q : ((blockIdx.z == 1) ? g_kk : g_v);
                    int bb = gm >> 11, t = gm & 2047;
                    int h = gn >> 6, d0 = gn & 63;
                    float* op = sel + ((size_t)((bb * 16 + h) * 2048 + t)) * 64 + d0;
                    op[0] = v0; op[1] = v1;
                } else if (MODE == 1) {
                    size_t o = (size_t)gm * 1024 + gn;
                    g_x1[o]     = v0 + bias[gn]     + resid[o];
                    g_x1[o + 1] = v1 + bias[gn + 1] + resid[o + 1];
                } else if (MODE == 2) {
                    size_t o = (size_t)gm * 4096 + gn;
                    g_ff1[o]     = f2tf_f(fmaxf(v0 + bias[gn],     0.f));
                    g_ff1[o + 1] = f2tf_f(fmaxf(v1 + bias[gn + 1], 0.f));
                } else {
                    size_t o = (size_t)gm * 1024 + gn;
                    outp[o]     = v0 + bias[gn]     + g_x1[o];
                    outp[o + 1] = v1 + bias[gn + 1] + g_x1[o + 1];
                }
            }
        }
    }
}

// ----------------------------------------------------------------------------
// Causal flash attention (SIMT; output row-major, tf32-rounded for proj GEMM)
// ----------------------------------------------------------------------------
__global__ void __launch_bounds__(128) attn_k()
{
    __shared__ float Ks[32][64];
    __shared__ float Vs[32][64];
    __shared__ float Ss[32][128];

    const int tid = threadIdx.x;
    const int bh = blockIdx.z * NHEAD + blockIdx.y;
    const int R0 = blockIdx.x * 128;
    const int r = R0 + tid;
    const size_t base = (size_t)bh * TLEN * HS;

    float q[64], acc[64];
#pragma unroll
    for (int d = 0; d < 64; d++) {
        q[d] = g_q[base + (size_t)r * 64 + d];
        acc[d] = 0.f;
    }

    float m = -1e30f, l = 0.f;
    const int ktmax = (R0 + 127) >> 5;

    for (int kt = 0; kt <= ktmax; kt++) {
        __syncthreads();
        const float* kp = &g_kk[base + (size_t)kt * 32 * 64];
        const float* vp = &g_v [base + (size_t)kt * 32 * 64];
#pragma unroll
        for (int i = 0; i < 16; i++) {
            ((float*)Ks)[tid + i * 128] = kp[tid + i * 128];
            ((float*)Vs)[tid + i * 128] = vp[tid + i * 128];
        }
        __syncthreads();

        float tmax = -1e30f;
#pragma unroll 1
        for (int j = 0; j < 32; j++) {
            float s = 0.f;
#pragma unroll
            for (int d = 0; d < 64; d++) s += q[d] * Ks[j][d];
            s *= 0.125f;
            if (kt * 32 + j > r) s = -1e30f;
            Ss[j][tid] = s;
            tmax = fmaxf(tmax, s);
        }

        float mnew = fmaxf(m, tmax);
        float corr = __expf(m - mnew);
        l *= corr;
#pragma unroll
        for (int d = 0; d < 64; d++) acc[d] *= corr;

#pragma unroll 1
        for (int j = 0; j < 32; j++) {
            float p = __expf(Ss[j][tid] - mnew);
            l += p;
#pragma unroll
            for (int d = 0; d < 64; d++) acc[d] += p * Vs[j][d];
        }
        m = mnew;
    }

    float inv = 1.f / l;
    size_t obase = (size_t)(blockIdx.z * TLEN + r) * CDIM + blockIdx.y * HS;
#pragma unroll
    for (int d = 0; d < 64; d++)
        g_attn[obase + d] = f2tf_f(acc[d] * inv);
}

// ----------------------------------------------------------------------------
// Launch
// ----------------------------------------------------------------------------
extern "C" void kernel_launch(void* const* d_in, const int* in_sizes, int n_in,
                              void* d_out, int out_size)
{
    const float* x     = (const float*)d_in[0];
    const float* Wq    = (const float*)d_in[1];
    const float* Wk    = (const float*)d_in[2];
    const float* Wv    = (const float*)d_in[3];
    const float* Wproj = (const float*)d_in[4];
    const float* bproj = (const float*)d_in[5];
    const float* g1    = (const float*)d_in[6];
    const float* b1    = (const float*)d_in[7];
    const float* g2    = (const float*)d_in[8];
    const float* b2    = (const float*)d_in[9];
    const float* Wff1  = (const float*)d_in[10];
    const float* bff1  = (const float*)d_in[11];
    const float* Wff2  = (const float*)d_in[12];
    const float* bff2  = (const float*)d_in[13];
    float* out = (float*)d_out;

    cudaFuncSetAttribute(mgemm<0>, cudaFuncAttributeMaxDynamicSharedMemorySize, MG_SMEM);
    cudaFuncSetAttribute(mgemm<1>, cudaFuncAttributeMaxDynamicSharedMemorySize, MG_SMEM);
    cudaFuncSetAttribute(mgemm<2>, cudaFuncAttributeMaxDynamicSharedMemorySize, MG_SMEM);
    cudaFuncSetAttribute(mgemm<3>, cudaFuncAttributeMaxDynamicSharedMemorySize, MG_SMEM);

    transpose_k<<<dim3(HS / 32, CDIM / 32, NHEAD), 256>>>(Wq, 0, CDIM, HS);
    transpose_k<<<dim3(HS / 32, CDIM / 32, NHEAD), 256>>>(Wk, 1, CDIM, HS);
    transpose_k<<<dim3(HS / 32, CDIM / 32, NHEAD), 256>>>(Wv, 2, CDIM, HS);
    transpose_k<<<dim3(CDIM / 32, CDIM / 32, 1),   256>>>(Wproj, 3, CDIM, CDIM);
    transpose_k<<<dim3(FDIM / 32, CDIM / 32, 1),   256>>>(Wff1, 4, CDIM, FDIM);
    transpose_k<<<dim3(CDIM / 32, FDIM / 32, 1),   256>>>(Wff2, 5, FDIM, CDIM);

    ln_k<<<MROWS, 256>>>(0, x, g1, b1);
    mgemm<0><<<dim3(CDIM / 128, MROWS / 128, 3), 256, MG_SMEM>>>(nullptr, nullptr, nullptr);
    attn_k<<<dim3(TLEN / 128, NHEAD, 2), 128>>>();
    mgemm<1><<<dim3(CDIM / 128, MROWS / 128), 256, MG_SMEM>>>(bproj, x, nullptr);
    ln_k<<<MROWS, 256>>>(1, nullptr, g2, b2);
    mgemm<2><<<dim3(FDIM / 128, MROWS / 128), 256, MG_SMEM>>>(bff1, nullptr, nullptr);
    mgemm<3><<<dim3(CDIM / 128, MROWS / 128), 256, MG_SMEM>>>(bff2, nullptr, out);
}

// round 5
// speedup vs baseline: 3.6910x; 1.7058x over previous
#include <cuda_runtime.h>
#include <cstdint>
#include <cstddef>

// ----------------------------------------------------------------------------
// B=2, T=2048, C=1024, H=16, hs=64 ; M = B*T = 4096
// ----------------------------------------------------------------------------
#define MROWS 4096
#define CDIM  1024
#define FDIM  4096
#define TLEN  2048
#define NHEAD 16
#define HS    64

__device__ float g_h1[MROWS * CDIM];          // tf32-rounded
__device__ float g_q [MROWS * CDIM];          // [B,H,T,hs] tf32-rounded
__device__ float g_kk[MROWS * CDIM];          // [B,H,T,hs] tf32-rounded
__device__ float g_v [MROWS * CDIM];          // [B,H,hs,T] (TRANSPOSED) tf32-rounded
__device__ float g_attn[MROWS * CDIM];        // row-major, tf32-rounded
__device__ float g_x1[MROWS * CDIM];          // fp32 (residual path)
__device__ float g_h2[MROWS * CDIM];          // tf32-rounded
__device__ float g_ff1[(size_t)MROWS * FDIM]; // tf32-rounded
__device__ float g_wqT[CDIM * CDIM];          // Bt[n][k], tf32-rounded
__device__ float g_wkT[CDIM * CDIM];
__device__ float g_wvT[CDIM * CDIM];
__device__ float g_wpT[CDIM * CDIM];
__device__ float g_wf1T[(size_t)CDIM * FDIM];
__device__ float g_wf2T[(size_t)CDIM * FDIM];

// ----------------------------------------------------------------------------
// Helpers (baseline sm_80+; NO tcgen05)
// ----------------------------------------------------------------------------
__device__ __forceinline__ uint32_t smem_u32(const void* p) {
    return (uint32_t)__cvta_generic_to_shared(p);
}
__device__ __forceinline__ void cp16(uint32_t dst, const void* src) {
    asm volatile("cp.async.cg.shared.global [%0], [%1], 16;\n" :: "r"(dst), "l"(src));
}
__device__ __forceinline__ void cp_commit() {
    asm volatile("cp.async.commit_group;\n" ::: "memory");
}
__device__ __forceinline__ void cp_wait2() {
    asm volatile("cp.async.wait_group 2;\n" ::: "memory");
}
__device__ __forceinline__ void cp_wait1() {
    asm volatile("cp.async.wait_group 1;\n" ::: "memory");
}
__device__ __forceinline__ float f2tf_f(float f) {
    uint32_t u;
    asm("cvt.rna.tf32.f32 %0, %1;" : "=r"(u) : "f"(f));
    return __uint_as_float(u);
}
__device__ __forceinline__ void mma8(float* d, const uint32_t* a, const uint32_t* b) {
    asm volatile(
        "mma.sync.aligned.m16n8k8.row.col.f32.tf32.tf32.f32 "
        "{%0,%1,%2,%3},{%4,%5,%6,%7},{%8,%9},{%0,%1,%2,%3};"
        : "+f"(d[0]), "+f"(d[1]), "+f"(d[2]), "+f"(d[3])
        : "r"(a[0]), "r"(a[1]), "r"(a[2]), "r"(a[3]), "r"(b[0]), "r"(b[1]));
}
__device__ __forceinline__ void ldsm_x4(uint32_t* r, uint32_t addr) {
    asm volatile("ldmatrix.sync.aligned.m8n8.x4.shared.b16 {%0,%1,%2,%3}, [%4];"
                 : "=r"(r[0]), "=r"(r[1]), "=r"(r[2]), "=r"(r[3]) : "r"(addr));
}
__device__ __forceinline__ void ldsm_x2(uint32_t* r, uint32_t addr) {
    asm volatile("ldmatrix.sync.aligned.m8n8.x2.shared.b16 {%0,%1}, [%2];"
                 : "=r"(r[0]), "=r"(r[1]) : "r"(addr));
}

// ----------------------------------------------------------------------------
// LayerNorm (tf32-rounded output; consumed only by GEMMs)
// ----------------------------------------------------------------------------
__global__ void __launch_bounds__(256) ln_k(int mode, const float* __restrict__ x_ext,
                                            const float* __restrict__ g,
                                            const float* __restrict__ b)
{
    const float* in = (mode == 0) ? x_ext : g_x1;
    float* out      = (mode == 0) ? g_h1  : g_h2;
    int row = blockIdx.x;
    int tid = threadIdx.x;
    size_t base = (size_t)row * CDIM;

    float v[4];
    float s = 0.f, s2 = 0.f;
#pragma unroll
    for (int i = 0; i < 4; i++) {
        v[i] = in[base + tid + i * 256];
        s += v[i]; s2 += v[i] * v[i];
    }
#pragma unroll
    for (int off = 16; off; off >>= 1) {
        s  += __shfl_xor_sync(0xffffffffu, s,  off);
        s2 += __shfl_xor_sync(0xffffffffu, s2, off);
    }
    __shared__ float rs[8], rs2[8];
    int warp = tid >> 5, lane = tid & 31;
    if (lane == 0) { rs[warp] = s; rs2[warp] = s2; }
    __syncthreads();
    __shared__ float mu_s, rstd_s;
    if (tid == 0) {
        float ts = 0.f, ts2 = 0.f;
#pragma unroll
        for (int i = 0; i < 8; i++) { ts += rs[i]; ts2 += rs2[i]; }
        float mu = ts * (1.f / CDIM);
        float var = ts2 * (1.f / CDIM) - mu * mu;
        mu_s = mu; rstd_s = rsqrtf(var + 1e-5f);
    }
    __syncthreads();
    float mu = mu_s, rstd = rstd_s;
#pragma unroll
    for (int i = 0; i < 4; i++) {
        int c = tid + i * 256;
        out[base + c] = f2tf_f((v[i] - mu) * rstd * g[c] + b[c]);
    }
}

// ----------------------------------------------------------------------------
// Batched 32x32 transpose -> Bt[n][k], tf32-rounded
// ----------------------------------------------------------------------------
__global__ void __launch_bounds__(256) transpose_k(const float* __restrict__ in,
                                                   int outsel, int R, int Cc)
{
    __shared__ float t[32][33];
    float* outg;
    switch (outsel) {
        case 0: outg = g_wqT; break;
        case 1: outg = g_wkT; break;
        case 2: outg = g_wvT; break;
        case 3: outg = g_wpT; break;
        case 4: outg = g_wf1T; break;
        default: outg = g_wf2T; break;
    }
    int batch = blockIdx.z;
    const float* ip = in + (size_t)batch * R * Cc;
    float* op = outg + (size_t)batch * R * Cc;
    int c0 = blockIdx.x * 32, r0 = blockIdx.y * 32;
    int tx = threadIdx.x & 31, ty = threadIdx.x >> 5;
#pragma unroll
    for (int i = 0; i < 32; i += 8)
        t[ty + i][tx] = ip[(size_t)(r0 + ty + i) * Cc + c0 + tx];
    __syncthreads();
#pragma unroll
    for (int i = 0; i < 32; i += 8)
        op[(size_t)(c0 + ty + i) * R + r0 + tx] = f2tf_f(t[tx][ty + i]);
}

// ----------------------------------------------------------------------------
// tf32 mma.sync GEMM with ldmatrix fragment loads (as round 4).
// MODE 0 epilogue: rounds q/k/v to tf32; V stored transposed [B,H,hs,T].
// ----------------------------------------------------------------------------
#define STG_FLOATS (128 * 36)
#define MG_SMEM    (4 * 2 * STG_FLOATS * 4)  // 147456 B

template <int MODE>
__global__ void __launch_bounds__(256) mgemm(const float* __restrict__ bias,
                                             const float* __restrict__ resid,
                                             float* __restrict__ outp)
{
    constexpr int K = (MODE == 3) ? 4096 : 1024;
    constexpr int NKIT = K / 32;

    extern __shared__ float sm[];
    const int tid = threadIdx.x, lane = tid & 31, wid = tid >> 5;
    const int wm = wid & 1, wn = wid >> 1;
    const int m0 = blockIdx.y * 128;
    const int n0 = blockIdx.x * 128;

    const float* A;
    if      (MODE == 0) A = g_h1;
    else if (MODE == 1) A = g_attn;
    else if (MODE == 2) A = g_h2;
    else                A = g_ff1;

    const float* B;
    if (MODE == 0) B = (blockIdx.z == 0) ? g_wqT : ((blockIdx.z == 1) ? g_wkT : g_wvT);
    else if (MODE == 1) B = g_wpT;
    else if (MODE == 2) B = g_wf1T;
    else                B = g_wf2T;

    float acc[4][4][4] = {};

    auto load_stage = [&](int j, int s) {
        float* As = sm + s * (2 * STG_FLOATS);
        float* Bs = As + STG_FLOATS;
#pragma unroll
        for (int i = 0; i < 4; i++) {
            int c = tid + i * 256;
            int row = c >> 3, kc = c & 7;
            cp16(smem_u32(As + row * 36 + kc * 4),
                 A + (size_t)(m0 + row) * K + j * 32 + kc * 4);
            cp16(smem_u32(Bs + row * 36 + kc * 4),
                 B + (size_t)(n0 + row) * K + j * 32 + kc * 4);
        }
        cp_commit();
    };

    const int arow = (lane & 7) + ((lane >> 3) & 1) * 8;
    const int ahalf = (lane >> 4) & 1;
    uint32_t offA[4], offB[4];
#pragma unroll
    for (int mi = 0; mi < 4; mi++)
        offA[mi] = ((wm * 64 + mi * 16 + arow) * 36 + ahalf * 4) * 4;
    const int brow = lane & 7;
    const int bhalf = (lane >> 3) & 1;
#pragma unroll
    for (int nj = 0; nj < 4; nj++)
        offB[nj] = ((wn * 32 + nj * 8 + brow) * 36 + bhalf * 4) * 4;

    load_stage(0, 0);
    load_stage(1, 1);
    load_stage(2, 2);

    for (int it = 0; it < NKIT; it++) {
        int s = it & 3;
        cp_wait2();
        __syncthreads();
        if (it + 3 < NKIT) load_stage(it + 3, (it + 3) & 3);
        else cp_commit();

        uint32_t AsU = smem_u32(sm + s * (2 * STG_FLOATS));
        uint32_t BsU = AsU + STG_FLOATS * 4;

#pragma unroll
        for (int ks = 0; ks < 4; ks++) {
            uint32_t af[4][4], bf[4][2];
#pragma unroll
            for (int mi = 0; mi < 4; mi++) ldsm_x4(af[mi], AsU + offA[mi] + ks * 32);
#pragma unroll
            for (int nj = 0; nj < 4; nj++) ldsm_x2(bf[nj], BsU + offB[nj] + ks * 32);
#pragma unroll
            for (int mi = 0; mi < 4; mi++)
#pragma unroll
                for (int nj = 0; nj < 4; nj++)
                    mma8(acc[mi][nj], af[mi], bf[nj]);
        }
    }

#pragma unroll
    for (int mi = 0; mi < 4; mi++) {
#pragma unroll
        for (int nj = 0; nj < 4; nj++) {
#pragma unroll
            for (int half = 0; half < 2; half++) {
                int gm = m0 + wm * 64 + mi * 16 + (lane >> 2) + half * 8;
                int gn = n0 + wn * 32 + nj * 8 + (lane & 3) * 2;
                float v0 = acc[mi][nj][half * 2 + 0];
                float v1 = acc[mi][nj][half * 2 + 1];
                if (MODE == 0) {
                    int bb = gm >> 11, t = gm & 2047;
                    int h = gn >> 6, d0 = gn & 63;
                    if (blockIdx.z == 2) {
                        // V transposed: [B,H,hs,T]
                        float* op = g_v + ((size_t)((bb * 16 + h) * 64 + d0)) * 2048 + t;
                        op[0]    = f2tf_f(v0);
                        op[2048] = f2tf_f(v1);
                    } else {
                        float* sel = (blockIdx.z == 0) ? g_q : g_kk;
                        float* op = sel + ((size_t)((bb * 16 + h) * 2048 + t)) * 64 + d0;
                        op[0] = f2tf_f(v0); op[1] = f2tf_f(v1);
                    }
                } else if (MODE == 1) {
                    size_t o = (size_t)gm * 1024 + gn;
                    g_x1[o]     = v0 + bias[gn]     + resid[o];
                    g_x1[o + 1] = v1 + bias[gn + 1] + resid[o + 1];
                } else if (MODE == 2) {
                    size_t o = (size_t)gm * 4096 + gn;
                    g_ff1[o]     = f2tf_f(fmaxf(v0 + bias[gn],     0.f));
                    g_ff1[o + 1] = f2tf_f(fmaxf(v1 + bias[gn + 1], 0.f));
                } else {
                    size_t o = (size_t)gm * 1024 + gn;
                    outp[o]     = v0 + bias[gn]     + g_x1[o];
                    outp[o + 1] = v1 + bias[gn + 1] + g_x1[o + 1];
                }
            }
        }
    }
}

// ----------------------------------------------------------------------------
// Tensor-core causal flash attention (tf32 mma.sync).
// Grid (16, 32): x -> query row-block (reversed for heavy-first), y -> b*16+h.
// Block 128 thr / 4 warps; warp owns 32 query rows. 32-key tiles, double-buf
// cp.async for K [key][dim] and Vt [dim][key] (V pre-transposed in gmem).
// ----------------------------------------------------------------------------
#define QPITCH 68
#define KPITCH 68
#define VPITCH 36
#define PPITCH 36
// floats: Q 128*68 | K 2*32*68 | Vt 2*64*36 | P 4*32*36
#define AT_QOFF 0
#define AT_KOFF (128 * QPITCH)
#define AT_VOFF (AT_KOFF + 2 * 32 * KPITCH)
#define AT_POFF (AT_VOFF + 2 * 64 * VPITCH)
#define AT_SMEM ((AT_POFF + 4 * 32 * PPITCH) * 4)  // 89088 B

__global__ void __launch_bounds__(128) attn_k()
{
    extern __shared__ float smA[];
    const int tid = threadIdx.x, lane = tid & 31, wid = tid >> 5;
    const int bh = blockIdx.y;
    const int rb = (int)gridDim.x - 1 - (int)blockIdx.x;  // heavy blocks first
    const int R0 = rb * 128;
    const size_t qkbase = (size_t)bh * TLEN * HS;  // q,k: [bh][t][d]
    const size_t vbase  = (size_t)bh * HS * TLEN;  // v: [bh][d][t]

    uint32_t QsU = smem_u32(smA);
    uint32_t KsU[2], VtU[2];
    KsU[0] = QsU + AT_KOFF * 4;  KsU[1] = KsU[0] + 32 * KPITCH * 4;
    VtU[0] = QsU + AT_VOFF * 4;  VtU[1] = VtU[0] + 64 * VPITCH * 4;
    uint32_t PsU = QsU + (AT_POFF + wid * 32 * PPITCH) * 4;

    // ---- async loads ----
    // Q block 128x64 -> Qs
    {
        const float* src = g_q + qkbase + (size_t)R0 * 64;
#pragma unroll
        for (int i = 0; i < 16; i++) {
            int c = tid + i * 128;
            int row = c >> 4, ch = c & 15;
            cp16(QsU + (row * QPITCH + ch * 4) * 4, src + row * 64 + ch * 4);
        }
    }
    auto load_tile = [&](int kt, int b) {
        const float* ks = g_kk + qkbase + (size_t)kt * 32 * 64;
#pragma unroll
        for (int i = 0; i < 4; i++) {
            int c = tid + i * 128;
            int row = c >> 4, ch = c & 15;
            cp16(KsU[b] + (row * KPITCH + ch * 4) * 4, ks + row * 64 + ch * 4);
        }
        const float* vs = g_v + vbase + kt * 32;
#pragma unroll
        for (int i = 0; i < 4; i++) {
            int c = tid + i * 128;
            int row = c >> 3, ch = c & 7;
            cp16(VtU[b] + (row * VPITCH + ch * 4) * 4, vs + (size_t)row * 2048 + ch * 4);
        }
    };

    const int NT = R0 / 32 + 4;
    const int maskstart = R0 / 32;

    load_tile(0, 0);
    cp_commit();  // group 0: Q + tile0

    // ldmatrix lane offsets
    const int arow = (lane & 7) + ((lane >> 3) & 1) * 8;
    const int ahalf = (lane >> 4) & 1;
    uint32_t offQ[2], offP[2], offK[2], offV[4];
#pragma unroll
    for (int mi = 0; mi < 2; mi++) {
        offQ[mi] = ((wid * 32 + mi * 16 + arow) * QPITCH + ahalf * 4) * 4;
        offP[mi] = ((mi * 16 + arow) * PPITCH + ahalf * 4) * 4;
    }
#pragma unroll
    for (int g = 0; g < 2; g++) offK[g] = ((g * 16 + arow) * KPITCH + ahalf * 4) * 4;
#pragma unroll
    for (int g = 0; g < 4; g++) offV[g] = ((g * 16 + arow) * VPITCH + ahalf * 4) * 4;

    uint32_t qf[2][8][4];
    float oacc[2][8][4] = {};
    float m_run[4] = {-1e30f, -1e30f, -1e30f, -1e30f};
    float l_run[4] = {};

    const int srow = lane >> 2;            // fragment row within m16 (also +8)
    const int scol = (lane & 3) * 2;       // fragment col pair base

    for (int it = 0; it < NT; it++) {
        __syncthreads();                   // all warps done with buffer (it+1)&1
        if (it + 1 < NT) load_tile(it + 1, (it + 1) & 1);
        cp_commit();
        cp_wait1();                        // tile it resident
        __syncthreads();

        if (it == 0) {
            // Q fragments, pre-scaled by hs^-0.5 (exact in tf32)
#pragma unroll
            for (int mi = 0; mi < 2; mi++)
#pragma unroll
                for (int kt = 0; kt < 8; kt++) {
                    ldsm_x4(qf[mi][kt], QsU + offQ[mi] + kt * 32);
#pragma unroll
                    for (int i = 0; i < 4; i++)
                        qf[mi][kt][i] = __float_as_uint(__uint_as_float(qf[mi][kt][i]) * 0.125f);
                }
        }

        const uint32_t Kb = KsU[it & 1], Vb = VtU[it & 1];

        // ---- S = Q K^T ----
        float sacc[2][4][4] = {};
#pragma unroll
        for (int kt = 0; kt < 8; kt++) {
#pragma unroll
            for (int g = 0; g < 2; g++) {
                uint32_t kb[4];
                ldsm_x4(kb, Kb + offK[g] + kt * 32);
                uint32_t blo[2] = {kb[0], kb[2]}, bhi[2] = {kb[1], kb[3]};
#pragma unroll
                for (int mi = 0; mi < 2; mi++) {
                    mma8(sacc[mi][g * 2],     qf[mi][kt], blo);
                    mma8(sacc[mi][g * 2 + 1], qf[mi][kt], bhi);
                }
            }
        }

        // ---- causal mask (diagonal tiles only) ----
        if (it >= maskstart) {
            const int colbase = it * 32 + scol;
#pragma unroll
            for (int mi = 0; mi < 2; mi++) {
                const int rowb = R0 + wid * 32 + mi * 16 + srow;
#pragma unroll
                for (int nt = 0; nt < 4; nt++)
#pragma unroll
                    for (int j = 0; j < 4; j++) {
                        int col = colbase + nt * 8 + (j & 1);
                        int row = rowb + 8 * (j >> 1);
                        if (col > row) sacc[mi][nt][j] = -1e30f;
                    }
            }
        }

        // ---- online softmax + P store ----
#pragma unroll
        for (int mi = 0; mi < 2; mi++) {
#pragma unroll
            for (int hf = 0; hf < 2; hf++) {
                const int slot = mi * 2 + hf;
                float vmax = m_run[slot];
#pragma unroll
                for (int nt = 0; nt < 4; nt++) {
                    vmax = fmaxf(vmax, sacc[mi][nt][hf * 2]);
                    vmax = fmaxf(vmax, sacc[mi][nt][hf * 2 + 1]);
                }
                vmax = fmaxf(vmax, __shfl_xor_sync(0xffffffffu, vmax, 1));
                vmax = fmaxf(vmax, __shfl_xor_sync(0xffffffffu, vmax, 2));
                const float mnew = vmax;
                const float scale = __expf(m_run[slot] - mnew);
                float lsum = 0.f;
                const int prow = mi * 16 + srow + 8 * hf;
#pragma unroll
                for (int nt = 0; nt < 4; nt++) {
                    float p0 = __expf(sacc[mi][nt][hf * 2]     - mnew);
                    float p1 = __expf(sacc[mi][nt][hf * 2 + 1] - mnew);
                    lsum += p0 + p1;
                    float2 pv = make_float2(f2tf_f(p0), f2tf_f(p1));
                    asm volatile("st.shared.v2.f32 [%0], {%1,%2};"
                                 :: "r"(PsU + (prow * PPITCH + nt * 8 + scol) * 4),
                                    "f"(pv.x), "f"(pv.y) : "memory");
                }
                lsum += __shfl_xor_sync(0xffffffffu, lsum, 1);
                lsum += __shfl_xor_sync(0xffffffffu, lsum, 2);
                l_run[slot] = l_run[slot] * scale + lsum;
                m_run[slot] = mnew;
#pragma unroll
                for (int nt = 0; nt < 8; nt++) {
                    oacc[mi][nt][hf * 2]     *= scale;
                    oacc[mi][nt][hf * 2 + 1] *= scale;
                }
            }
        }

        // ---- O += P V ---- (P warp-private; no block sync needed)
#pragma unroll
        for (int kt = 0; kt < 4; kt++) {
            uint32_t pa[2][4];
#pragma unroll
            for (int mi = 0; mi < 2; mi++) ldsm_x4(pa[mi], PsU + offP[mi] + kt * 32);
#pragma unroll
            for (int g = 0; g < 4; g++) {
                uint32_t vb[4];
                ldsm_x4(vb, Vb + offV[g] + kt * 32);
                uint32_t blo[2] = {vb[0], vb[2]}, bhi[2] = {vb[1], vb[3]};
#pragma unroll
                for (int mi = 0; mi < 2; mi++) {
                    mma8(oacc[mi][g * 2],     pa[mi], blo);
                    mma8(oacc[mi][g * 2 + 1], pa[mi], bhi);
                }
            }
        }
    }

    // ---- finalize: O /= l, write row-major tf32 ----
    const int b = bh >> 4, h = bh & 15;
#pragma unroll
    for (int mi = 0; mi < 2; mi++) {
#pragma unroll
        for (int hf = 0; hf < 2; hf++) {
            const float inv = 1.f / l_run[mi * 2 + hf];
            const int grow = R0 + wid * 32 + mi * 16 + srow + 8 * hf;
            float* op = g_attn + ((size_t)(b * 2048 + grow)) * 1024 + h * 64 + scol;
#pragma unroll
            for (int nt = 0; nt < 8; nt++) {
                float2 ov = make_float2(f2tf_f(oacc[mi][nt][hf * 2] * inv),
                                        f2tf_f(oacc[mi][nt][hf * 2 + 1] * inv));
                *(float2*)(op + nt * 8) = ov;
            }
        }
    }
}

// ----------------------------------------------------------------------------
// Launch
// ----------------------------------------------------------------------------
extern "C" void kernel_launch(void* const* d_in, const int* in_sizes, int n_in,
                              void* d_out, int out_size)
{
    const float* x     = (const float*)d_in[0];
    const float* Wq    = (const float*)d_in[1];
    const float* Wk    = (const float*)d_in[2];
    const float* Wv    = (const float*)d_in[3];
    const float* Wproj = (const float*)d_in[4];
    const float* bproj = (const float*)d_in[5];
    const float* g1    = (const float*)d_in[6];
    const float* b1    = (const float*)d_in[7];
    const float* g2    = (const float*)d_in[8];
    const float* b2    = (const float*)d_in[9];
    const float* Wff1  = (const float*)d_in[10];
    const float* bff1  = (const float*)d_in[11];
    const float* Wff2  = (const float*)d_in[12];
    const float* bff2  = (const float*)d_in[13];
    float* out = (float*)d_out;

    cudaFuncSetAttribute(mgemm<0>, cudaFuncAttributeMaxDynamicSharedMemorySize, MG_SMEM);
    cudaFuncSetAttribute(mgemm<1>, cudaFuncAttributeMaxDynamicSharedMemorySize, MG_SMEM);
    cudaFuncSetAttribute(mgemm<2>, cudaFuncAttributeMaxDynamicSharedMemorySize, MG_SMEM);
    cudaFuncSetAttribute(mgemm<3>, cudaFuncAttributeMaxDynamicSharedMemorySize, MG_SMEM);
    cudaFuncSetAttribute(attn_k,   cudaFuncAttributeMaxDynamicSharedMemorySize, AT_SMEM);

    transpose_k<<<dim3(HS / 32, CDIM / 32, NHEAD), 256>>>(Wq, 0, CDIM, HS);
    transpose_k<<<dim3(HS / 32, CDIM / 32, NHEAD), 256>>>(Wk, 1, CDIM, HS);
    transpose_k<<<dim3(HS / 32, CDIM / 32, NHEAD), 256>>>(Wv, 2, CDIM, HS);
    transpose_k<<<dim3(CDIM / 32, CDIM / 32, 1),   256>>>(Wproj, 3, CDIM, CDIM);
    transpose_k<<<dim3(FDIM / 32, CDIM / 32, 1),   256>>>(Wff1, 4, CDIM, FDIM);
    transpose_k<<<dim3(CDIM / 32, FDIM / 32, 1),   256>>>(Wff2, 5, FDIM, CDIM);

    ln_k<<<MROWS, 256>>>(0, x, g1, b1);
    mgemm<0><<<dim3(CDIM / 128, MROWS / 128, 3), 256, MG_SMEM>>>(nullptr, nullptr, nullptr);
    attn_k<<<dim3(TLEN / 128, NHEAD * 2), 128, AT_SMEM>>>();
    mgemm<1><<<dim3(CDIM / 128, MROWS / 128), 256, MG_SMEM>>>(bproj, x, nullptr);
    ln_k<<<MROWS, 256>>>(1, nullptr, g2, b2);
    mgemm<2><<<dim3(FDIM / 128, MROWS / 128), 256, MG_SMEM>>>(bff1, nullptr, nullptr);
    mgemm<3><<<dim3(CDIM / 128, MROWS / 128), 256, MG_SMEM>>>(bff2, nullptr, out);
}

// round 6
// speedup vs baseline: 3.7482x; 1.0155x over previous
#include <cuda_runtime.h>
#include <cstdint>
#include <cstddef>

// ----------------------------------------------------------------------------
// B=2, T=2048, C=1024, H=16, hs=64 ; M = B*T = 4096
// ----------------------------------------------------------------------------
#define MROWS 4096
#define CDIM  1024
#define FDIM  4096
#define TLEN  2048
#define NHEAD 16
#define HS    64

__device__ float g_h1[MROWS * CDIM];          // tf32-rounded
__device__ float g_q [MROWS * CDIM];          // [B,H,T,hs] tf32-rounded
__device__ float g_kk[MROWS * CDIM];          // [B,H,T,hs] tf32-rounded
__device__ float g_v [MROWS * CDIM];          // [B,H,hs,T] (TRANSPOSED) tf32-rounded
__device__ float g_attn[MROWS * CDIM];        // row-major, tf32-rounded
__device__ float g_x1[MROWS * CDIM];          // fp32 (residual path)
__device__ float g_h2[MROWS * CDIM];          // tf32-rounded
__device__ float g_ff1[(size_t)MROWS * FDIM]; // tf32-rounded
__device__ float g_wqT[CDIM * CDIM];          // Bt[n][k], tf32-rounded
__device__ float g_wkT[CDIM * CDIM];
__device__ float g_wvT[CDIM * CDIM];
__device__ float g_wpT[CDIM * CDIM];
__device__ float g_wf1T[(size_t)CDIM * FDIM];
__device__ float g_wf2T[(size_t)CDIM * FDIM];

// ----------------------------------------------------------------------------
// Helpers (baseline sm_80+; NO tcgen05)
// ----------------------------------------------------------------------------
__device__ __forceinline__ uint32_t smem_u32(const void* p) {
    return (uint32_t)__cvta_generic_to_shared(p);
}
__device__ __forceinline__ void cp16(uint32_t dst, const void* src) {
    asm volatile("cp.async.cg.shared.global [%0], [%1], 16;\n" :: "r"(dst), "l"(src));
}
__device__ __forceinline__ void cp_commit() {
    asm volatile("cp.async.commit_group;\n" ::: "memory");
}
__device__ __forceinline__ void cp_wait1() {
    asm volatile("cp.async.wait_group 1;\n" ::: "memory");
}
__device__ __forceinline__ float f2tf_f(float f) {
    uint32_t u;
    asm("cvt.rna.tf32.f32 %0, %1;" : "=r"(u) : "f"(f));
    return __uint_as_float(u);
}
__device__ __forceinline__ void mma8(float* d, const uint32_t* a, const uint32_t* b) {
    asm volatile(
        "mma.sync.aligned.m16n8k8.row.col.f32.tf32.tf32.f32 "
        "{%0,%1,%2,%3},{%4,%5,%6,%7},{%8,%9},{%0,%1,%2,%3};"
        : "+f"(d[0]), "+f"(d[1]), "+f"(d[2]), "+f"(d[3])
        : "r"(a[0]), "r"(a[1]), "r"(a[2]), "r"(a[3]), "r"(b[0]), "r"(b[1]));
}
__device__ __forceinline__ void ldsm_x4(uint32_t* r, uint32_t addr) {
    asm volatile("ldmatrix.sync.aligned.m8n8.x4.shared.b16 {%0,%1,%2,%3}, [%4];"
                 : "=r"(r[0]), "=r"(r[1]), "=r"(r[2]), "=r"(r[3]) : "r"(addr));
}

// ----------------------------------------------------------------------------
// LayerNorm (tf32-rounded output; consumed only by GEMMs)
// ----------------------------------------------------------------------------
__global__ void __launch_bounds__(256) ln_k(int mode, const float* __restrict__ x_ext,
                                            const float* __restrict__ g,
                                            const float* __restrict__ b)
{
    const float* in = (mode == 0) ? x_ext : g_x1;
    float* out      = (mode == 0) ? g_h1  : g_h2;
    int row = blockIdx.x;
    int tid = threadIdx.x;
    size_t base = (size_t)row * CDIM;

    float v[4];
    float s = 0.f, s2 = 0.f;
#pragma unroll
    for (int i = 0; i < 4; i++) {
        v[i] = in[base + tid + i * 256];
        s += v[i]; s2 += v[i] * v[i];
    }
#pragma unroll
    for (int off = 16; off; off >>= 1) {
        s  += __shfl_xor_sync(0xffffffffu, s,  off);
        s2 += __shfl_xor_sync(0xffffffffu, s2, off);
    }
    __shared__ float rs[8], rs2[8];
    int warp = tid >> 5, lane = tid & 31;
    if (lane == 0) { rs[warp] = s; rs2[warp] = s2; }
    __syncthreads();
    __shared__ float mu_s, rstd_s;
    if (tid == 0) {
        float ts = 0.f, ts2 = 0.f;
#pragma unroll
        for (int i = 0; i < 8; i++) { ts += rs[i]; ts2 += rs2[i]; }
        float mu = ts * (1.f / CDIM);
        float var = ts2 * (1.f / CDIM) - mu * mu;
        mu_s = mu; rstd_s = rsqrtf(var + 1e-5f);
    }
    __syncthreads();
    float mu = mu_s, rstd = rstd_s;
#pragma unroll
    for (int i = 0; i < 4; i++) {
        int c = tid + i * 256;
        out[base + c] = f2tf_f((v[i] - mu) * rstd * g[c] + b[c]);
    }
}

// ----------------------------------------------------------------------------
// Batched 32x32 transpose -> Bt[n][k], tf32-rounded
// ----------------------------------------------------------------------------
__global__ void __launch_bounds__(256) transpose_k(const float* __restrict__ in,
                                                   int outsel, int R, int Cc)
{
    __shared__ float t[32][33];
    float* outg;
    switch (outsel) {
        case 0: outg = g_wqT; break;
        case 1: outg = g_wkT; break;
        case 2: outg = g_wvT; break;
        case 3: outg = g_wpT; break;
        case 4: outg = g_wf1T; break;
        default: outg = g_wf2T; break;
    }
    int batch = blockIdx.z;
    const float* ip = in + (size_t)batch * R * Cc;
    float* op = outg + (size_t)batch * R * Cc;
    int c0 = blockIdx.x * 32, r0 = blockIdx.y * 32;
    int tx = threadIdx.x & 31, ty = threadIdx.x >> 5;
#pragma unroll
    for (int i = 0; i < 32; i += 8)
        t[ty + i][tx] = ip[(size_t)(r0 + ty + i) * Cc + c0 + tx];
    __syncthreads();
#pragma unroll
    for (int i = 0; i < 32; i += 8)
        op[(size_t)(c0 + ty + i) * R + r0 + tx] = f2tf_f(t[tx][ty + i]);
}

// ----------------------------------------------------------------------------
// tf32 mma.sync GEMM, CTA tile 128(M) x 256(N), 8 warps (2x4), warp = 64x64.
// Per k8-step per warp: 32 MMA + 8 LDSM.x4 (MMA:LDSM = 4:1).
// BK=32, 3-stage cp.async pipeline (distance-2 prefetch). Pitch 36 floats.
// MODE 0 epilogue: rounds q/k/v to tf32; V stored transposed [B,H,hs,T].
// ----------------------------------------------------------------------------
#define STG_FLOATS ((128 + 256) * 36)
#define MG_SMEM    (3 * STG_FLOATS * 4)   // 165888 B

template <int MODE>
__global__ void __launch_bounds__(256) mgemm(const float* __restrict__ bias,
                                             const float* __restrict__ resid,
                                             float* __restrict__ outp)
{
    constexpr int K = (MODE == 3) ? 4096 : 1024;
    constexpr int NKIT = K / 32;

    extern __shared__ float sm[];
    const int tid = threadIdx.x, lane = tid & 31, wid = tid >> 5;
    const int wm = wid & 1, wn = wid >> 1;   // warp tile: rows wm*64, cols wn*64
    const int m0 = blockIdx.y * 128;
    const int n0 = blockIdx.x * 256;

    const float* A;
    if      (MODE == 0) A = g_h1;
    else if (MODE == 1) A = g_attn;
    else if (MODE == 2) A = g_h2;
    else                A = g_ff1;

    const float* B;
    if (MODE == 0) B = (blockIdx.z == 0) ? g_wqT : ((blockIdx.z == 1) ? g_wkT : g_wvT);
    else if (MODE == 1) B = g_wpT;
    else if (MODE == 2) B = g_wf1T;
    else                B = g_wf2T;

    float acc[4][8][4] = {};

    auto load_stage = [&](int j, int s) {
        float* As = sm + s * STG_FLOATS;
        float* Bs = As + 128 * 36;
#pragma unroll
        for (int i = 0; i < 4; i++) {
            int c = tid + i * 256;
            int row = c >> 3, kc = c & 7;
            cp16(smem_u32(As + row * 36 + kc * 4),
                 A + (size_t)(m0 + row) * K + j * 32 + kc * 4);
        }
#pragma unroll
        for (int i = 0; i < 8; i++) {
            int c = tid + i * 256;
            int row = c >> 3, kc = c & 7;
            cp16(smem_u32(Bs + row * 36 + kc * 4),
                 B + (size_t)(n0 + row) * K + j * 32 + kc * 4);
        }
        cp_commit();
    };

    // ldmatrix lane offsets (A and B use the same 4-matrix x4 pattern)
    const int arow = (lane & 7) + ((lane >> 3) & 1) * 8;
    const int ahalf = (lane >> 4) & 1;
    uint32_t offA[4], offB[4];
#pragma unroll
    for (int mi = 0; mi < 4; mi++)
        offA[mi] = ((wm * 64 + mi * 16 + arow) * 36 + ahalf * 4) * 4;
#pragma unroll
    for (int g = 0; g < 4; g++)
        offB[g] = ((wn * 64 + g * 16 + arow) * 36 + ahalf * 4) * 4;

    load_stage(0, 0);
    load_stage(1, 1);

    for (int it = 0; it < NKIT; it++) {
        int s = it % 3;
        cp_wait1();          // stage it resident
        __syncthreads();     // all warps done with stage it-1 (buffer (it+2)%3)
        if (it + 2 < NKIT) load_stage(it + 2, (it + 2) % 3);
        else cp_commit();    // keep group-count invariant

        uint32_t AsU = smem_u32(sm + s * STG_FLOATS);
        uint32_t BsU = AsU + 128 * 36 * 4;

#pragma unroll
        for (int ks = 0; ks < 4; ks++) {
            uint32_t af[4][4], bb[4][4];
#pragma unroll
            for (int mi = 0; mi < 4; mi++) ldsm_x4(af[mi], AsU + offA[mi] + ks * 32);
#pragma unroll
            for (int g = 0; g < 4; g++)  ldsm_x4(bb[g], BsU + offB[g] + ks * 32);
#pragma unroll
            for (int mi = 0; mi < 4; mi++)
#pragma unroll
                for (int g = 0; g < 4; g++) {
                    uint32_t blo[2] = {bb[g][0], bb[g][2]};
                    uint32_t bhi[2] = {bb[g][1], bb[g][3]};
                    mma8(acc[mi][g * 2],     af[mi], blo);
                    mma8(acc[mi][g * 2 + 1], af[mi], bhi);
                }
        }
    }

    // epilogue: d0:(r,c) d1:(r,c+1) d2:(r+8,c) d3:(r+8,c+1)
#pragma unroll
    for (int mi = 0; mi < 4; mi++) {
#pragma unroll
        for (int nj = 0; nj < 8; nj++) {
#pragma unroll
            for (int half = 0; half < 2; half++) {
                int gm = m0 + wm * 64 + mi * 16 + (lane >> 2) + half * 8;
                int gn = n0 + wn * 64 + nj * 8 + (lane & 3) * 2;
                float v0 = acc[mi][nj][half * 2 + 0];
                float v1 = acc[mi][nj][half * 2 + 1];
                if (MODE == 0) {
                    int bb2 = gm >> 11, t = gm & 2047;
                    int h = gn >> 6, d0 = gn & 63;
                    if (blockIdx.z == 2) {
                        float* op = g_v + ((size_t)((bb2 * 16 + h) * 64 + d0)) * 2048 + t;
                        op[0]    = f2tf_f(v0);
                        op[2048] = f2tf_f(v1);
                    } else {
                        float* sel = (blockIdx.z == 0) ? g_q : g_kk;
                        float* op = sel + ((size_t)((bb2 * 16 + h) * 2048 + t)) * 64 + d0;
                        op[0] = f2tf_f(v0); op[1] = f2tf_f(v1);
                    }
                } else if (MODE == 1) {
                    size_t o = (size_t)gm * 1024 + gn;
                    g_x1[o]     = v0 + bias[gn]     + resid[o];
                    g_x1[o + 1] = v1 + bias[gn + 1] + resid[o + 1];
                } else if (MODE == 2) {
                    size_t o = (size_t)gm * 4096 + gn;
                    g_ff1[o]     = f2tf_f(fmaxf(v0 + bias[gn],     0.f));
                    g_ff1[o + 1] = f2tf_f(fmaxf(v1 + bias[gn + 1], 0.f));
                } else {
                    size_t o = (size_t)gm * 1024 + gn;
                    outp[o]     = v0 + bias[gn]     + g_x1[o];
                    outp[o + 1] = v1 + bias[gn + 1] + g_x1[o + 1];
                }
            }
        }
    }
}

// ----------------------------------------------------------------------------
// Tensor-core causal flash attention (tf32 mma.sync) — unchanged from round 5.
// ----------------------------------------------------------------------------
#define QPITCH 68
#define KPITCH 68
#define VPITCH 36
#define PPITCH 36
#define AT_QOFF 0
#define AT_KOFF (128 * QPITCH)
#define AT_VOFF (AT_KOFF + 2 * 32 * KPITCH)
#define AT_POFF (AT_VOFF + 2 * 64 * VPITCH)
#define AT_SMEM ((AT_POFF + 4 * 32 * PPITCH) * 4)  // 89088 B

__global__ void __launch_bounds__(128) attn_k()
{
    extern __shared__ float smA[];
    const int tid = threadIdx.x, lane = tid & 31, wid = tid >> 5;
    const int bh = blockIdx.y;
    const int rb = (int)gridDim.x - 1 - (int)blockIdx.x;
    const int R0 = rb * 128;
    const size_t qkbase = (size_t)bh * TLEN * HS;
    const size_t vbase  = (size_t)bh * HS * TLEN;

    uint32_t QsU = smem_u32(smA);
    uint32_t KsU[2], VtU[2];
    KsU[0] = QsU + AT_KOFF * 4;  KsU[1] = KsU[0] + 32 * KPITCH * 4;
    VtU[0] = QsU + AT_VOFF * 4;  VtU[1] = VtU[0] + 64 * VPITCH * 4;
    uint32_t PsU = QsU + (AT_POFF + wid * 32 * PPITCH) * 4;

    {
        const float* src = g_q + qkbase + (size_t)R0 * 64;
#pragma unroll
        for (int i = 0; i < 16; i++) {
            int c = tid + i * 128;
            int row = c >> 4, ch = c & 15;
            cp16(QsU + (row * QPITCH + ch * 4) * 4, src + row * 64 + ch * 4);
        }
    }
    auto load_tile = [&](int kt, int b) {
        const float* ks = g_kk + qkbase + (size_t)kt * 32 * 64;
#pragma unroll
        for (int i = 0; i < 4; i++) {
            int c = tid + i * 128;
            int row = c >> 4, ch = c & 15;
            cp16(KsU[b] + (row * KPITCH + ch * 4) * 4, ks + row * 64 + ch * 4);
        }
        const float* vs = g_v + vbase + kt * 32;
#pragma unroll
        for (int i = 0; i < 4; i++) {
            int c = tid + i * 128;
            int row = c >> 3, ch = c & 7;
            cp16(VtU[b] + (row * VPITCH + ch * 4) * 4, vs + (size_t)row * 2048 + ch * 4);
        }
    };

    const int NT = R0 / 32 + 4;
    const int maskstart = R0 / 32;

    load_tile(0, 0);
    cp_commit();

    const int arow = (lane & 7) + ((lane >> 3) & 1) * 8;
    const int ahalf = (lane >> 4) & 1;
    uint32_t offQ[2], offP[2], offK[2], offV[4];
#pragma unroll
    for (int mi = 0; mi < 2; mi++) {
        offQ[mi] = ((wid * 32 + mi * 16 + arow) * QPITCH + ahalf * 4) * 4;
        offP[mi] = ((mi * 16 + arow) * PPITCH + ahalf * 4) * 4;
    }
#pragma unroll
    for (int g = 0; g < 2; g++) offK[g] = ((g * 16 + arow) * KPITCH + ahalf * 4) * 4;
#pragma unroll
    for (int g = 0; g < 4; g++) offV[g] = ((g * 16 + arow) * VPITCH + ahalf * 4) * 4;

    uint32_t qf[2][8][4];
    float oacc[2][8][4] = {};
    float m_run[4] = {-1e30f, -1e30f, -1e30f, -1e30f};
    float l_run[4] = {};

    const int srow = lane >> 2;
    const int scol = (lane & 3) * 2;

    for (int it = 0; it < NT; it++) {
        __syncthreads();
        if (it + 1 < NT) load_tile(it + 1, (it + 1) & 1);
        cp_commit();
        cp_wait1();
        __syncthreads();

        if (it == 0) {
#pragma unroll
            for (int mi = 0; mi < 2; mi++)
#pragma unroll
                for (int kt = 0; kt < 8; kt++) {
                    ldsm_x4(qf[mi][kt], QsU + offQ[mi] + kt * 32);
#pragma unroll
                    for (int i = 0; i < 4; i++)
                        qf[mi][kt][i] = __float_as_uint(__uint_as_float(qf[mi][kt][i]) * 0.125f);
                }
        }

        const uint32_t Kb = KsU[it & 1], Vb = VtU[it & 1];

        float sacc[2][4][4] = {};
#pragma unroll
        for (int kt = 0; kt < 8; kt++) {
#pragma unroll
            for (int g = 0; g < 2; g++) {
                uint32_t kb[4];
                ldsm_x4(kb, Kb + offK[g] + kt * 32);
                uint32_t blo[2] = {kb[0], kb[2]}, bhi[2] = {kb[1], kb[3]};
#pragma unroll
                for (int mi = 0; mi < 2; mi++) {
                    mma8(sacc[mi][g * 2],     qf[mi][kt], blo);
                    mma8(sacc[mi][g * 2 + 1], qf[mi][kt], bhi);
                }
            }
        }

        if (it >= maskstart) {
            const int colbase = it * 32 + scol;
#pragma unroll
            for (int mi = 0; mi < 2; mi++) {
                const int rowb = R0 + wid * 32 + mi * 16 + srow;
#pragma unroll
                for (int nt = 0; nt < 4; nt++)
#pragma unroll
                    for (int j = 0; j < 4; j++) {
                        int col = colbase + nt * 8 + (j & 1);
                        int row = rowb + 8 * (j >> 1);
                        if (col > row) sacc[mi][nt][j] = -1e30f;
                    }
            }
        }

#pragma unroll
        for (int mi = 0; mi < 2; mi++) {
#pragma unroll
            for (int hf = 0; hf < 2; hf++) {
                const int slot = mi * 2 + hf;
                float vmax = m_run[slot];
#pragma unroll
                for (int nt = 0; nt < 4; nt++) {
                    vmax = fmaxf(vmax, sacc[mi][nt][hf * 2]);
                    vmax = fmaxf(vmax, sacc[mi][nt][hf * 2 + 1]);
                }
                vmax = fmaxf(vmax, __shfl_xor_sync(0xffffffffu, vmax, 1));
                vmax = fmaxf(vmax, __shfl_xor_sync(0xffffffffu, vmax, 2));
                const float mnew = vmax;
                const float scale = __expf(m_run[slot] - mnew);
                float lsum = 0.f;
                const int prow = mi * 16 + srow + 8 * hf;
#pragma unroll
                for (int nt = 0; nt < 4; nt++) {
                    float p0 = __expf(sacc[mi][nt][hf * 2]     - mnew);
                    float p1 = __expf(sacc[mi][nt][hf * 2 + 1] - mnew);
                    lsum += p0 + p1;
                    float2 pv = make_float2(f2tf_f(p0), f2tf_f(p1));
                    asm volatile("st.shared.v2.f32 [%0], {%1,%2};"
                                 :: "r"(PsU + (prow * PPITCH + nt * 8 + scol) * 4),
                                    "f"(pv.x), "f"(pv.y) : "memory");
                }
                lsum += __shfl_xor_sync(0xffffffffu, lsum, 1);
                lsum += __shfl_xor_sync(0xffffffffu, lsum, 2);
                l_run[slot] = l_run[slot] * scale + lsum;
                m_run[slot] = mnew;
#pragma unroll
                for (int nt = 0; nt < 8; nt++) {
                    oacc[mi][nt][hf * 2]     *= scale;
                    oacc[mi][nt][hf * 2 + 1] *= scale;
                }
            }
        }

#pragma unroll
        for (int kt = 0; kt < 4; kt++) {
            uint32_t pa[2][4];
#pragma unroll
            for (int mi = 0; mi < 2; mi++) ldsm_x4(pa[mi], PsU + offP[mi] + kt * 32);
#pragma unroll
            for (int g = 0; g < 4; g++) {
                uint32_t vb[4];
                ldsm_x4(vb, Vb + offV[g] + kt * 32);
                uint32_t blo[2] = {vb[0], vb[2]}, bhi[2] = {vb[1], vb[3]};
#pragma unroll
                for (int mi = 0; mi < 2; mi++) {
                    mma8(oacc[mi][g * 2],     pa[mi], blo);
                    mma8(oacc[mi][g * 2 + 1], pa[mi], bhi);
                }
            }
        }
    }

    const int b = bh >> 4, h = bh & 15;
#pragma unroll
    for (int mi = 0; mi < 2; mi++) {
#pragma unroll
        for (int hf = 0; hf < 2; hf++) {
            const float inv = 1.f / l_run[mi * 2 + hf];
            const int grow = R0 + wid * 32 + mi * 16 + srow + 8 * hf;
            float* op = g_attn + ((size_t)(b * 2048 + grow)) * 1024 + h * 64 + scol;
#pragma unroll
            for (int nt = 0; nt < 8; nt++) {
                float2 ov = make_float2(f2tf_f(oacc[mi][nt][hf * 2] * inv),
                                        f2tf_f(oacc[mi][nt][hf * 2 + 1] * inv));
                *(float2*)(op + nt * 8) = ov;
            }
        }
    }
}

// ----------------------------------------------------------------------------
// Launch
// ----------------------------------------------------------------------------
extern "C" void kernel_launch(void* const* d_in, const int* in_sizes, int n_in,
                              void* d_out, int out_size)
{
    const float* x     = (const float*)d_in[0];
    const float* Wq    = (const float*)d_in[1];
    const float* Wk    = (const float*)d_in[2];
    const float* Wv    = (const float*)d_in[3];
    const float* Wproj = (const float*)d_in[4];
    const float* bproj = (const float*)d_in[5];
    const float* g1    = (const float*)d_in[6];
    const float* b1    = (const float*)d_in[7];
    const float* g2    = (const float*)d_in[8];
    const float* b2    = (const float*)d_in[9];
    const float* Wff1  = (const float*)d_in[10];
    const float* bff1  = (const float*)d_in[11];
    const float* Wff2  = (const float*)d_in[12];
    const float* bff2  = (const float*)d_in[13];
    float* out = (float*)d_out;

    cudaFuncSetAttribute(mgemm<0>, cudaFuncAttributeMaxDynamicSharedMemorySize, MG_SMEM);
    cudaFuncSetAttribute(mgemm<1>, cudaFuncAttributeMaxDynamicSharedMemorySize, MG_SMEM);
    cudaFuncSetAttribute(mgemm<2>, cudaFuncAttributeMaxDynamicSharedMemorySize, MG_SMEM);
    cudaFuncSetAttribute(mgemm<3>, cudaFuncAttributeMaxDynamicSharedMemorySize, MG_SMEM);
    cudaFuncSetAttribute(attn_k,   cudaFuncAttributeMaxDynamicSharedMemorySize, AT_SMEM);

    transpose_k<<<dim3(HS / 32, CDIM / 32, NHEAD), 256>>>(Wq, 0, CDIM, HS);
    transpose_k<<<dim3(HS / 32, CDIM / 32, NHEAD), 256>>>(Wk, 1, CDIM, HS);
    transpose_k<<<dim3(HS / 32, CDIM / 32, NHEAD), 256>>>(Wv, 2, CDIM, HS);
    transpose_k<<<dim3(CDIM / 32, CDIM / 32, 1),   256>>>(Wproj, 3, CDIM, CDIM);
    transpose_k<<<dim3(FDIM / 32, CDIM / 32, 1),   256>>>(Wff1, 4, CDIM, FDIM);
    transpose_k<<<dim3(CDIM / 32, FDIM / 32, 1),   256>>>(Wff2, 5, FDIM, CDIM);

    ln_k<<<MROWS, 256>>>(0, x, g1, b1);
    mgemm<0><<<dim3(CDIM / 256, MROWS / 128, 3), 256, MG_SMEM>>>(nullptr, nullptr, nullptr);
    attn_k<<<dim3(TLEN / 128, NHEAD * 2), 128, AT_SMEM>>>();
    mgemm<1><<<dim3(CDIM / 256, MROWS / 128), 256, MG_SMEM>>>(bproj, x, nullptr);
    ln_k<<<MROWS, 256>>>(1, nullptr, g2, b2);
    mgemm<2><<<dim3(FDIM / 256, MROWS / 128), 256, MG_SMEM>>>(bff1, nullptr, nullptr);
    mgemm<3><<<dim3(CDIM / 256, MROWS / 128), 256, MG_SMEM>>>(bff2, nullptr, out);
}

// round 7
// speedup vs baseline: 3.7622x; 1.0037x over previous
#include <cuda_runtime.h>
#include <cstdint>
#include <cstddef>

// ----------------------------------------------------------------------------
// B=2, T=2048, C=1024, H=16, hs=64 ; M = B*T = 4096
// ----------------------------------------------------------------------------
#define MROWS 4096
#define CDIM  1024
#define FDIM  4096
#define TLEN  2048
#define NHEAD 16
#define HS    64

__device__ float g_h1[MROWS * CDIM];          // tf32-rounded
__device__ float g_q [MROWS * CDIM];          // [B,H,T,hs] tf32-rounded
__device__ float g_kk[MROWS * CDIM];          // [B,H,T,hs] tf32-rounded
__device__ float g_v [MROWS * CDIM];          // [B,H,hs,T] (TRANSPOSED) tf32-rounded
__device__ float g_attn[MROWS * CDIM];        // row-major, tf32-rounded
__device__ float g_x1[MROWS * CDIM];          // fp32 (residual path)
__device__ float g_h2[MROWS * CDIM];          // tf32-rounded
__device__ float g_ff1[(size_t)MROWS * FDIM]; // tf32-rounded
__device__ float g_wqT[CDIM * CDIM];          // Bt[n][k], tf32-rounded
__device__ float g_wkT[CDIM * CDIM];
__device__ float g_wvT[CDIM * CDIM];
__device__ float g_wpT[CDIM * CDIM];
__device__ float g_wf1T[(size_t)CDIM * FDIM];
__device__ float g_wf2T[(size_t)CDIM * FDIM];

// ----------------------------------------------------------------------------
// Helpers (baseline sm_80+; NO tcgen05)
// ----------------------------------------------------------------------------
__device__ __forceinline__ uint32_t smem_u32(const void* p) {
    return (uint32_t)__cvta_generic_to_shared(p);
}
__device__ __forceinline__ void cp16(uint32_t dst, const void* src) {
    asm volatile("cp.async.cg.shared.global [%0], [%1], 16;\n" :: "r"(dst), "l"(src));
}
__device__ __forceinline__ void cp_commit() {
    asm volatile("cp.async.commit_group;\n" ::: "memory");
}
__device__ __forceinline__ void cp_wait1() {
    asm volatile("cp.async.wait_group 1;\n" ::: "memory");
}
__device__ __forceinline__ void cp_wait2() {
    asm volatile("cp.async.wait_group 2;\n" ::: "memory");
}
__device__ __forceinline__ float f2tf_f(float f) {
    uint32_t u;
    asm("cvt.rna.tf32.f32 %0, %1;" : "=r"(u) : "f"(f));
    return __uint_as_float(u);
}
__device__ __forceinline__ void mma8(float* d, const uint32_t* a, const uint32_t* b) {
    asm volatile(
        "mma.sync.aligned.m16n8k8.row.col.f32.tf32.tf32.f32 "
        "{%0,%1,%2,%3},{%4,%5,%6,%7},{%8,%9},{%0,%1,%2,%3};"
        : "+f"(d[0]), "+f"(d[1]), "+f"(d[2]), "+f"(d[3])
        : "r"(a[0]), "r"(a[1]), "r"(a[2]), "r"(a[3]), "r"(b[0]), "r"(b[1]));
}
__device__ __forceinline__ void ldsm_x4(uint32_t* r, uint32_t addr) {
    asm volatile("ldmatrix.sync.aligned.m8n8.x4.shared.b16 {%0,%1,%2,%3}, [%4];"
                 : "=r"(r[0]), "=r"(r[1]), "=r"(r[2]), "=r"(r[3]) : "r"(addr));
}

// ----------------------------------------------------------------------------
// LayerNorm (tf32-rounded output; consumed only by GEMMs)
// ----------------------------------------------------------------------------
__global__ void __launch_bounds__(256) ln_k(int mode, const float* __restrict__ x_ext,
                                            const float* __restrict__ g,
                                            const float* __restrict__ b)
{
    const float* in = (mode == 0) ? x_ext : g_x1;
    float* out      = (mode == 0) ? g_h1  : g_h2;
    int row = blockIdx.x;
    int tid = threadIdx.x;
    size_t base = (size_t)row * CDIM;

    float v[4];
    float s = 0.f, s2 = 0.f;
#pragma unroll
    for (int i = 0; i < 4; i++) {
        v[i] = in[base + tid + i * 256];
        s += v[i]; s2 += v[i] * v[i];
    }
#pragma unroll
    for (int off = 16; off; off >>= 1) {
        s  += __shfl_xor_sync(0xffffffffu, s,  off);
        s2 += __shfl_xor_sync(0xffffffffu, s2, off);
    }
    __shared__ float rs[8], rs2[8];
    int warp = tid >> 5, lane = tid & 31;
    if (lane == 0) { rs[warp] = s; rs2[warp] = s2; }
    __syncthreads();
    __shared__ float mu_s, rstd_s;
    if (tid == 0) {
        float ts = 0.f, ts2 = 0.f;
#pragma unroll
        for (int i = 0; i < 8; i++) { ts += rs[i]; ts2 += rs2[i]; }
        float mu = ts * (1.f / CDIM);
        float var = ts2 * (1.f / CDIM) - mu * mu;
        mu_s = mu; rstd_s = rsqrtf(var + 1e-5f);
    }
    __syncthreads();
    float mu = mu_s, rstd = rstd_s;
#pragma unroll
    for (int i = 0; i < 4; i++) {
        int c = tid + i * 256;
        out[base + c] = f2tf_f((v[i] - mu) * rstd * g[c] + b[c]);
    }
}

// ----------------------------------------------------------------------------
// Batched 32x32 transpose -> Bt[n][k], tf32-rounded
// ----------------------------------------------------------------------------
__global__ void __launch_bounds__(256) transpose_k(const float* __restrict__ in,
                                                   int outsel, int R, int Cc)
{
    __shared__ float t[32][33];
    float* outg;
    switch (outsel) {
        case 0: outg = g_wqT; break;
        case 1: outg = g_wkT; break;
        case 2: outg = g_wvT; break;
        case 3: outg = g_wpT; break;
        case 4: outg = g_wf1T; break;
        default: outg = g_wf2T; break;
    }
    int batch = blockIdx.z;
    const float* ip = in + (size_t)batch * R * Cc;
    float* op = outg + (size_t)batch * R * Cc;
    int c0 = blockIdx.x * 32, r0 = blockIdx.y * 32;
    int tx = threadIdx.x & 31, ty = threadIdx.x >> 5;
#pragma unroll
    for (int i = 0; i < 32; i += 8)
        t[ty + i][tx] = ip[(size_t)(r0 + ty + i) * Cc + c0 + tx];
    __syncthreads();
#pragma unroll
    for (int i = 0; i < 32; i += 8)
        op[(size_t)(c0 + ty + i) * R + r0 + tx] = f2tf_f(t[tx][ty + i]);
}

// ----------------------------------------------------------------------------
// tf32 mma.sync GEMM, CTA tile 128(M) x 256(N), 8 warps (2x4), warp = 64x64.
// BK=32, FOUR-stage cp.async pipeline (prefetch distance 3 => ~900+ cyc,
// above worst-case DRAM latency; 1 CTA/SM so depth must hide it alone).
// MODE 0 epilogue: rounds q/k/v to tf32; V stored transposed [B,H,hs,T].
// ----------------------------------------------------------------------------
#define STG_FLOATS ((128 + 256) * 36)
#define MG_SMEM    (4 * STG_FLOATS * 4)   // 221184 B < 227KB cap

template <int MODE>
__global__ void __launch_bounds__(256) mgemm(const float* __restrict__ bias,
                                             const float* __restrict__ resid,
                                             float* __restrict__ outp)
{
    constexpr int K = (MODE == 3) ? 4096 : 1024;
    constexpr int NKIT = K / 32;

    extern __shared__ float sm[];
    const int tid = threadIdx.x, lane = tid & 31, wid = tid >> 5;
    const int wm = wid & 1, wn = wid >> 1;   // warp tile: rows wm*64, cols wn*64
    const int m0 = blockIdx.y * 128;
    const int n0 = blockIdx.x * 256;

    const float* A;
    if      (MODE == 0) A = g_h1;
    else if (MODE == 1) A = g_attn;
    else if (MODE == 2) A = g_h2;
    else                A = g_ff1;

    const float* B;
    if (MODE == 0) B = (blockIdx.z == 0) ? g_wqT : ((blockIdx.z == 1) ? g_wkT : g_wvT);
    else if (MODE == 1) B = g_wpT;
    else if (MODE == 2) B = g_wf1T;
    else                B = g_wf2T;

    float acc[4][8][4] = {};

    auto load_stage = [&](int j, int s) {
        float* As = sm + s * STG_FLOATS;
        float* Bs = As + 128 * 36;
#pragma unroll
        for (int i = 0; i < 4; i++) {
            int c = tid + i * 256;
            int row = c >> 3, kc = c & 7;
            cp16(smem_u32(As + row * 36 + kc * 4),
                 A + (size_t)(m0 + row) * K + j * 32 + kc * 4);
        }
#pragma unroll
        for (int i = 0; i < 8; i++) {
            int c = tid + i * 256;
            int row = c >> 3, kc = c & 7;
            cp16(smem_u32(Bs + row * 36 + kc * 4),
                 B + (size_t)(n0 + row) * K + j * 32 + kc * 4);
        }
        cp_commit();
    };

    // ldmatrix lane offsets (A and B use the same 4-matrix x4 pattern)
    const int arow = (lane & 7) + ((lane >> 3) & 1) * 8;
    const int ahalf = (lane >> 4) & 1;
    uint32_t offA[4], offB[4];
#pragma unroll
    for (int mi = 0; mi < 4; mi++)
        offA[mi] = ((wm * 64 + mi * 16 + arow) * 36 + ahalf * 4) * 4;
#pragma unroll
    for (int g = 0; g < 4; g++)
        offB[g] = ((wn * 64 + g * 16 + arow) * 36 + ahalf * 4) * 4;

    load_stage(0, 0);
    load_stage(1, 1);
    load_stage(2, 2);

    for (int it = 0; it < NKIT; it++) {
        int s = it & 3;
        cp_wait2();          // stage it resident (<=2 younger groups in flight)
        __syncthreads();     // all warps done with stage it-1 (buffer (it+3)&3)
        if (it + 3 < NKIT) load_stage(it + 3, (it + 3) & 3);
        else cp_commit();    // keep group-count invariant

        uint32_t AsU = smem_u32(sm + s * STG_FLOATS);
        uint32_t BsU = AsU + 128 * 36 * 4;

#pragma unroll
        for (int ks = 0; ks < 4; ks++) {
            uint32_t af[4][4], bb[4][4];
#pragma unroll
            for (int mi = 0; mi < 4; mi++) ldsm_x4(af[mi], AsU + offA[mi] + ks * 32);
#pragma unroll
            for (int g = 0; g < 4; g++)  ldsm_x4(bb[g], BsU + offB[g] + ks * 32);
#pragma unroll
            for (int mi = 0; mi < 4; mi++)
#pragma unroll
                for (int g = 0; g < 4; g++) {
                    uint32_t blo[2] = {bb[g][0], bb[g][2]};
                    uint32_t bhi[2] = {bb[g][1], bb[g][3]};
                    mma8(acc[mi][g * 2],     af[mi], blo);
                    mma8(acc[mi][g * 2 + 1], af[mi], bhi);
                }
        }
    }

    // epilogue: d0:(r,c) d1:(r,c+1) d2:(r+8,c) d3:(r+8,c+1)
#pragma unroll
    for (int mi = 0; mi < 4; mi++) {
#pragma unroll
        for (int nj = 0; nj < 8; nj++) {
#pragma unroll
            for (int half = 0; half < 2; half++) {
                int gm = m0 + wm * 64 + mi * 16 + (lane >> 2) + half * 8;
                int gn = n0 + wn * 64 + nj * 8 + (lane & 3) * 2;
                float v0 = acc[mi][nj][half * 2 + 0];
                float v1 = acc[mi][nj][half * 2 + 1];
                if (MODE == 0) {
                    int bb2 = gm >> 11, t = gm & 2047;
                    int h = gn >> 6, d0 = gn & 63;
                    if (blockIdx.z == 2) {
                        float* op = g_v + ((size_t)((bb2 * 16 + h) * 64 + d0)) * 2048 + t;
                        op[0]    = f2tf_f(v0);
                        op[2048] = f2tf_f(v1);
                    } else {
                        float* sel = (blockIdx.z == 0) ? g_q : g_kk;
                        float* op = sel + ((size_t)((bb2 * 16 + h) * 2048 + t)) * 64 + d0;
                        op[0] = f2tf_f(v0); op[1] = f2tf_f(v1);
                    }
                } else if (MODE == 1) {
                    size_t o = (size_t)gm * 1024 + gn;
                    g_x1[o]     = v0 + bias[gn]     + resid[o];
                    g_x1[o + 1] = v1 + bias[gn + 1] + resid[o + 1];
                } else if (MODE == 2) {
                    size_t o = (size_t)gm * 4096 + gn;
                    g_ff1[o]     = f2tf_f(fmaxf(v0 + bias[gn],     0.f));
                    g_ff1[o + 1] = f2tf_f(fmaxf(v1 + bias[gn + 1], 0.f));
                } else {
                    size_t o = (size_t)gm * 1024 + gn;
                    outp[o]     = v0 + bias[gn]     + g_x1[o];
                    outp[o + 1] = v1 + bias[gn + 1] + g_x1[o + 1];
                }
            }
        }
    }
}

// ----------------------------------------------------------------------------
// Tensor-core causal flash attention (tf32 mma.sync) — unchanged.
// ----------------------------------------------------------------------------
#define QPITCH 68
#define KPITCH 68
#define VPITCH 36
#define PPITCH 36
#define AT_QOFF 0
#define AT_KOFF (128 * QPITCH)
#define AT_VOFF (AT_KOFF + 2 * 32 * KPITCH)
#define AT_POFF (AT_VOFF + 2 * 64 * VPITCH)
#define AT_SMEM ((AT_POFF + 4 * 32 * PPITCH) * 4)  // 89088 B

__global__ void __launch_bounds__(128) attn_k()
{
    extern __shared__ float smA[];
    const int tid = threadIdx.x, lane = tid & 31, wid = tid >> 5;
    const int bh = blockIdx.y;
    const int rb = (int)gridDim.x - 1 - (int)blockIdx.x;
    const int R0 = rb * 128;
    const size_t qkbase = (size_t)bh * TLEN * HS;
    const size_t vbase  = (size_t)bh * HS * TLEN;

    uint32_t QsU = smem_u32(smA);
    uint32_t KsU[2], VtU[2];
    KsU[0] = QsU + AT_KOFF * 4;  KsU[1] = KsU[0] + 32 * KPITCH * 4;
    VtU[0] = QsU + AT_VOFF * 4;  VtU[1] = VtU[0] + 64 * VPITCH * 4;
    uint32_t PsU = QsU + (AT_POFF + wid * 32 * PPITCH) * 4;

    {
        const float* src = g_q + qkbase + (size_t)R0 * 64;
#pragma unroll
        for (int i = 0; i < 16; i++) {
            int c = tid + i * 128;
            int row = c >> 4, ch = c & 15;
            cp16(QsU + (row * QPITCH + ch * 4) * 4, src + row * 64 + ch * 4);
        }
    }
    auto load_tile = [&](int kt, int b) {
        const float* ks = g_kk + qkbase + (size_t)kt * 32 * 64;
#pragma unroll
        for (int i = 0; i < 4; i++) {
            int c = tid + i * 128;
            int row = c >> 4, ch = c & 15;
            cp16(KsU[b] + (row * KPITCH + ch * 4) * 4, ks + row * 64 + ch * 4);
        }
        const float* vs = g_v + vbase + kt * 32;
#pragma unroll
        for (int i = 0; i < 4; i++) {
            int c = tid + i * 128;
            int row = c >> 3, ch = c & 7;
            cp16(VtU[b] + (row * VPITCH + ch * 4) * 4, vs + (size_t)row * 2048 + ch * 4);
        }
    };

    const int NT = R0 / 32 + 4;
    const int maskstart = R0 / 32;

    load_tile(0, 0);
    cp_commit();

    const int arow = (lane & 7) + ((lane >> 3) & 1) * 8;
    const int ahalf = (lane >> 4) & 1;
    uint32_t offQ[2], offP[2], offK[2], offV[4];
#pragma unroll
    for (int mi = 0; mi < 2; mi++) {
        offQ[mi] = ((wid * 32 + mi * 16 + arow) * QPITCH + ahalf * 4) * 4;
        offP[mi] = ((mi * 16 + arow) * PPITCH + ahalf * 4) * 4;
    }
#pragma unroll
    for (int g = 0; g < 2; g++) offK[g] = ((g * 16 + arow) * KPITCH + ahalf * 4) * 4;
#pragma unroll
    for (int g = 0; g < 4; g++) offV[g] = ((g * 16 + arow) * VPITCH + ahalf * 4) * 4;

    uint32_t qf[2][8][4];
    float oacc[2][8][4] = {};
    float m_run[4] = {-1e30f, -1e30f, -1e30f, -1e30f};
    float l_run[4] = {};

    const int srow = lane >> 2;
    const int scol = (lane & 3) * 2;

    for (int it = 0; it < NT; it++) {
        __syncthreads();
        if (it + 1 < NT) load_tile(it + 1, (it + 1) & 1);
        cp_commit();
        cp_wait1();
        __syncthreads();

        if (it == 0) {
#pragma unroll
            for (int mi = 0; mi < 2; mi++)
#pragma unroll
                for (int kt = 0; kt < 8; kt++) {
                    ldsm_x4(qf[mi][kt], QsU + offQ[mi] + kt * 32);
#pragma unroll
                    for (int i = 0; i < 4; i++)
                        qf[mi][kt][i] = __float_as_uint(__uint_as_float(qf[mi][kt][i]) * 0.125f);
                }
        }

        const uint32_t Kb = KsU[it & 1], Vb = VtU[it & 1];

        float sacc[2][4][4] = {};
#pragma unroll
        for (int kt = 0; kt < 8; kt++) {
#pragma unroll
            for (int g = 0; g < 2; g++) {
                uint32_t kb[4];
                ldsm_x4(kb, Kb + offK[g] + kt * 32);
                uint32_t blo[2] = {kb[0], kb[2]}, bhi[2] = {kb[1], kb[3]};
#pragma unroll
                for (int mi = 0; mi < 2; mi++) {
                    mma8(sacc[mi][g * 2],     qf[mi][kt], blo);
                    mma8(sacc[mi][g * 2 + 1], qf[mi][kt], bhi);
                }
            }
        }

        if (it >= maskstart) {
            const int colbase = it * 32 + scol;
#pragma unroll
            for (int mi = 0; mi < 2; mi++) {
                const int rowb = R0 + wid * 32 + mi * 16 + srow;
#pragma unroll
                for (int nt = 0; nt < 4; nt++)
#pragma unroll
                    for (int j = 0; j < 4; j++) {
                        int col = colbase + nt * 8 + (j & 1);
                        int row = rowb + 8 * (j >> 1);
                        if (col > row) sacc[mi][nt][j] = -1e30f;
                    }
            }
        }

#pragma unroll
        for (int mi = 0; mi < 2; mi++) {
#pragma unroll
            for (int hf = 0; hf < 2; hf++) {
                const int slot = mi * 2 + hf;
                float vmax = m_run[slot];
#pragma unroll
                for (int nt = 0; nt < 4; nt++) {
                    vmax = fmaxf(vmax, sacc[mi][nt][hf * 2]);
                    vmax = fmaxf(vmax, sacc[mi][nt][hf * 2 + 1]);
                }
                vmax = fmaxf(vmax, __shfl_xor_sync(0xffffffffu, vmax, 1));
                vmax = fmaxf(vmax, __shfl_xor_sync(0xffffffffu, vmax, 2));
                const float mnew = vmax;
                const float scale = __expf(m_run[slot] - mnew);
                float lsum = 0.f;
                const int prow = mi * 16 + srow + 8 * hf;
#pragma unroll
                for (int nt = 0; nt < 4; nt++) {
                    float p0 = __expf(sacc[mi][nt][hf * 2]     - mnew);
                    float p1 = __expf(sacc[mi][nt][hf * 2 + 1] - mnew);
                    lsum += p0 + p1;
                    float2 pv = make_float2(f2tf_f(p0), f2tf_f(p1));
                    asm volatile("st.shared.v2.f32 [%0], {%1,%2};"
                                 :: "r"(PsU + (prow * PPITCH + nt * 8 + scol) * 4),
                                    "f"(pv.x), "f"(pv.y) : "memory");
                }
                lsum += __shfl_xor_sync(0xffffffffu, lsum, 1);
                lsum += __shfl_xor_sync(0xffffffffu, lsum, 2);
                l_run[slot] = l_run[slot] * scale + lsum;
                m_run[slot] = mnew;
#pragma unroll
                for (int nt = 0; nt < 8; nt++) {
                    oacc[mi][nt][hf * 2]     *= scale;
                    oacc[mi][nt][hf * 2 + 1] *= scale;
                }
            }
        }

#pragma unroll
        for (int kt = 0; kt < 4; kt++) {
            uint32_t pa[2][4];
#pragma unroll
            for (int mi = 0; mi < 2; mi++) ldsm_x4(pa[mi], PsU + offP[mi] + kt * 32);
#pragma unroll
            for (int g = 0; g < 4; g++) {
                uint32_t vb[4];
                ldsm_x4(vb, Vb + offV[g] + kt * 32);
                uint32_t blo[2] = {vb[0], vb[2]}, bhi[2] = {vb[1], vb[3]};
#pragma unroll
                for (int mi = 0; mi < 2; mi++) {
                    mma8(oacc[mi][g * 2],     pa[mi], blo);
                    mma8(oacc[mi][g * 2 + 1], pa[mi], bhi);
                }
            }
        }
    }

    const int b = bh >> 4, h = bh & 15;
#pragma unroll
    for (int mi = 0; mi < 2; mi++) {
#pragma unroll
        for (int hf = 0; hf < 2; hf++) {
            const float inv = 1.f / l_run[mi * 2 + hf];
            const int grow = R0 + wid * 32 + mi * 16 + srow + 8 * hf;
            float* op = g_attn + ((size_t)(b * 2048 + grow)) * 1024 + h * 64 + scol;
#pragma unroll
            for (int nt = 0; nt < 8; nt++) {
                float2 ov = make_float2(f2tf_f(oacc[mi][nt][hf * 2] * inv),
                                        f2tf_f(oacc[mi][nt][hf * 2 + 1] * inv));
                *(float2*)(op + nt * 8) = ov;
            }
        }
    }
}

// ----------------------------------------------------------------------------
// Launch
// ----------------------------------------------------------------------------
extern "C" void kernel_launch(void* const* d_in, const int* in_sizes, int n_in,
                              void* d_out, int out_size)
{
    const float* x     = (const float*)d_in[0];
    const float* Wq    = (const float*)d_in[1];
    const float* Wk    = (const float*)d_in[2];
    const float* Wv    = (const float*)d_in[3];
    const float* Wproj = (const float*)d_in[4];
    const float* bproj = (const float*)d_in[5];
    const float* g1    = (const float*)d_in[6];
    const float* b1    = (const float*)d_in[7];
    const float* g2    = (const float*)d_in[8];
    const float* b2    = (const float*)d_in[9];
    const float* Wff1  = (const float*)d_in[10];
    const float* bff1  = (const float*)d_in[11];
    const float* Wff2  = (const float*)d_in[12];
    const float* bff2  = (const float*)d_in[13];
    float* out = (float*)d_out;

    cudaFuncSetAttribute(mgemm<0>, cudaFuncAttributeMaxDynamicSharedMemorySize, MG_SMEM);
    cudaFuncSetAttribute(mgemm<1>, cudaFuncAttributeMaxDynamicSharedMemorySize, MG_SMEM);
    cudaFuncSetAttribute(mgemm<2>, cudaFuncAttributeMaxDynamicSharedMemorySize, MG_SMEM);
    cudaFuncSetAttribute(mgemm<3>, cudaFuncAttributeMaxDynamicSharedMemorySize, MG_SMEM);
    cudaFuncSetAttribute(attn_k,   cudaFuncAttributeMaxDynamicSharedMemorySize, AT_SMEM);

    transpose_k<<<dim3(HS / 32, CDIM / 32, NHEAD), 256>>>(Wq, 0, CDIM, HS);
    transpose_k<<<dim3(HS / 32, CDIM / 32, NHEAD), 256>>>(Wk, 1, CDIM, HS);
    transpose_k<<<dim3(HS / 32, CDIM / 32, NHEAD), 256>>>(Wv, 2, CDIM, HS);
    transpose_k<<<dim3(CDIM / 32, CDIM / 32, 1),   256>>>(Wproj, 3, CDIM, CDIM);
    transpose_k<<<dim3(FDIM / 32, CDIM / 32, 1),   256>>>(Wff1, 4, CDIM, FDIM);
    transpose_k<<<dim3(CDIM / 32, FDIM / 32, 1),   256>>>(Wff2, 5, FDIM, CDIM);

    ln_k<<<MROWS, 256>>>(0, x, g1, b1);
    mgemm<0><<<dim3(CDIM / 256, MROWS / 128, 3), 256, MG_SMEM>>>(nullptr, nullptr, nullptr);
    attn_k<<<dim3(TLEN / 128, NHEAD * 2), 128, AT_SMEM>>>();
    mgemm<1><<<dim3(CDIM / 256, MROWS / 128), 256, MG_SMEM>>>(bproj, x, nullptr);
    ln_k<<<MROWS, 256>>>(1, nullptr, g2, b2);
    mgemm<2><<<dim3(FDIM / 256, MROWS / 128), 256, MG_SMEM>>>(bff1, nullptr, nullptr);
    mgemm<3><<<dim3(CDIM / 256, MROWS / 128), 256, MG_SMEM>>>(bff2, nullptr, out);
}

// round 8
// speedup vs baseline: 6.5768x; 1.7481x over previous
#include <cuda_runtime.h>
#include <cuda_fp16.h>
#include <cstdint>
#include <cstddef>

// ----------------------------------------------------------------------------
// B=2, T=2048, C=1024, H=16, hs=64 ; M = B*T = 4096
// ----------------------------------------------------------------------------
#define MROWS 4096
#define CDIM  1024
#define FDIM  4096
#define TLEN  2048
#define NHEAD 16
#define HS    64

__device__ __half g_h1[MROWS * CDIM];          // fp16 operands
__device__ __half g_q [MROWS * CDIM];          // [B,H,T,hs]
__device__ __half g_kk[MROWS * CDIM];          // [B,H,T,hs]
__device__ __half g_v [MROWS * CDIM];          // [B,H,hs,T] (TRANSPOSED)
__device__ __half g_attn[MROWS * CDIM];        // row-major
__device__ float  g_x1[MROWS * CDIM];          // fp32 residual path
__device__ __half g_h2[MROWS * CDIM];
__device__ __half g_ff1[(size_t)MROWS * FDIM];
__device__ __half g_wqT[CDIM * CDIM];          // Bt[n][k]
__device__ __half g_wkT[CDIM * CDIM];
__device__ __half g_wvT[CDIM * CDIM];
__device__ __half g_wpT[CDIM * CDIM];
__device__ __half g_wf1T[(size_t)CDIM * FDIM];
__device__ __half g_wf2T[(size_t)CDIM * FDIM];

// ----------------------------------------------------------------------------
// Helpers (baseline sm_80+; NO tcgen05)
// ----------------------------------------------------------------------------
__device__ __forceinline__ uint32_t smem_u32(const void* p) {
    return (uint32_t)__cvta_generic_to_shared(p);
}
__device__ __forceinline__ void cp16(uint32_t dst, const void* src) {
    asm volatile("cp.async.cg.shared.global [%0], [%1], 16;\n" :: "r"(dst), "l"(src));
}
__device__ __forceinline__ void cp_commit() {
    asm volatile("cp.async.commit_group;\n" ::: "memory");
}
__device__ __forceinline__ void cp_wait1() {
    asm volatile("cp.async.wait_group 1;\n" ::: "memory");
}
__device__ __forceinline__ void cp_wait2() {
    asm volatile("cp.async.wait_group 2;\n" ::: "memory");
}
// fp16 mma: D(f32) += A(f16 m16k16) * B(f16 k16n8)
__device__ __forceinline__ void mma16(float* d, const uint32_t* a, const uint32_t* b) {
    asm volatile(
        "mma.sync.aligned.m16n8k16.row.col.f32.f16.f16.f32 "
        "{%0,%1,%2,%3},{%4,%5,%6,%7},{%8,%9},{%0,%1,%2,%3};"
        : "+f"(d[0]), "+f"(d[1]), "+f"(d[2]), "+f"(d[3])
        : "r"(a[0]), "r"(a[1]), "r"(a[2]), "r"(a[3]), "r"(b[0]), "r"(b[1]));
}
__device__ __forceinline__ void ldsm_x4(uint32_t* r, uint32_t addr) {
    asm volatile("ldmatrix.sync.aligned.m8n8.x4.shared.b16 {%0,%1,%2,%3}, [%4];"
                 : "=r"(r[0]), "=r"(r[1]), "=r"(r[2]), "=r"(r[3]) : "r"(addr));
}

// ----------------------------------------------------------------------------
// LayerNorm (fp16 output; consumed only by GEMMs)
// ----------------------------------------------------------------------------
__global__ void __launch_bounds__(256) ln_k(int mode, const float* __restrict__ x_ext,
                                            const float* __restrict__ g,
                                            const float* __restrict__ b)
{
    const float* in = (mode == 0) ? x_ext : g_x1;
    __half* out     = (mode == 0) ? g_h1  : g_h2;
    int row = blockIdx.x;
    int tid = threadIdx.x;
    size_t base = (size_t)row * CDIM;

    float v[4];
    float s = 0.f, s2 = 0.f;
#pragma unroll
    for (int i = 0; i < 4; i++) {
        v[i] = in[base + tid + i * 256];
        s += v[i]; s2 += v[i] * v[i];
    }
#pragma unroll
    for (int off = 16; off; off >>= 1) {
        s  += __shfl_xor_sync(0xffffffffu, s,  off);
        s2 += __shfl_xor_sync(0xffffffffu, s2, off);
    }
    __shared__ float rs[8], rs2[8];
    int warp = tid >> 5, lane = tid & 31;
    if (lane == 0) { rs[warp] = s; rs2[warp] = s2; }
    __syncthreads();
    __shared__ float mu_s, rstd_s;
    if (tid == 0) {
        float ts = 0.f, ts2 = 0.f;
#pragma unroll
        for (int i = 0; i < 8; i++) { ts += rs[i]; ts2 += rs2[i]; }
        float mu = ts * (1.f / CDIM);
        float var = ts2 * (1.f / CDIM) - mu * mu;
        mu_s = mu; rstd_s = rsqrtf(var + 1e-5f);
    }
    __syncthreads();
    float mu = mu_s, rstd = rstd_s;
#pragma unroll
    for (int i = 0; i < 4; i++) {
        int c = tid + i * 256;
        out[base + c] = __float2half((v[i] - mu) * rstd * g[c] + b[c]);
    }
}

// ----------------------------------------------------------------------------
// Batched 32x32 transpose -> Bt[n][k], fp16
// ----------------------------------------------------------------------------
__global__ void __launch_bounds__(256) transpose_k(const float* __restrict__ in,
                                                   int outsel, int R, int Cc)
{
    __shared__ float t[32][33];
    __half* outg;
    switch (outsel) {
        case 0: outg = g_wqT; break;
        case 1: outg = g_wkT; break;
        case 2: outg = g_wvT; break;
        case 3: outg = g_wpT; break;
        case 4: outg = g_wf1T; break;
        default: outg = g_wf2T; break;
    }
    int batch = blockIdx.z;
    const float* ip = in + (size_t)batch * R * Cc;
    __half* op = outg + (size_t)batch * R * Cc;
    int c0 = blockIdx.x * 32, r0 = blockIdx.y * 32;
    int tx = threadIdx.x & 31, ty = threadIdx.x >> 5;
#pragma unroll
    for (int i = 0; i < 32; i += 8)
        t[ty + i][tx] = ip[(size_t)(r0 + ty + i) * Cc + c0 + tx];
    __syncthreads();
#pragma unroll
    for (int i = 0; i < 32; i += 8)
        op[(size_t)(c0 + ty + i) * R + r0 + tx] = __float2half(t[tx][ty + i]);
}

// ----------------------------------------------------------------------------
// fp16 mma.sync GEMM, CTA tile 128(M) x 256(N), 8 warps (2x4), warp = 64x64.
// m16n8k16, BK=64 halves, 4-stage cp.async pipeline. Pitch 72 halves (144B).
// MODE 0: A=g_h1, Bt=wq/wk/wvT (z) -> g_q/g_kk (row) / g_v (transposed), fp16
// MODE 1: A=g_attn, Bt=g_wpT -> g_x1 = acc + bias + resid(x)  (fp32)
// MODE 2: A=g_h2,  Bt=g_wf1T -> g_ff1 = relu(acc + bias)  (fp16, N=4096)
// MODE 3: A=g_ff1 (K=4096), Bt=g_wf2T -> outp = acc + bias + g_x1  (fp32)
// ----------------------------------------------------------------------------
#define GPITCH 72
#define STG_HALVES ((128 + 256) * GPITCH)
#define MG_SMEM    (4 * STG_HALVES * 2)   // 221184 B

template <int MODE>
__global__ void __launch_bounds__(256) mgemm(const float* __restrict__ bias,
                                             const float* __restrict__ resid,
                                             float* __restrict__ outp)
{
    constexpr int K = (MODE == 3) ? 4096 : 1024;
    constexpr int NKIT = K / 64;

    extern __shared__ __half smh[];
    const int tid = threadIdx.x, lane = tid & 31, wid = tid >> 5;
    const int wm = wid & 1, wn = wid >> 1;   // warp tile: rows wm*64, cols wn*64
    const int m0 = blockIdx.y * 128;
    const int n0 = blockIdx.x * 256;

    const __half* A;
    if      (MODE == 0) A = g_h1;
    else if (MODE == 1) A = g_attn;
    else if (MODE == 2) A = g_h2;
    else                A = g_ff1;

    const __half* B;
    if (MODE == 0) B = (blockIdx.z == 0) ? g_wqT : ((blockIdx.z == 1) ? g_wkT : g_wvT);
    else if (MODE == 1) B = g_wpT;
    else if (MODE == 2) B = g_wf1T;
    else                B = g_wf2T;

    float acc[4][8][4] = {};

    auto load_stage = [&](int j, int s) {
        __half* As = smh + s * STG_HALVES;
        __half* Bs = As + 128 * GPITCH;
        // A: 128 rows x 64 halves = 8 chunks/row -> 1024 chunks, 4/thread
#pragma unroll
        for (int i = 0; i < 4; i++) {
            int c = tid + i * 256;
            int row = c >> 3, kc = c & 7;
            cp16(smem_u32(As + row * GPITCH + kc * 8),
                 A + (size_t)(m0 + row) * K + j * 64 + kc * 8);
        }
        // B: 256 rows -> 2048 chunks, 8/thread
#pragma unroll
        for (int i = 0; i < 8; i++) {
            int c = tid + i * 256;
            int row = c >> 3, kc = c & 7;
            cp16(smem_u32(Bs + row * GPITCH + kc * 8),
                 B + (size_t)(n0 + row) * K + j * 64 + kc * 8);
        }
        cp_commit();
    };

    // ldmatrix lane offsets (bytes): row = m16-local row, +16B for k8-15 half
    const int arow = (lane & 7) + ((lane >> 3) & 1) * 8;
    const int ahalf = (lane >> 4) & 1;
    uint32_t offA[4], offB[4];
#pragma unroll
    for (int mi = 0; mi < 4; mi++)
        offA[mi] = ((wm * 64 + mi * 16 + arow) * GPITCH + ahalf * 8) * 2;
#pragma unroll
    for (int g = 0; g < 4; g++)
        offB[g] = ((wn * 64 + g * 16 + arow) * GPITCH + ahalf * 8) * 2;

    load_stage(0, 0);
    load_stage(1, 1);
    load_stage(2, 2);

    for (int it = 0; it < NKIT; it++) {
        int s = it & 3;
        cp_wait2();
        __syncthreads();
        if (it + 3 < NKIT) load_stage(it + 3, (it + 3) & 3);
        else cp_commit();

        uint32_t AsU = smem_u32(smh + s * STG_HALVES);
        uint32_t BsU = AsU + 128 * GPITCH * 2;

#pragma unroll
        for (int ks = 0; ks < 4; ks++) {   // 4 x k16 per 64-half stage
            uint32_t af[4][4], bb[4][4];
#pragma unroll
            for (int mi = 0; mi < 4; mi++) ldsm_x4(af[mi], AsU + offA[mi] + ks * 32);
#pragma unroll
            for (int g = 0; g < 4; g++)  ldsm_x4(bb[g], BsU + offB[g] + ks * 32);
#pragma unroll
            for (int mi = 0; mi < 4; mi++)
#pragma unroll
                for (int g = 0; g < 4; g++) {
                    uint32_t blo[2] = {bb[g][0], bb[g][2]};
                    uint32_t bhi[2] = {bb[g][1], bb[g][3]};
                    mma16(acc[mi][g * 2],     af[mi], blo);
                    mma16(acc[mi][g * 2 + 1], af[mi], bhi);
                }
        }
    }

    // epilogue: d0:(r,c) d1:(r,c+1) d2:(r+8,c) d3:(r+8,c+1)
#pragma unroll
    for (int mi = 0; mi < 4; mi++) {
#pragma unroll
        for (int nj = 0; nj < 8; nj++) {
#pragma unroll
            for (int half = 0; half < 2; half++) {
                int gm = m0 + wm * 64 + mi * 16 + (lane >> 2) + half * 8;
                int gn = n0 + wn * 64 + nj * 8 + (lane & 3) * 2;
                float v0 = acc[mi][nj][half * 2 + 0];
                float v1 = acc[mi][nj][half * 2 + 1];
                if (MODE == 0) {
                    int bb2 = gm >> 11, t = gm & 2047;
                    int h = gn >> 6, d0 = gn & 63;
                    if (blockIdx.z == 2) {
                        __half* op = g_v + ((size_t)((bb2 * 16 + h) * 64 + d0)) * 2048 + t;
                        op[0]    = __float2half(v0);
                        op[2048] = __float2half(v1);
                    } else {
                        __half* sel = (blockIdx.z == 0) ? g_q : g_kk;
                        __half* op = sel + ((size_t)((bb2 * 16 + h) * 2048 + t)) * 64 + d0;
                        *(__half2*)op = __floats2half2_rn(v0, v1);
                    }
                } else if (MODE == 1) {
                    size_t o = (size_t)gm * 1024 + gn;
                    g_x1[o]     = v0 + bias[gn]     + resid[o];
                    g_x1[o + 1] = v1 + bias[gn + 1] + resid[o + 1];
                } else if (MODE == 2) {
                    size_t o = (size_t)gm * 4096 + gn;
                    *(__half2*)(g_ff1 + o) =
                        __floats2half2_rn(fmaxf(v0 + bias[gn], 0.f),
                                          fmaxf(v1 + bias[gn + 1], 0.f));
                } else {
                    size_t o = (size_t)gm * 1024 + gn;
                    outp[o]     = v0 + bias[gn]     + g_x1[o];
                    outp[o + 1] = v1 + bias[gn + 1] + g_x1[o + 1];
                }
            }
        }
    }
}

// ----------------------------------------------------------------------------
// fp16 tensor-core causal flash attention.
// Grid (16, 32). Block 128 thr / 4 warps; warp owns 32 query rows.
// 32-key tiles, double-buffered cp.async; V pre-transposed [B,H,hs,T].
// ----------------------------------------------------------------------------
#define QPITCH 72
#define KPITCH 72
#define VPITCH 40
#define PPITCH 40
// halves: Q 128*72 | K 2*32*72 | Vt 2*64*40 | P 4*32*40
#define AT_KOFF (128 * QPITCH)
#define AT_VOFF (AT_KOFF + 2 * 32 * KPITCH)
#define AT_POFF (AT_VOFF + 2 * 64 * VPITCH)
#define AT_SMEM ((AT_POFF + 4 * 32 * PPITCH) * 2)  // 48128 B

__global__ void __launch_bounds__(128) attn_k()
{
    extern __shared__ __half smA[];
    const int tid = threadIdx.x, lane = tid & 31, wid = tid >> 5;
    const int bh = blockIdx.y;
    const int rb = (int)gridDim.x - 1 - (int)blockIdx.x;  // heavy blocks first
    const int R0 = rb * 128;
    const size_t qkbase = (size_t)bh * TLEN * HS;
    const size_t vbase  = (size_t)bh * HS * TLEN;

    uint32_t QsU = smem_u32(smA);
    uint32_t KsU[2], VtU[2];
    KsU[0] = QsU + AT_KOFF * 2;  KsU[1] = KsU[0] + 32 * KPITCH * 2;
    VtU[0] = QsU + AT_VOFF * 2;  VtU[1] = VtU[0] + 64 * VPITCH * 2;
    uint32_t PsU = QsU + (AT_POFF + wid * 32 * PPITCH) * 2;

    // Q block 128x64 halves: 8 chunks/row -> 8 per thread
    {
        const __half* src = g_q + qkbase + (size_t)R0 * 64;
#pragma unroll
        for (int i = 0; i < 8; i++) {
            int c = tid + i * 128;
            int row = c >> 3, ch = c & 7;
            cp16(QsU + (row * QPITCH + ch * 8) * 2, src + row * 64 + ch * 8);
        }
    }
    auto load_tile = [&](int kt, int b) {
        const __half* ks = g_kk + qkbase + (size_t)kt * 32 * 64;
#pragma unroll
        for (int i = 0; i < 2; i++) {
            int c = tid + i * 128;
            int row = c >> 3, ch = c & 7;
            cp16(KsU[b] + (row * KPITCH + ch * 8) * 2, ks + row * 64 + ch * 8);
        }
        const __half* vs = g_v + vbase + kt * 32;
#pragma unroll
        for (int i = 0; i < 2; i++) {
            int c = tid + i * 128;
            int row = c >> 2, ch = c & 3;
            cp16(VtU[b] + (row * VPITCH + ch * 8) * 2, vs + (size_t)row * 2048 + ch * 8);
        }
    };

    const int NT = R0 / 32 + 4;
    const int maskstart = R0 / 32;

    load_tile(0, 0);
    cp_commit();   // group 0: Q + tile0

    const int arow = (lane & 7) + ((lane >> 3) & 1) * 8;
    const int ahalf = (lane >> 4) & 1;
    uint32_t offQ[2], offP[2], offK[2], offV[4];
#pragma unroll
    for (int mi = 0; mi < 2; mi++) {
        offQ[mi] = ((wid * 32 + mi * 16 + arow) * QPITCH + ahalf * 8) * 2;
        offP[mi] = ((mi * 16 + arow) * PPITCH + ahalf * 8) * 2;
    }
#pragma unroll
    for (int g = 0; g < 2; g++) offK[g] = ((g * 16 + arow) * KPITCH + ahalf * 8) * 2;
#pragma unroll
    for (int g = 0; g < 4; g++) offV[g] = ((g * 16 + arow) * VPITCH + ahalf * 8) * 2;

    uint32_t qf[2][4][4];
    float oacc[2][8][4] = {};
    float m_run[4] = {-1e30f, -1e30f, -1e30f, -1e30f};
    float l_run[4] = {};

    const int srow = lane >> 2;
    const int scol = (lane & 3) * 2;

    for (int it = 0; it < NT; it++) {
        __syncthreads();
        if (it + 1 < NT) load_tile(it + 1, (it + 1) & 1);
        cp_commit();
        cp_wait1();
        __syncthreads();

        if (it == 0) {
            const __half2 sc = __float2half2_rn(0.125f);  // hs^-0.5, exact
#pragma unroll
            for (int mi = 0; mi < 2; mi++)
#pragma unroll
                for (int kt = 0; kt < 4; kt++) {
                    ldsm_x4(qf[mi][kt], QsU + offQ[mi] + kt * 32);
#pragma unroll
                    for (int i = 0; i < 4; i++) {
                        __half2 h = *(__half2*)&qf[mi][kt][i];
                        h = __hmul2(h, sc);
                        qf[mi][kt][i] = *(uint32_t*)&h;
                    }
                }
        }

        const uint32_t Kb = KsU[it & 1], Vb = VtU[it & 1];

        // ---- S = Q K^T ----
        float sacc[2][4][4] = {};
#pragma unroll
        for (int kt = 0; kt < 4; kt++) {
#pragma unroll
            for (int g = 0; g < 2; g++) {
                uint32_t kb[4];
                ldsm_x4(kb, Kb + offK[g] + kt * 32);
                uint32_t blo[2] = {kb[0], kb[2]}, bhi[2] = {kb[1], kb[3]};
#pragma unroll
                for (int mi = 0; mi < 2; mi++) {
                    mma16(sacc[mi][g * 2],     qf[mi][kt], blo);
                    mma16(sacc[mi][g * 2 + 1], qf[mi][kt], bhi);
                }
            }
        }

        // ---- causal mask (diagonal tiles only) ----
        if (it >= maskstart) {
            const int colbase = it * 32 + scol;
#pragma unroll
            for (int mi = 0; mi < 2; mi++) {
                const int rowb = R0 + wid * 32 + mi * 16 + srow;
#pragma unroll
                for (int nt = 0; nt < 4; nt++)
#pragma unroll
                    for (int j = 0; j < 4; j++) {
                        int col = colbase + nt * 8 + (j & 1);
                        int row = rowb + 8 * (j >> 1);
                        if (col > row) sacc[mi][nt][j] = -1e30f;
                    }
            }
        }

        // ---- online softmax + P store (fp16 pairs) ----
#pragma unroll
        for (int mi = 0; mi < 2; mi++) {
#pragma unroll
            for (int hf = 0; hf < 2; hf++) {
                const int slot = mi * 2 + hf;
                float vmax = m_run[slot];
#pragma unroll
                for (int nt = 0; nt < 4; nt++) {
                    vmax = fmaxf(vmax, sacc[mi][nt][hf * 2]);
                    vmax = fmaxf(vmax, sacc[mi][nt][hf * 2 + 1]);
                }
                vmax = fmaxf(vmax, __shfl_xor_sync(0xffffffffu, vmax, 1));
                vmax = fmaxf(vmax, __shfl_xor_sync(0xffffffffu, vmax, 2));
                const float mnew = vmax;
                const float scale = __expf(m_run[slot] - mnew);
                float lsum = 0.f;
                const int prow = mi * 16 + srow + 8 * hf;
#pragma unroll
                for (int nt = 0; nt < 4; nt++) {
                    float p0 = __expf(sacc[mi][nt][hf * 2]     - mnew);
                    float p1 = __expf(sacc[mi][nt][hf * 2 + 1] - mnew);
                    lsum += p0 + p1;
                    __half2 ph = __floats2half2_rn(p0, p1);
                    asm volatile("st.shared.u32 [%0], %1;"
                                 :: "r"(PsU + (prow * PPITCH + nt * 8 + scol) * 2),
                                    "r"(*(uint32_t*)&ph) : "memory");
                }
                lsum += __shfl_xor_sync(0xffffffffu, lsum, 1);
                lsum += __shfl_xor_sync(0xffffffffu, lsum, 2);
                l_run[slot] = l_run[slot] * scale + lsum;
                m_run[slot] = mnew;
#pragma unroll
                for (int nt = 0; nt < 8; nt++) {
                    oacc[mi][nt][hf * 2]     *= scale;
                    oacc[mi][nt][hf * 2 + 1] *= scale;
                }
            }
        }

        // ---- O += P V ---- (P warp-private)
#pragma unroll
        for (int kt = 0; kt < 2; kt++) {
            uint32_t pa[2][4];
#pragma unroll
            for (int mi = 0; mi < 2; mi++) ldsm_x4(pa[mi], PsU + offP[mi] + kt * 32);
#pragma unroll
            for (int g = 0; g < 4; g++) {
                uint32_t vb[4];
                ldsm_x4(vb, Vb + offV[g] + kt * 32);
                uint32_t blo[2] = {vb[0], vb[2]}, bhi[2] = {vb[1], vb[3]};
#pragma unroll
                for (int mi = 0; mi < 2; mi++) {
                    mma16(oacc[mi][g * 2],     pa[mi], blo);
                    mma16(oacc[mi][g * 2 + 1], pa[mi], bhi);
                }
            }
        }
    }

    // ---- finalize: O /= l, write fp16 row-major ----
    const int b = bh >> 4, h = bh & 15;
#pragma unroll
    for (int mi = 0; mi < 2; mi++) {
#pragma unroll
        for (int hf = 0; hf < 2; hf++) {
            const float inv = 1.f / l_run[mi * 2 + hf];
            const int grow = R0 + wid * 32 + mi * 16 + srow + 8 * hf;
            __half* op = g_attn + ((size_t)(b * 2048 + grow)) * 1024 + h * 64 + scol;
#pragma unroll
            for (int nt = 0; nt < 8; nt++)
                *(__half2*)(op + nt * 8) =
                    __floats2half2_rn(oacc[mi][nt][hf * 2] * inv,
                                      oacc[mi][nt][hf * 2 + 1] * inv);
        }
    }
}

// ----------------------------------------------------------------------------
// Launch
// ----------------------------------------------------------------------------
extern "C" void kernel_launch(void* const* d_in, const int* in_sizes, int n_in,
                              void* d_out, int out_size)
{
    const float* x     = (const float*)d_in[0];
    const float* Wq    = (const float*)d_in[1];
    const float* Wk    = (const float*)d_in[2];
    const float* Wv    = (const float*)d_in[3];
    const float* Wproj = (const float*)d_in[4];
    const float* bproj = (const float*)d_in[5];
    const float* g1    = (const float*)d_in[6];
    const float* b1    = (const float*)d_in[7];
    const float* g2    = (const float*)d_in[8];
    const float* b2    = (const float*)d_in[9];
    const float* Wff1  = (const float*)d_in[10];
    const float* bff1  = (const float*)d_in[11];
    const float* Wff2  = (const float*)d_in[12];
    const float* bff2  = (const float*)d_in[13];
    float* out = (float*)d_out;

    cudaFuncSetAttribute(mgemm<0>, cudaFuncAttributeMaxDynamicSharedMemorySize, MG_SMEM);
    cudaFuncSetAttribute(mgemm<1>, cudaFuncAttributeMaxDynamicSharedMemorySize, MG_SMEM);
    cudaFuncSetAttribute(mgemm<2>, cudaFuncAttributeMaxDynamicSharedMemorySize, MG_SMEM);
    cudaFuncSetAttribute(mgemm<3>, cudaFuncAttributeMaxDynamicSharedMemorySize, MG_SMEM);
    cudaFuncSetAttribute(attn_k,   cudaFuncAttributeMaxDynamicSharedMemorySize, AT_SMEM);

    transpose_k<<<dim3(HS / 32, CDIM / 32, NHEAD), 256>>>(Wq, 0, CDIM, HS);
    transpose_k<<<dim3(HS / 32, CDIM / 32, NHEAD), 256>>>(Wk, 1, CDIM, HS);
    transpose_k<<<dim3(HS / 32, CDIM / 32, NHEAD), 256>>>(Wv, 2, CDIM, HS);
    transpose_k<<<dim3(CDIM / 32, CDIM / 32, 1),   256>>>(Wproj, 3, CDIM, CDIM);
    transpose_k<<<dim3(FDIM / 32, CDIM / 32, 1),   256>>>(Wff1, 4, CDIM, FDIM);
    transpose_k<<<dim3(CDIM / 32, FDIM / 32, 1),   256>>>(Wff2, 5, FDIM, CDIM);

    ln_k<<<MROWS, 256>>>(0, x, g1, b1);
    mgemm<0><<<dim3(CDIM / 256, MROWS / 128, 3), 256, MG_SMEM>>>(nullptr, nullptr, nullptr);
    attn_k<<<dim3(TLEN / 128, NHEAD * 2), 128, AT_SMEM>>>();
    mgemm<1><<<dim3(CDIM / 256, MROWS / 128), 256, MG_SMEM>>>(bproj, x, nullptr);
    ln_k<<<MROWS, 256>>>(1, nullptr, g2, b2);
    mgemm<2><<<dim3(FDIM / 256, MROWS / 128), 256, MG_SMEM>>>(bff1, nullptr, nullptr);
    mgemm<3><<<dim3(CDIM / 256, MROWS / 128), 256, MG_SMEM>>>(bff2, nullptr, out);
}

// round 9
// speedup vs baseline: 6.9710x; 1.0599x over previous
#include <cuda_runtime.h>
#include <cuda_fp16.h>
#include <cstdint>
#include <cstddef>

// ----------------------------------------------------------------------------
// B=2, T=2048, C=1024, H=16, hs=64 ; M = B*T = 4096
// ----------------------------------------------------------------------------
#define MROWS 4096
#define CDIM  1024
#define FDIM  4096
#define TLEN  2048
#define NHEAD 16
#define HS    64

__device__ __half g_h1[MROWS * CDIM];          // fp16 operands
__device__ __half g_q [MROWS * CDIM];          // [B,H,T,hs]
__device__ __half g_kk[MROWS * CDIM];          // [B,H,T,hs]
__device__ __half g_v [MROWS * CDIM];          // [B,H,hs,T] (TRANSPOSED)
__device__ __half g_attn[MROWS * CDIM];        // row-major
__device__ float  g_x1[MROWS * CDIM];          // fp32 residual path
__device__ __half g_h2[MROWS * CDIM];
__device__ __half g_ff1[(size_t)MROWS * FDIM];
__device__ __half g_wqT[CDIM * CDIM];          // Bt[n][k]
__device__ __half g_wkT[CDIM * CDIM];
__device__ __half g_wvT[CDIM * CDIM];
__device__ __half g_wpT[CDIM * CDIM];
__device__ __half g_wf1T[(size_t)CDIM * FDIM];
__device__ __half g_wf2T[(size_t)CDIM * FDIM];

// ----------------------------------------------------------------------------
// Helpers (baseline sm_80+; NO tcgen05)
// ----------------------------------------------------------------------------
__device__ __forceinline__ uint32_t smem_u32(const void* p) {
    return (uint32_t)__cvta_generic_to_shared(p);
}
__device__ __forceinline__ void cp16(uint32_t dst, const void* src) {
    asm volatile("cp.async.cg.shared.global [%0], [%1], 16;\n" :: "r"(dst), "l"(src));
}
__device__ __forceinline__ void cp_commit() {
    asm volatile("cp.async.commit_group;\n" ::: "memory");
}
__device__ __forceinline__ void cp_wait1() {
    asm volatile("cp.async.wait_group 1;\n" ::: "memory");
}
__device__ __forceinline__ void mma16(float* d, const uint32_t* a, const uint32_t* b) {
    asm volatile(
        "mma.sync.aligned.m16n8k16.row.col.f32.f16.f16.f32 "
        "{%0,%1,%2,%3},{%4,%5,%6,%7},{%8,%9},{%0,%1,%2,%3};"
        : "+f"(d[0]), "+f"(d[1]), "+f"(d[2]), "+f"(d[3])
        : "r"(a[0]), "r"(a[1]), "r"(a[2]), "r"(a[3]), "r"(b[0]), "r"(b[1]));
}
__device__ __forceinline__ void ldsm_x4(uint32_t* r, uint32_t addr) {
    asm volatile("ldmatrix.sync.aligned.m8n8.x4.shared.b16 {%0,%1,%2,%3}, [%4];"
                 : "=r"(r[0]), "=r"(r[1]), "=r"(r[2]), "=r"(r[3]) : "r"(addr));
}

// ----------------------------------------------------------------------------
// LayerNorm (vectorized: float4 in, half2 out; thread owns 4 contiguous cols)
// ----------------------------------------------------------------------------
__global__ void __launch_bounds__(256) ln_k(int mode, const float* __restrict__ x_ext,
                                            const float* __restrict__ g,
                                            const float* __restrict__ b)
{
    const float* in = (mode == 0) ? x_ext : g_x1;
    __half* out     = (mode == 0) ? g_h1  : g_h2;
    int row = blockIdx.x;
    int tid = threadIdx.x;
    size_t base = (size_t)row * CDIM;

    float4 v = *(const float4*)(in + base + tid * 4);
    float s  = v.x + v.y + v.z + v.w;
    float s2 = v.x * v.x + v.y * v.y + v.z * v.z + v.w * v.w;
#pragma unroll
    for (int off = 16; off; off >>= 1) {
        s  += __shfl_xor_sync(0xffffffffu, s,  off);
        s2 += __shfl_xor_sync(0xffffffffu, s2, off);
    }
    __shared__ float rs[8], rs2[8];
    int warp = tid >> 5, lane = tid & 31;
    if (lane == 0) { rs[warp] = s; rs2[warp] = s2; }
    __syncthreads();
    __shared__ float mu_s, rstd_s;
    if (tid == 0) {
        float ts = 0.f, ts2 = 0.f;
#pragma unroll
        for (int i = 0; i < 8; i++) { ts += rs[i]; ts2 += rs2[i]; }
        float mu = ts * (1.f / CDIM);
        float var = ts2 * (1.f / CDIM) - mu * mu;
        mu_s = mu; rstd_s = rsqrtf(var + 1e-5f);
    }
    __syncthreads();
    float mu = mu_s, rstd = rstd_s;
    int c = tid * 4;
    float4 gg = *(const float4*)(g + c);
    float4 bb = *(const float4*)(b + c);
    __half2 h01 = __floats2half2_rn((v.x - mu) * rstd * gg.x + bb.x,
                                    (v.y - mu) * rstd * gg.y + bb.y);
    __half2 h23 = __floats2half2_rn((v.z - mu) * rstd * gg.z + bb.z,
                                    (v.w - mu) * rstd * gg.w + bb.w);
    *(__half2*)(out + base + c)     = h01;
    *(__half2*)(out + base + c + 2) = h23;
}

// ----------------------------------------------------------------------------
// Weight convert+transpose (fp32 [r][c] -> fp16 [c][r]), 32x32 tiles.
// ----------------------------------------------------------------------------
__device__ __forceinline__ void tr_tile(const float* __restrict__ ip,
                                        __half* __restrict__ op,
                                        int R, int Cc, int c0, int r0)
{
    __shared__ float t[32][33];
    int tx = threadIdx.x & 31, ty = threadIdx.x >> 5;
#pragma unroll
    for (int i = 0; i < 32; i += 8)
        t[ty + i][tx] = ip[(size_t)(r0 + ty + i) * Cc + c0 + tx];
    __syncthreads();
#pragma unroll
    for (int i = 0; i < 32; i += 8)
        op[(size_t)(c0 + ty + i) * R + r0 + tx] = __float2half(t[tx][ty + i]);
}

// QKV weights: [H=16 batches][1024][64] each; grid (2, 32, 48), z = m*16+batch
__global__ void __launch_bounds__(256) conv_qkv(const float* __restrict__ Wq,
                                                const float* __restrict__ Wk,
                                                const float* __restrict__ Wv)
{
    int m = blockIdx.z >> 4, batch = blockIdx.z & 15;
    const float* src = (m == 0) ? Wq : ((m == 1) ? Wk : Wv);
    __half* dst = (m == 0) ? g_wqT : ((m == 1) ? g_wkT : g_wvT);
    tr_tile(src + (size_t)batch * CDIM * HS, dst + (size_t)batch * CDIM * HS,
            CDIM, HS, blockIdx.x * 32, blockIdx.y * 32);
}

// Wproj [1024][1024]; grid (32, 32)
__global__ void __launch_bounds__(256) conv_wp(const float* __restrict__ Wp)
{
    tr_tile(Wp, g_wpT, CDIM, CDIM, blockIdx.x * 32, blockIdx.y * 32);
}

// Wff1 [1024][4096] + Wff2 [4096][1024]; grid (128, 32, 2) flat-decoded
__global__ void __launch_bounds__(256) conv_ff(const float* __restrict__ W1,
                                               const float* __restrict__ W2)
{
    int id = blockIdx.x * 32 + blockIdx.y;
    if (blockIdx.z == 0) {
        int c_t = id & 127, r_t = id >> 7;   // C=4096: 128 c-tiles, R=1024: 32 r-tiles
        tr_tile(W1, g_wf1T, CDIM, FDIM, c_t * 32, r_t * 32);
    } else {
        int c_t = id & 31, r_t = id >> 5;    // C=1024: 32 c-tiles, R=4096: 128 r-tiles
        tr_tile(W2, g_wf2T, FDIM, CDIM, c_t * 32, r_t * 32);
    }
}

// ----------------------------------------------------------------------------
// fp16 mma.sync GEMM, CTA tile 128x128, 8 warps (2 M x 4 N), warp = 64x32.
// m16n8k16, BK=64 halves, 3-stage cp.async, 110.6KB smem -> TWO CTAs per SM
// (smooths wave quantization; co-resident CTA hides pipeline latency).
// __launch_bounds__(256,2) caps regs at 128 (acc=64 + frags fits).
// ----------------------------------------------------------------------------
#define GPITCH 72
#define STG_HALVES ((128 + 128) * GPITCH)   // 18432 halves = 36864 B
#define MG_SMEM    (3 * STG_HALVES * 2)     // 110592 B; x2 CTA = 221184 <= SM cap

template <int MODE>
__global__ void __launch_bounds__(256, 2) mgemm(const float* __restrict__ bias,
                                                const float* __restrict__ resid,
                                                float* __restrict__ outp)
{
    constexpr int K = (MODE == 3) ? 4096 : 1024;
    constexpr int NKIT = K / 64;

    extern __shared__ __half smh[];
    const int tid = threadIdx.x, lane = tid & 31, wid = tid >> 5;
    const int wm = wid & 1, wn = wid >> 1;   // warp: rows wm*64, cols wn*32
    const int m0 = blockIdx.y * 128;
    const int n0 = blockIdx.x * 128;

    const __half* A;
    if      (MODE == 0) A = g_h1;
    else if (MODE == 1) A = g_attn;
    else if (MODE == 2) A = g_h2;
    else                A = g_ff1;

    const __half* B;
    if (MODE == 0) B = (blockIdx.z == 0) ? g_wqT : ((blockIdx.z == 1) ? g_wkT : g_wvT);
    else if (MODE == 1) B = g_wpT;
    else if (MODE == 2) B = g_wf1T;
    else                B = g_wf2T;

    float acc[4][4][4] = {};

    auto load_stage = [&](int j, int s) {
        __half* As = smh + s * STG_HALVES;
        __half* Bs = As + 128 * GPITCH;
        // A: 128 rows x 8 16B-chunks = 1024 chunks, 4/thread; B same
#pragma unroll
        for (int i = 0; i < 4; i++) {
            int c = tid + i * 256;
            int row = c >> 3, kc = c & 7;
            cp16(smem_u32(As + row * GPITCH + kc * 8),
                 A + (size_t)(m0 + row) * K + j * 64 + kc * 8);
        }
#pragma unroll
        for (int i = 0; i < 4; i++) {
            int c = tid + i * 256;
            int row = c >> 3, kc = c & 7;
            cp16(smem_u32(Bs + row * GPITCH + kc * 8),
                 B + (size_t)(n0 + row) * K + j * 64 + kc * 8);
        }
        cp_commit();
    };

    const int arow = (lane & 7) + ((lane >> 3) & 1) * 8;
    const int ahalf = (lane >> 4) & 1;
    uint32_t offA[4], offB[2];
#pragma unroll
    for (int mi = 0; mi < 4; mi++)
        offA[mi] = ((wm * 64 + mi * 16 + arow) * GPITCH + ahalf * 8) * 2;
#pragma unroll
    for (int g = 0; g < 2; g++)
        offB[g] = ((wn * 32 + g * 16 + arow) * GPITCH + ahalf * 8) * 2;

    load_stage(0, 0);
    load_stage(1, 1);

    for (int it = 0; it < NKIT; it++) {
        int s = it % 3;
        cp_wait1();
        __syncthreads();
        if (it + 2 < NKIT) load_stage(it + 2, (it + 2) % 3);
        else cp_commit();

        uint32_t AsU = smem_u32(smh + s * STG_HALVES);
        uint32_t BsU = AsU + 128 * GPITCH * 2;

#pragma unroll
        for (int ks = 0; ks < 4; ks++) {
            uint32_t af[4][4], bb[2][4];
#pragma unroll
            for (int mi = 0; mi < 4; mi++) ldsm_x4(af[mi], AsU + offA[mi] + ks * 32);
#pragma unroll
            for (int g = 0; g < 2; g++)  ldsm_x4(bb[g], BsU + offB[g] + ks * 32);
#pragma unroll
            for (int mi = 0; mi < 4; mi++)
#pragma unroll
                for (int g = 0; g < 2; g++) {
                    uint32_t blo[2] = {bb[g][0], bb[g][2]};
                    uint32_t bhi[2] = {bb[g][1], bb[g][3]};
                    mma16(acc[mi][g * 2],     af[mi], blo);
                    mma16(acc[mi][g * 2 + 1], af[mi], bhi);
                }
        }
    }

    // epilogue: d0:(r,c) d1:(r,c+1) d2:(r+8,c) d3:(r+8,c+1)
#pragma unroll
    for (int mi = 0; mi < 4; mi++) {
#pragma unroll
        for (int nj = 0; nj < 4; nj++) {
#pragma unroll
            for (int half = 0; half < 2; half++) {
                int gm = m0 + wm * 64 + mi * 16 + (lane >> 2) + half * 8;
                int gn = n0 + wn * 32 + nj * 8 + (lane & 3) * 2;
                float v0 = acc[mi][nj][half * 2 + 0];
                float v1 = acc[mi][nj][half * 2 + 1];
                if (MODE == 0) {
                    int bb2 = gm >> 11, t = gm & 2047;
                    int h = gn >> 6, d0 = gn & 63;
                    if (blockIdx.z == 2) {
                        __half* op = g_v + ((size_t)((bb2 * 16 + h) * 64 + d0)) * 2048 + t;
                        op[0]    = __float2half(v0);
                        op[2048] = __float2half(v1);
                    } else {
                        __half* sel = (blockIdx.z == 0) ? g_q : g_kk;
                        __half* op = sel + ((size_t)((bb2 * 16 + h) * 2048 + t)) * 64 + d0;
                        *(__half2*)op = __floats2half2_rn(v0, v1);
                    }
                } else if (MODE == 1) {
                    size_t o = (size_t)gm * 1024 + gn;
                    g_x1[o]     = v0 + bias[gn]     + resid[o];
                    g_x1[o + 1] = v1 + bias[gn + 1] + resid[o + 1];
                } else if (MODE == 2) {
                    size_t o = (size_t)gm * 4096 + gn;
                    *(__half2*)(g_ff1 + o) =
                        __floats2half2_rn(fmaxf(v0 + bias[gn], 0.f),
                                          fmaxf(v1 + bias[gn + 1], 0.f));
                } else {
                    size_t o = (size_t)gm * 1024 + gn;
                    outp[o]     = v0 + bias[gn]     + g_x1[o];
                    outp[o + 1] = v1 + bias[gn + 1] + g_x1[o + 1];
                }
            }
        }
    }
}

// ----------------------------------------------------------------------------
// fp16 tensor-core causal flash attention (unchanged from round 8).
// ----------------------------------------------------------------------------
#define QPITCH 72
#define KPITCH 72
#define VPITCH 40
#define PPITCH 40
#define AT_KOFF (128 * QPITCH)
#define AT_VOFF (AT_KOFF + 2 * 32 * KPITCH)
#define AT_POFF (AT_VOFF + 2 * 64 * VPITCH)
#define AT_SMEM ((AT_POFF + 4 * 32 * PPITCH) * 2)  // 48128 B

__global__ void __launch_bounds__(128) attn_k()
{
    extern __shared__ __half smA[];
    const int tid = threadIdx.x, lane = tid & 31, wid = tid >> 5;
    const int bh = blockIdx.y;
    const int rb = (int)gridDim.x - 1 - (int)blockIdx.x;  // heavy blocks first
    const int R0 = rb * 128;
    const size_t qkbase = (size_t)bh * TLEN * HS;
    const size_t vbase  = (size_t)bh * HS * TLEN;

    uint32_t QsU = smem_u32(smA);
    uint32_t KsU[2], VtU[2];
    KsU[0] = QsU + AT_KOFF * 2;  KsU[1] = KsU[0] + 32 * KPITCH * 2;
    VtU[0] = QsU + AT_VOFF * 2;  VtU[1] = VtU[0] + 64 * VPITCH * 2;
    uint32_t PsU = QsU + (AT_POFF + wid * 32 * PPITCH) * 2;

    {
        const __half* src = g_q + qkbase + (size_t)R0 * 64;
#pragma unroll
        for (int i = 0; i < 8; i++) {
            int c = tid + i * 128;
            int row = c >> 3, ch = c & 7;
            cp16(QsU + (row * QPITCH + ch * 8) * 2, src + row * 64 + ch * 8);
        }
    }
    auto load_tile = [&](int kt, int b) {
        const __half* ks = g_kk + qkbase + (size_t)kt * 32 * 64;
#pragma unroll
        for (int i = 0; i < 2; i++) {
            int c = tid + i * 128;
            int row = c >> 3, ch = c & 7;
            cp16(KsU[b] + (row * KPITCH + ch * 8) * 2, ks + row * 64 + ch * 8);
        }
        const __half* vs = g_v + vbase + kt * 32;
#pragma unroll
        for (int i = 0; i < 2; i++) {
            int c = tid + i * 128;
            int row = c >> 2, ch = c & 3;
            cp16(VtU[b] + (row * VPITCH + ch * 8) * 2, vs + (size_t)row * 2048 + ch * 8);
        }
    };

    const int NT = R0 / 32 + 4;
    const int maskstart = R0 / 32;

    load_tile(0, 0);
    cp_commit();

    const int arow = (lane & 7) + ((lane >> 3) & 1) * 8;
    const int ahalf = (lane >> 4) & 1;
    uint32_t offQ[2], offP[2], offK[2], offV[4];
#pragma unroll
    for (int mi = 0; mi < 2; mi++) {
        offQ[mi] = ((wid * 32 + mi * 16 + arow) * QPITCH + ahalf * 8) * 2;
        offP[mi] = ((mi * 16 + arow) * PPITCH + ahalf * 8) * 2;
    }
#pragma unroll
    for (int g = 0; g < 2; g++) offK[g] = ((g * 16 + arow) * KPITCH + ahalf * 8) * 2;
#pragma unroll
    for (int g = 0; g < 4; g++) offV[g] = ((g * 16 + arow) * VPITCH + ahalf * 8) * 2;

    uint32_t qf[2][4][4];
    float oacc[2][8][4] = {};
    float m_run[4] = {-1e30f, -1e30f, -1e30f, -1e30f};
    float l_run[4] = {};

    const int srow = lane >> 2;
    const int scol = (lane & 3) * 2;

    for (int it = 0; it < NT; it++) {
        __syncthreads();
        if (it + 1 < NT) load_tile(it + 1, (it + 1) & 1);
        cp_commit();
        cp_wait1();
        __syncthreads();

        if (it == 0) {
            const __half2 sc = __float2half2_rn(0.125f);
#pragma unroll
            for (int mi = 0; mi < 2; mi++)
#pragma unroll
                for (int kt = 0; kt < 4; kt++) {
                    ldsm_x4(qf[mi][kt], QsU + offQ[mi] + kt * 32);
#pragma unroll
                    for (int i = 0; i < 4; i++) {
                        __half2 h = *(__half2*)&qf[mi][kt][i];
                        h = __hmul2(h, sc);
                        qf[mi][kt][i] = *(uint32_t*)&h;
                    }
                }
        }

        const uint32_t Kb = KsU[it & 1], Vb = VtU[it & 1];

        float sacc[2][4][4] = {};
#pragma unroll
        for (int kt = 0; kt < 4; kt++) {
#pragma unroll
            for (int g = 0; g < 2; g++) {
                uint32_t kb[4];
                ldsm_x4(kb, Kb + offK[g] + kt * 32);
                uint32_t blo[2] = {kb[0], kb[2]}, bhi[2] = {kb[1], kb[3]};
#pragma unroll
                for (int mi = 0; mi < 2; mi++) {
                    mma16(sacc[mi][g * 2],     qf[mi][kt], blo);
                    mma16(sacc[mi][g * 2 + 1], qf[mi][kt], bhi);
                }
            }
        }

        if (it >= maskstart) {
            const int colbase = it * 32 + scol;
#pragma unroll
            for (int mi = 0; mi < 2; mi++) {
                const int rowb = R0 + wid * 32 + mi * 16 + srow;
#pragma unroll
                for (int nt = 0; nt < 4; nt++)
#pragma unroll
                    for (int j = 0; j < 4; j++) {
                        int col = colbase + nt * 8 + (j & 1);
                        int row = rowb + 8 * (j >> 1);
                        if (col > row) sacc[mi][nt][j] = -1e30f;
                    }
            }
        }

#pragma unroll
        for (int mi = 0; mi < 2; mi++) {
#pragma unroll
            for (int hf = 0; hf < 2; hf++) {
                const int slot = mi * 2 + hf;
                float vmax = m_run[slot];
#pragma unroll
                for (int nt = 0; nt < 4; nt++) {
                    vmax = fmaxf(vmax, sacc[mi][nt][hf * 2]);
                    vmax = fmaxf(vmax, sacc[mi][nt][hf * 2 + 1]);
                }
                vmax = fmaxf(vmax, __shfl_xor_sync(0xffffffffu, vmax, 1));
                vmax = fmaxf(vmax, __shfl_xor_sync(0xffffffffu, vmax, 2));
                const float mnew = vmax;
                const float scale = __expf(m_run[slot] - mnew);
                float lsum = 0.f;
                const int prow = mi * 16 + srow + 8 * hf;
#pragma unroll
                for (int nt = 0; nt < 4; nt++) {
                    float p0 = __expf(sacc[mi][nt][hf * 2]     - mnew);
                    float p1 = __expf(sacc[mi][nt][hf * 2 + 1] - mnew);
                    lsum += p0 + p1;
                    __half2 ph = __floats2half2_rn(p0, p1);
                    asm volatile("st.shared.u32 [%0], %1;"
                                 :: "r"(PsU + (prow * PPITCH + nt * 8 + scol) * 2),
                                    "r"(*(uint32_t*)&ph) : "memory");
                }
                lsum += __shfl_xor_sync(0xffffffffu, lsum, 1);
                lsum += __shfl_xor_sync(0xffffffffu, lsum, 2);
                l_run[slot] = l_run[slot] * scale + lsum;
                m_run[slot] = mnew;
#pragma unroll
                for (int nt = 0; nt < 8; nt++) {
                    oacc[mi][nt][hf * 2]     *= scale;
                    oacc[mi][nt][hf * 2 + 1] *= scale;
                }
            }
        }

#pragma unroll
        for (int kt = 0; kt < 2; kt++) {
            uint32_t pa[2][4];
#pragma unroll
            for (int mi = 0; mi < 2; mi++) ldsm_x4(pa[mi], PsU + offP[mi] + kt * 32);
#pragma unroll
            for (int g = 0; g < 4; g++) {
                uint32_t vb[4];
                ldsm_x4(vb, Vb + offV[g] + kt * 32);
                uint32_t blo[2] = {vb[0], vb[2]}, bhi[2] = {vb[1], vb[3]};
#pragma unroll
                for (int mi = 0; mi < 2; mi++) {
                    mma16(oacc[mi][g * 2],     pa[mi], blo);
                    mma16(oacc[mi][g * 2 + 1], pa[mi], bhi);
                }
            }
        }
    }

    const int b = bh >> 4, h = bh & 15;
#pragma unroll
    for (int mi = 0; mi < 2; mi++) {
#pragma unroll
        for (int hf = 0; hf < 2; hf++) {
            const float inv = 1.f / l_run[mi * 2 + hf];
            const int grow = R0 + wid * 32 + mi * 16 + srow + 8 * hf;
            __half* op = g_attn + ((size_t)(b * 2048 + grow)) * 1024 + h * 64 + scol;
#pragma unroll
            for (int nt = 0; nt < 8; nt++)
                *(__half2*)(op + nt * 8) =
                    __floats2half2_rn(oacc[mi][nt][hf * 2] * inv,
                                      oacc[mi][nt][hf * 2 + 1] * inv);
        }
    }
}

// ----------------------------------------------------------------------------
// Launch (attn_k at launch index 5 so ncu -s 5 -c 1 profiles it)
// ----------------------------------------------------------------------------
extern "C" void kernel_launch(void* const* d_in, const int* in_sizes, int n_in,
                              void* d_out, int out_size)
{
    const float* x     = (const float*)d_in[0];
    const float* Wq    = (const float*)d_in[1];
    const float* Wk    = (const float*)d_in[2];
    const float* Wv    = (const float*)d_in[3];
    const float* Wproj = (const float*)d_in[4];
    const float* bproj = (const float*)d_in[5];
    const float* g1    = (const float*)d_in[6];
    const float* b1    = (const float*)d_in[7];
    const float* g2    = (const float*)d_in[8];
    const float* b2    = (const float*)d_in[9];
    const float* Wff1  = (const float*)d_in[10];
    const float* bff1  = (const float*)d_in[11];
    const float* Wff2  = (const float*)d_in[12];
    const float* bff2  = (const float*)d_in[13];
    float* out = (float*)d_out;

    cudaFuncSetAttribute(mgemm<0>, cudaFuncAttributeMaxDynamicSharedMemorySize, MG_SMEM);
    cudaFuncSetAttribute(mgemm<1>, cudaFuncAttributeMaxDynamicSharedMemorySize, MG_SMEM);
    cudaFuncSetAttribute(mgemm<2>, cudaFuncAttributeMaxDynamicSharedMemorySize, MG_SMEM);
    cudaFuncSetAttribute(mgemm<3>, cudaFuncAttributeMaxDynamicSharedMemorySize, MG_SMEM);
    cudaFuncSetAttribute(attn_k,   cudaFuncAttributeMaxDynamicSharedMemorySize, AT_SMEM);

    // 0..2: weight converts (merged 6 -> 3 launches)
    conv_qkv<<<dim3(2, 32, 48), 256>>>(Wq, Wk, Wv);
    conv_wp <<<dim3(32, 32),    256>>>(Wproj);
    conv_ff <<<dim3(128, 32, 2),256>>>(Wff1, Wff2);
    // 3: LN1
    ln_k<<<MROWS, 256>>>(0, x, g1, b1);
    // 4: QKV
    mgemm<0><<<dim3(CDIM / 128, MROWS / 128, 3), 256, MG_SMEM>>>(nullptr, nullptr, nullptr);
    // 5: attention  <-- profiled by ncu (-s 5 -c 1)
    attn_k<<<dim3(TLEN / 128, NHEAD * 2), 128, AT_SMEM>>>();
    // 6: proj + bias + residual
    mgemm<1><<<dim3(CDIM / 128, MROWS / 128), 256, MG_SMEM>>>(bproj, x, nullptr);
    // 7: LN2
    ln_k<<<MROWS, 256>>>(1, nullptr, g2, b2);
    // 8: FFN1 + relu
    mgemm<2><<<dim3(FDIM / 128, MROWS / 128), 256, MG_SMEM>>>(bff1, nullptr, nullptr);
    // 9: FFN2 + bias + residual -> out
    mgemm<3><<<dim3(CDIM / 128, MROWS / 128), 256, MG_SMEM>>>(bff2, nullptr, out);
}

// round 11
// speedup vs baseline: 7.0353x; 1.0092x over previous
#include <cuda_runtime.h>
#include <cuda_fp16.h>
#include <cstdint>
#include <cstddef>

// ----------------------------------------------------------------------------
// B=2, T=2048, C=1024, H=16, hs=64 ; M = B*T = 4096
// ----------------------------------------------------------------------------
#define MROWS 4096
#define CDIM  1024
#define FDIM  4096
#define TLEN  2048
#define NHEAD 16
#define HS    64

__device__ __half g_h1[MROWS * CDIM];          // fp16 operands
__device__ __half g_q [MROWS * CDIM];          // [B,H,T,hs]
__device__ __half g_kk[MROWS * CDIM];          // [B,H,T,hs]
__device__ __half g_v [MROWS * CDIM];          // [B,H,T,hs] (row-major now)
__device__ __half g_attn[MROWS * CDIM];        // row-major
__device__ float  g_x1[MROWS * CDIM];          // fp32 residual path
__device__ __half g_h2[MROWS * CDIM];
__device__ __half g_ff1[(size_t)MROWS * FDIM];
__device__ __half g_wqT[CDIM * CDIM];          // Bt[n][k]
__device__ __half g_wkT[CDIM * CDIM];
__device__ __half g_wvT[CDIM * CDIM];
__device__ __half g_wpT[CDIM * CDIM];
__device__ __half g_wf1T[(size_t)CDIM * FDIM];
__device__ __half g_wf2T[(size_t)CDIM * FDIM];

// ----------------------------------------------------------------------------
// Helpers (baseline sm_80+; NO tcgen05)
// ----------------------------------------------------------------------------
__device__ __forceinline__ uint32_t smem_u32(const void* p) {
    return (uint32_t)__cvta_generic_to_shared(p);
}
__device__ __forceinline__ void cp16(uint32_t dst, const void* src) {
    asm volatile("cp.async.cg.shared.global [%0], [%1], 16;\n" :: "r"(dst), "l"(src));
}
__device__ __forceinline__ void cp_commit() {
    asm volatile("cp.async.commit_group;\n" ::: "memory");
}
__device__ __forceinline__ void cp_wait1() {
    asm volatile("cp.async.wait_group 1;\n" ::: "memory");
}
__device__ __forceinline__ void mma16(float* d, const uint32_t* a, const uint32_t* b) {
    asm volatile(
        "mma.sync.aligned.m16n8k16.row.col.f32.f16.f16.f32 "
        "{%0,%1,%2,%3},{%4,%5,%6,%7},{%8,%9},{%0,%1,%2,%3};"
        : "+f"(d[0]), "+f"(d[1]), "+f"(d[2]), "+f"(d[3])
        : "r"(a[0]), "r"(a[1]), "r"(a[2]), "r"(a[3]), "r"(b[0]), "r"(b[1]));
}
__device__ __forceinline__ void ldsm_x4(uint32_t* r, uint32_t addr) {
    asm volatile("ldmatrix.sync.aligned.m8n8.x4.shared.b16 {%0,%1,%2,%3}, [%4];"
                 : "=r"(r[0]), "=r"(r[1]), "=r"(r[2]), "=r"(r[3]) : "r"(addr));
}
__device__ __forceinline__ void ldsm_x4t(uint32_t* r, uint32_t addr) {
    asm volatile("ldmatrix.sync.aligned.m8n8.x4.trans.shared.b16 {%0,%1,%2,%3}, [%4];"
                 : "=r"(r[0]), "=r"(r[1]), "=r"(r[2]), "=r"(r[3]) : "r"(addr));
}

// ----------------------------------------------------------------------------
// LayerNorm: warp-per-row (8 rows/block), no smem / no block sync.
// ----------------------------------------------------------------------------
__global__ void __launch_bounds__(256) ln_k(int mode, const float* __restrict__ x_ext,
                                            const float* __restrict__ g,
                                            const float* __restrict__ b)
{
    const float* in = (mode == 0) ? x_ext : g_x1;
    __half* out     = (mode == 0) ? g_h1  : g_h2;
    const int lane = threadIdx.x & 31;
    const int row = blockIdx.x * 8 + (threadIdx.x >> 5);
    const size_t base = (size_t)row * CDIM;

    float4 v[8];
    float s = 0.f, s2 = 0.f;
#pragma unroll
    for (int i = 0; i < 8; i++) {
        v[i] = *(const float4*)(in + base + lane * 4 + i * 128);
        s  += v[i].x + v[i].y + v[i].z + v[i].w;
        s2 += v[i].x * v[i].x + v[i].y * v[i].y + v[i].z * v[i].z + v[i].w * v[i].w;
    }
#pragma unroll
    for (int off = 16; off; off >>= 1) {
        s  += __shfl_xor_sync(0xffffffffu, s,  off);
        s2 += __shfl_xor_sync(0xffffffffu, s2, off);
    }
    const float mu = s * (1.f / CDIM);
    const float rstd = rsqrtf(s2 * (1.f / CDIM) - mu * mu + 1e-5f);
#pragma unroll
    for (int i = 0; i < 8; i++) {
        int c = lane * 4 + i * 128;
        float4 gg = *(const float4*)(g + c);
        float4 bb = *(const float4*)(b + c);
        *(__half2*)(out + base + c) =
            __floats2half2_rn((v[i].x - mu) * rstd * gg.x + bb.x,
                              (v[i].y - mu) * rstd * gg.y + bb.y);
        *(__half2*)(out + base + c + 2) =
            __floats2half2_rn((v[i].z - mu) * rstd * gg.z + bb.z,
                              (v[i].w - mu) * rstd * gg.w + bb.w);
    }
}

// ----------------------------------------------------------------------------
// Weight convert+transpose (fp32 [r][c] -> fp16 [c][r]), 32x32 tiles.
// ----------------------------------------------------------------------------
__device__ __forceinline__ void tr_tile(const float* __restrict__ ip,
                                        __half* __restrict__ op,
                                        int R, int Cc, int c0, int r0)
{
    __shared__ float t[32][33];
    int tx = threadIdx.x & 31, ty = threadIdx.x >> 5;
#pragma unroll
    for (int i = 0; i < 32; i += 8)
        t[ty + i][tx] = ip[(size_t)(r0 + ty + i) * Cc + c0 + tx];
    __syncthreads();
#pragma unroll
    for (int i = 0; i < 32; i += 8)
        op[(size_t)(c0 + ty + i) * R + r0 + tx] = __float2half(t[tx][ty + i]);
}

__global__ void __launch_bounds__(256) conv_qkv(const float* __restrict__ Wq,
                                                const float* __restrict__ Wk,
                                                const float* __restrict__ Wv)
{
    int m = blockIdx.z >> 4, batch = blockIdx.z & 15;
    const float* src = (m == 0) ? Wq : ((m == 1) ? Wk : Wv);
    __half* dst = (m == 0) ? g_wqT : ((m == 1) ? g_wkT : g_wvT);
    tr_tile(src + (size_t)batch * CDIM * HS, dst + (size_t)batch * CDIM * HS,
            CDIM, HS, blockIdx.x * 32, blockIdx.y * 32);
}

__global__ void __launch_bounds__(256) conv_wp(const float* __restrict__ Wp)
{
    tr_tile(Wp, g_wpT, CDIM, CDIM, blockIdx.x * 32, blockIdx.y * 32);
}

__global__ void __launch_bounds__(256) conv_ff(const float* __restrict__ W1,
                                               const float* __restrict__ W2)
{
    int id = blockIdx.x * 32 + blockIdx.y;
    if (blockIdx.z == 0) {
        int c_t = id & 127, r_t = id >> 7;
        tr_tile(W1, g_wf1T, CDIM, FDIM, c_t * 32, r_t * 32);
    } else {
        int c_t = id & 31, r_t = id >> 5;
        tr_tile(W2, g_wf2T, FDIM, CDIM, c_t * 32, r_t * 32);
    }
}

// ----------------------------------------------------------------------------
// fp16 mma.sync GEMM, CTA tile 128x128, 8 warps (2 M x 4 N), warp = 64x32.
// m16n8k16, BK=64, 3-stage cp.async, 110.6KB smem -> 2 CTAs/SM.
// MODE 0 epilogue: all of q/k/v written row-major [B,H,T,hs] (coalesced half2).
// ----------------------------------------------------------------------------
#define GPITCH 72
#define STG_HALVES ((128 + 128) * GPITCH)
#define MG_SMEM    (3 * STG_HALVES * 2)     // 110592 B

template <int MODE>
__global__ void __launch_bounds__(256, 2) mgemm(const float* __restrict__ bias,
                                                const float* __restrict__ resid,
                                                float* __restrict__ outp)
{
    constexpr int K = (MODE == 3) ? 4096 : 1024;
    constexpr int NKIT = K / 64;

    extern __shared__ __half smh[];
    const int tid = threadIdx.x, lane = tid & 31, wid = tid >> 5;
    const int wm = wid & 1, wn = wid >> 1;
    const int m0 = blockIdx.y * 128;
    const int n0 = blockIdx.x * 128;

    const __half* A;
    if      (MODE == 0) A = g_h1;
    else if (MODE == 1) A = g_attn;
    else if (MODE == 2) A = g_h2;
    else                A = g_ff1;

    const __half* B;
    if (MODE == 0) B = (blockIdx.z == 0) ? g_wqT : ((blockIdx.z == 1) ? g_wkT : g_wvT);
    else if (MODE == 1) B = g_wpT;
    else if (MODE == 2) B = g_wf1T;
    else                B = g_wf2T;

    float acc[4][4][4] = {};

    auto load_stage = [&](int j, int s) {
        __half* As = smh + s * STG_HALVES;
        __half* Bs = As + 128 * GPITCH;
#pragma unroll
        for (int i = 0; i < 4; i++) {
            int c = tid + i * 256;
            int row = c >> 3, kc = c & 7;
            cp16(smem_u32(As + row * GPITCH + kc * 8),
                 A + (size_t)(m0 + row) * K + j * 64 + kc * 8);
        }
#pragma unroll
        for (int i = 0; i < 4; i++) {
            int c = tid + i * 256;
            int row = c >> 3, kc = c & 7;
            cp16(smem_u32(Bs + row * GPITCH + kc * 8),
                 B + (size_t)(n0 + row) * K + j * 64 + kc * 8);
        }
        cp_commit();
    };

    const int arow = (lane & 7) + ((lane >> 3) & 1) * 8;
    const int ahalf = (lane >> 4) & 1;
    uint32_t offA[4], offB[2];
#pragma unroll
    for (int mi = 0; mi < 4; mi++)
        offA[mi] = ((wm * 64 + mi * 16 + arow) * GPITCH + ahalf * 8) * 2;
#pragma unroll
    for (int g = 0; g < 2; g++)
        offB[g] = ((wn * 32 + g * 16 + arow) * GPITCH + ahalf * 8) * 2;

    load_stage(0, 0);
    load_stage(1, 1);

    for (int it = 0; it < NKIT; it++) {
        int s = it % 3;
        cp_wait1();
        __syncthreads();
        if (it + 2 < NKIT) load_stage(it + 2, (it + 2) % 3);
        else cp_commit();

        uint32_t AsU = smem_u32(smh + s * STG_HALVES);
        uint32_t BsU = AsU + 128 * GPITCH * 2;

#pragma unroll
        for (int ks = 0; ks < 4; ks++) {
            uint32_t af[4][4], bb[2][4];
#pragma unroll
            for (int mi = 0; mi < 4; mi++) ldsm_x4(af[mi], AsU + offA[mi] + ks * 32);
#pragma unroll
            for (int g = 0; g < 2; g++)  ldsm_x4(bb[g], BsU + offB[g] + ks * 32);
#pragma unroll
            for (int mi = 0; mi < 4; mi++)
#pragma unroll
                for (int g = 0; g < 2; g++) {
                    uint32_t blo[2] = {bb[g][0], bb[g][2]};
                    uint32_t bhi[2] = {bb[g][1], bb[g][3]};
                    mma16(acc[mi][g * 2],     af[mi], blo);
                    mma16(acc[mi][g * 2 + 1], af[mi], bhi);
                }
        }
    }

#pragma unroll
    for (int mi = 0; mi < 4; mi++) {
#pragma unroll
        for (int nj = 0; nj < 4; nj++) {
#pragma unroll
            for (int half = 0; half < 2; half++) {
                int gm = m0 + wm * 64 + mi * 16 + (lane >> 2) + half * 8;
                int gn = n0 + wn * 32 + nj * 8 + (lane & 3) * 2;
                float v0 = acc[mi][nj][half * 2 + 0];
                float v1 = acc[mi][nj][half * 2 + 1];
                if (MODE == 0) {
                    int bb2 = gm >> 11, t = gm & 2047;
                    int h = gn >> 6, d0 = gn & 63;
                    __half* sel = (blockIdx.z == 0) ? g_q : ((blockIdx.z == 1) ? g_kk : g_v);
                    __half* op = sel + ((size_t)((bb2 * 16 + h) * 2048 + t)) * 64 + d0;
                    *(__half2*)op = __floats2half2_rn(v0, v1);
                } else if (MODE == 1) {
                    size_t o = (size_t)gm * 1024 + gn;
                    g_x1[o]     = v0 + bias[gn]     + resid[o];
                    g_x1[o + 1] = v1 + bias[gn + 1] + resid[o + 1];
                } else if (MODE == 2) {
                    size_t o = (size_t)gm * 4096 + gn;
                    *(__half2*)(g_ff1 + o) =
                        __floats2half2_rn(fmaxf(v0 + bias[gn], 0.f),
                                          fmaxf(v1 + bias[gn + 1], 0.f));
                } else {
                    size_t o = (size_t)gm * 1024 + gn;
                    outp[o]     = v0 + bias[gn]     + g_x1[o];
                    outp[o + 1] = v1 + bias[gn + 1] + g_x1[o + 1];
                }
            }
        }
    }
}

// ----------------------------------------------------------------------------
// fp16 tensor-core causal flash attention.
// V now row-major [B,H,T,hs]; PV B-fragments via ldmatrix.x4.trans.
// ----------------------------------------------------------------------------
#define QPITCH 72
#define KPITCH 72
#define VPITCH 72
#define PPITCH 40
#define AT_KOFF (128 * QPITCH)
#define AT_VOFF (AT_KOFF + 2 * 32 * KPITCH)
#define AT_POFF (AT_VOFF + 2 * 32 * VPITCH)
#define AT_SMEM ((AT_POFF + 4 * 32 * PPITCH) * 2)  // 47104 B

__global__ void __launch_bounds__(128) attn_k()
{
    extern __shared__ __half smA[];
    const int tid = threadIdx.x, lane = tid & 31, wid = tid >> 5;
    const int bh = blockIdx.y;
    const int rb = (int)gridDim.x - 1 - (int)blockIdx.x;  // heavy blocks first
    const int R0 = rb * 128;
    const size_t qkbase = (size_t)bh * TLEN * HS;

    uint32_t QsU = smem_u32(smA);
    uint32_t KsU[2], VtU[2];
    KsU[0] = QsU + AT_KOFF * 2;  KsU[1] = KsU[0] + 32 * KPITCH * 2;
    VtU[0] = QsU + AT_VOFF * 2;  VtU[1] = VtU[0] + 32 * VPITCH * 2;
    uint32_t PsU = QsU + (AT_POFF + wid * 32 * PPITCH) * 2;

    {
        const __half* src = g_q + qkbase + (size_t)R0 * 64;
#pragma unroll
        for (int i = 0; i < 8; i++) {
            int c = tid + i * 128;
            int row = c >> 3, ch = c & 7;
            cp16(QsU + (row * QPITCH + ch * 8) * 2, src + row * 64 + ch * 8);
        }
    }
    auto load_tile = [&](int kt, int b) {
        const __half* ks = g_kk + qkbase + (size_t)kt * 32 * 64;
        const __half* vs = g_v  + qkbase + (size_t)kt * 32 * 64;
#pragma unroll
        for (int i = 0; i < 2; i++) {
            int c = tid + i * 128;
            int row = c >> 3, ch = c & 7;
            cp16(KsU[b] + (row * KPITCH + ch * 8) * 2, ks + row * 64 + ch * 8);
            cp16(VtU[b] + (row * VPITCH + ch * 8) * 2, vs + row * 64 + ch * 8);
        }
    };

    const int NT = R0 / 32 + 4;
    const int maskstart = R0 / 32;

    load_tile(0, 0);
    cp_commit();

    const int arow = (lane & 7) + ((lane >> 3) & 1) * 8;
    const int ahalf = (lane >> 4) & 1;
    uint32_t offQ[2], offP[2], offK[2], offV[4];
#pragma unroll
    for (int mi = 0; mi < 2; mi++) {
        offQ[mi] = ((wid * 32 + mi * 16 + arow) * QPITCH + ahalf * 8) * 2;
        offP[mi] = ((mi * 16 + arow) * PPITCH + ahalf * 8) * 2;
    }
#pragma unroll
    for (int g = 0; g < 2; g++) offK[g] = ((g * 16 + arow) * KPITCH + ahalf * 8) * 2;
    // trans V: group0=(k0-7,n0-7) g1=(k0-7,n8-15) g2=(k8-15,n0-7) g3=(k8-15,n8-15)
    const int vk = (lane & 7) + ((lane >> 4) & 1) * 8;
    const int vn = ((lane >> 3) & 1) * 8;
#pragma unroll
    for (int g = 0; g < 4; g++) offV[g] = (vk * VPITCH + g * 16 + vn) * 2;

    uint32_t qf[2][4][4];
    float oacc[2][8][4] = {};
    float m_run[4] = {-1e30f, -1e30f, -1e30f, -1e30f};
    float l_run[4] = {};

    const int srow = lane >> 2;
    const int scol = (lane & 3) * 2;

    for (int it = 0; it < NT; it++) {
        __syncthreads();
        if (it + 1 < NT) load_tile(it + 1, (it + 1) & 1);
        cp_commit();
        cp_wait1();
        __syncthreads();

        if (it == 0) {
            const __half2 sc = __float2half2_rn(0.125f);
#pragma unroll
            for (int mi = 0; mi < 2; mi++)
#pragma unroll
                for (int kt = 0; kt < 4; kt++) {
                    ldsm_x4(qf[mi][kt], QsU + offQ[mi] + kt * 32);
#pragma unroll
                    for (int i = 0; i < 4; i++) {
                        __half2 h = *(__half2*)&qf[mi][kt][i];
                        h = __hmul2(h, sc);
                        qf[mi][kt][i] = *(uint32_t*)&h;
                    }
                }
        }

        const uint32_t Kb = KsU[it & 1], Vb = VtU[it & 1];

        float sacc[2][4][4] = {};
#pragma unroll
        for (int kt = 0; kt < 4; kt++) {
#pragma unroll
            for (int g = 0; g < 2; g++) {
                uint32_t kb[4];
                ldsm_x4(kb, Kb + offK[g] + kt * 32);
                uint32_t blo[2] = {kb[0], kb[2]}, bhi[2] = {kb[1], kb[3]};
#pragma unroll
                for (int mi = 0; mi < 2; mi++) {
                    mma16(sacc[mi][g * 2],     qf[mi][kt], blo);
                    mma16(sacc[mi][g * 2 + 1], qf[mi][kt], bhi);
                }
            }
        }

        if (it >= maskstart) {
            const int colbase = it * 32 + scol;
#pragma unroll
            for (int mi = 0; mi < 2; mi++) {
                const int rowb = R0 + wid * 32 + mi * 16 + srow;
#pragma unroll
                for (int nt = 0; nt < 4; nt++)
#pragma unroll
                    for (int j = 0; j < 4; j++) {
                        int col = colbase + nt * 8 + (j & 1);
                        int row = rowb + 8 * (j >> 1);
                        if (col > row) sacc[mi][nt][j] = -1e30f;
                    }
            }
        }

#pragma unroll
        for (int mi = 0; mi < 2; mi++) {
#pragma unroll
            for (int hf = 0; hf < 2; hf++) {
                const int slot = mi * 2 + hf;
                float vmax = m_run[slot];
#pragma unroll
                for (int nt = 0; nt < 4; nt++) {
                    vmax = fmaxf(vmax, sacc[mi][nt][hf * 2]);
                    vmax = fmaxf(vmax, sacc[mi][nt][hf * 2 + 1]);
                }
                vmax = fmaxf(vmax, __shfl_xor_sync(0xffffffffu, vmax, 1));
                vmax = fmaxf(vmax, __shfl_xor_sync(0xffffffffu, vmax, 2));
                const float mnew = vmax;
                const float scale = __expf(m_run[slot] - mnew);
                float lsum = 0.f;
                const int prow = mi * 16 + srow + 8 * hf;
#pragma unroll
                for (int nt = 0; nt < 4; nt++) {
                    float p0 = __expf(sacc[mi][nt][hf * 2]     - mnew);
                    float p1 = __expf(sacc[mi][nt][hf * 2 + 1] - mnew);
                    lsum += p0 + p1;
                    __half2 ph = __floats2half2_rn(p0, p1);
                    asm volatile("st.shared.u32 [%0], %1;"
                                 :: "r"(PsU + (prow * PPITCH + nt * 8 + scol) * 2),
                                    "r"(*(uint32_t*)&ph) : "memory");
                }
                lsum += __shfl_xor_sync(0xffffffffu, lsum, 1);
                lsum += __shfl_xor_sync(0xffffffffu, lsum, 2);
                l_run[slot] = l_run[slot] * scale + lsum;
                m_run[slot] = mnew;
#pragma unroll
                for (int nt = 0; nt < 8; nt++) {
                    oacc[mi][nt][hf * 2]     *= scale;
                    oacc[mi][nt][hf * 2 + 1] *= scale;
                }
            }
        }

        // ---- O += P V (V row-major, trans loads) ----
#pragma unroll
        for (int kt = 0; kt < 2; kt++) {
            uint32_t pa[2][4];
#pragma unroll
            for (int mi = 0; mi < 2; mi++) ldsm_x4(pa[mi], PsU + offP[mi] + kt * 32);
#pragma unroll
            for (int g = 0; g < 4; g++) {
                uint32_t vb[4];
                ldsm_x4t(vb, Vb + offV[g] + kt * 16 * VPITCH * 2);
                uint32_t blo[2] = {vb[0], vb[2]}, bhi[2] = {vb[1], vb[3]};
#pragma unroll
                for (int mi = 0; mi < 2; mi++) {
                    mma16(oacc[mi][g * 2],     pa[mi], blo);
                    mma16(oacc[mi][g * 2 + 1], pa[mi], bhi);
                }
            }
        }
    }

    const int b = bh >> 4, h = bh & 15;
#pragma unroll
    for (int mi = 0; mi < 2; mi++) {
#pragma unroll
        for (int hf = 0; hf < 2; hf++) {
            const float inv = 1.f / l_run[mi * 2 + hf];
            const int grow = R0 + wid * 32 + mi * 16 + srow + 8 * hf;
            __half* op = g_attn + ((size_t)(b * 2048 + grow)) * 1024 + h * 64 + scol;
#pragma unroll
            for (int nt = 0; nt < 8; nt++)
                *(__half2*)(op + nt * 8) =
                    __floats2half2_rn(oacc[mi][nt][hf * 2] * inv,
                                      oacc[mi][nt][hf * 2 + 1] * inv);
        }
    }
}

// ----------------------------------------------------------------------------
// Launch: background stream carries proj/FFN weight converts (fork/join via
// events -> capture-legal), overlapping QKV + attention.
// ----------------------------------------------------------------------------
extern "C" void kernel_launch(void* const* d_in, const int* in_sizes, int n_in,
                              void* d_out, int out_size)
{
    const float* x     = (const float*)d_in[0];
    const float* Wq    = (const float*)d_in[1];
    const float* Wk    = (const float*)d_in[2];
    const float* Wv    = (const float*)d_in[3];
    const float* Wproj = (const float*)d_in[4];
    const float* bproj = (const float*)d_in[5];
    const float* g1    = (const float*)d_in[6];
    const float* b1    = (const float*)d_in[7];
    const float* g2    = (const float*)d_in[8];
    const float* b2    = (const float*)d_in[9];
    const float* Wff1  = (const float*)d_in[10];
    const float* bff1  = (const float*)d_in[11];
    const float* Wff2  = (const float*)d_in[12];
    const float* bff2  = (const float*)d_in[13];
    float* out = (float*)d_out;

    static cudaStream_t sbg = nullptr;
    static cudaEvent_t  efork = nullptr, ejoin = nullptr;
    if (sbg == nullptr) {
        cudaStreamCreateWithFlags(&sbg, cudaStreamNonBlocking);
        cudaEventCreateWithFlags(&efork, cudaEventDisableTiming);
        cudaEventCreateWithFlags(&ejoin, cudaEventDisableTiming);
        cudaFuncSetAttribute(mgemm<0>, cudaFuncAttributeMaxDynamicSharedMemorySize, MG_SMEM);
        cudaFuncSetAttribute(mgemm<1>, cudaFuncAttributeMaxDynamicSharedMemorySize, MG_SMEM);
        cudaFuncSetAttribute(mgemm<2>, cudaFuncAttributeMaxDynamicSharedMemorySize, MG_SMEM);
        cudaFuncSetAttribute(mgemm<3>, cudaFuncAttributeMaxDynamicSharedMemorySize, MG_SMEM);
        cudaFuncSetAttribute(attn_k,   cudaFuncAttributeMaxDynamicSharedMemorySize, AT_SMEM);
    }

    // fork background converts (needed only at proj / FFN)
    cudaEventRecord(efork, 0);
    cudaStreamWaitEvent(sbg, efork, 0);
    conv_wp <<<dim3(32, 32),     256, 0, sbg>>>(Wproj);
    conv_ff <<<dim3(128, 32, 2), 256, 0, sbg>>>(Wff1, Wff2);
    cudaEventRecord(ejoin, sbg);

    // main chain
    conv_qkv<<<dim3(2, 32, 48), 256>>>(Wq, Wk, Wv);
    ln_k<<<MROWS / 8, 256>>>(0, x, g1, b1);
    mgemm<0><<<dim3(CDIM / 128, MROWS / 128, 3), 256, MG_SMEM>>>(nullptr, nullptr, nullptr);
    attn_k<<<dim3(TLEN / 128, NHEAD * 2), 128, AT_SMEM>>>();

    cudaStreamWaitEvent(0, ejoin, 0);   // join: proj needs g_wpT
    mgemm<1><<<dim3(CDIM / 128, MROWS / 128), 256, MG_SMEM>>>(bproj, x, nullptr);
    ln_k<<<MROWS / 8, 256>>>(1, nullptr, g2, b2);
    mgemm<2><<<dim3(FDIM / 128, MROWS / 128), 256, MG_SMEM>>>(bff1, nullptr, nullptr);
    mgemm<3><<<dim3(CDIM / 128, MROWS / 128), 256, MG_SMEM>>>(bff2, nullptr, out);
}

// round 13
// speedup vs baseline: 7.0431x; 1.0011x over previous
#include <cuda_runtime.h>
#include <cuda_fp16.h>
#include <cstdint>
#include <cstddef>

// ----------------------------------------------------------------------------
// B=2, T=2048, C=1024, H=16, hs=64 ; M = B*T = 4096
// ----------------------------------------------------------------------------
#define MROWS 4096
#define CDIM  1024
#define FDIM  4096
#define TLEN  2048
#define NHEAD 16
#define HS    64

__device__ __half g_h1[MROWS * CDIM];          // fp16 operands
__device__ __half g_q [MROWS * CDIM];          // [B,H,T,hs]
__device__ __half g_kk[MROWS * CDIM];          // [B,H,T,hs]
__device__ __half g_v [MROWS * CDIM];          // [B,H,T,hs] (row-major)
__device__ __half g_attn[MROWS * CDIM];        // row-major
__device__ float  g_x1[MROWS * CDIM];          // fp32 residual path
__device__ __half g_h2[MROWS * CDIM];
__device__ __half g_ff1[(size_t)MROWS * FDIM];
__device__ __half g_wqT[CDIM * CDIM];          // Bt[n][k]
__device__ __half g_wkT[CDIM * CDIM];
__device__ __half g_wvT[CDIM * CDIM];
__device__ __half g_wpT[CDIM * CDIM];
__device__ __half g_wf1T[(size_t)CDIM * FDIM];
__device__ __half g_wf2T[(size_t)CDIM * FDIM];

// ----------------------------------------------------------------------------
// Helpers (baseline sm_80+; NO tcgen05)
// ----------------------------------------------------------------------------
__device__ __forceinline__ uint32_t smem_u32(const void* p) {
    return (uint32_t)__cvta_generic_to_shared(p);
}
__device__ __forceinline__ void cp16(uint32_t dst, const void* src) {
    asm volatile("cp.async.cg.shared.global [%0], [%1], 16;\n" :: "r"(dst), "l"(src));
}
__device__ __forceinline__ void cp_commit() {
    asm volatile("cp.async.commit_group;\n" ::: "memory");
}
__device__ __forceinline__ void cp_wait1() {
    asm volatile("cp.async.wait_group 1;\n" ::: "memory");
}
__device__ __forceinline__ void mma16(float* d, const uint32_t* a, const uint32_t* b) {
    asm volatile(
        "mma.sync.aligned.m16n8k16.row.col.f32.f16.f16.f32 "
        "{%0,%1,%2,%3},{%4,%5,%6,%7},{%8,%9},{%0,%1,%2,%3};"
        : "+f"(d[0]), "+f"(d[1]), "+f"(d[2]), "+f"(d[3])
        : "r"(a[0]), "r"(a[1]), "r"(a[2]), "r"(a[3]), "r"(b[0]), "r"(b[1]));
}
__device__ __forceinline__ void ldsm_x4(uint32_t* r, uint32_t addr) {
    asm volatile("ldmatrix.sync.aligned.m8n8.x4.shared.b16 {%0,%1,%2,%3}, [%4];"
                 : "=r"(r[0]), "=r"(r[1]), "=r"(r[2]), "=r"(r[3]) : "r"(addr));
}
__device__ __forceinline__ void ldsm_x4t(uint32_t* r, uint32_t addr) {
    asm volatile("ldmatrix.sync.aligned.m8n8.x4.trans.shared.b16 {%0,%1,%2,%3}, [%4];"
                 : "=r"(r[0]), "=r"(r[1]), "=r"(r[2]), "=r"(r[3]) : "r"(addr));
}

// ----------------------------------------------------------------------------
// LayerNorm: warp-per-row (8 rows/block)
// ----------------------------------------------------------------------------
__global__ void __launch_bounds__(256) ln_k(int mode, const float* __restrict__ x_ext,
                                            const float* __restrict__ g,
                                            const float* __restrict__ b)
{
    const float* in = (mode == 0) ? x_ext : g_x1;
    __half* out     = (mode == 0) ? g_h1  : g_h2;
    const int lane = threadIdx.x & 31;
    const int row = blockIdx.x * 8 + (threadIdx.x >> 5);
    const size_t base = (size_t)row * CDIM;

    float4 v[8];
    float s = 0.f, s2 = 0.f;
#pragma unroll
    for (int i = 0; i < 8; i++) {
        v[i] = *(const float4*)(in + base + lane * 4 + i * 128);
        s  += v[i].x + v[i].y + v[i].z + v[i].w;
        s2 += v[i].x * v[i].x + v[i].y * v[i].y + v[i].z * v[i].z + v[i].w * v[i].w;
    }
#pragma unroll
    for (int off = 16; off; off >>= 1) {
        s  += __shfl_xor_sync(0xffffffffu, s,  off);
        s2 += __shfl_xor_sync(0xffffffffu, s2, off);
    }
    const float mu = s * (1.f / CDIM);
    const float rstd = rsqrtf(s2 * (1.f / CDIM) - mu * mu + 1e-5f);
#pragma unroll
    for (int i = 0; i < 8; i++) {
        int c = lane * 4 + i * 128;
        float4 gg = *(const float4*)(g + c);
        float4 bb = *(const float4*)(b + c);
        *(__half2*)(out + base + c) =
            __floats2half2_rn((v[i].x - mu) * rstd * gg.x + bb.x,
                              (v[i].y - mu) * rstd * gg.y + bb.y);
        *(__half2*)(out + base + c + 2) =
            __floats2half2_rn((v[i].z - mu) * rstd * gg.z + bb.z,
                              (v[i].w - mu) * rstd * gg.w + bb.w);
    }
}

// ----------------------------------------------------------------------------
// Weight convert+transpose (fp32 [r][c] -> fp16 [c][r]), 32x32 tiles.
// ----------------------------------------------------------------------------
__device__ __forceinline__ void tr_tile(const float* __restrict__ ip,
                                        __half* __restrict__ op,
                                        int R, int Cc, int c0, int r0)
{
    __shared__ float t[32][33];
    int tx = threadIdx.x & 31, ty = threadIdx.x >> 5;
#pragma unroll
    for (int i = 0; i < 32; i += 8)
        t[ty + i][tx] = ip[(size_t)(r0 + ty + i) * Cc + c0 + tx];
    __syncthreads();
#pragma unroll
    for (int i = 0; i < 32; i += 8)
        op[(size_t)(c0 + ty + i) * R + r0 + tx] = __float2half(t[tx][ty + i]);
}

__global__ void __launch_bounds__(256) conv_qkv(const float* __restrict__ Wq,
                                                const float* __restrict__ Wk,
                                                const float* __restrict__ Wv)
{
    int m = blockIdx.z >> 4, batch = blockIdx.z & 15;
    const float* src = (m == 0) ? Wq : ((m == 1) ? Wk : Wv);
    __half* dst = (m == 0) ? g_wqT : ((m == 1) ? g_wkT : g_wvT);
    tr_tile(src + (size_t)batch * CDIM * HS, dst + (size_t)batch * CDIM * HS,
            CDIM, HS, blockIdx.x * 32, blockIdx.y * 32);
}

__global__ void __launch_bounds__(256) conv_wp(const float* __restrict__ Wp)
{
    tr_tile(Wp, g_wpT, CDIM, CDIM, blockIdx.x * 32, blockIdx.y * 32);
}

__global__ void __launch_bounds__(256) conv_ff(const float* __restrict__ W1,
                                               const float* __restrict__ W2)
{
    int id = blockIdx.x * 32 + blockIdx.y;
    if (blockIdx.z == 0) {
        int c_t = id & 127, r_t = id >> 7;
        tr_tile(W1, g_wf1T, CDIM, FDIM, c_t * 32, r_t * 32);
    } else {
        int c_t = id & 31, r_t = id >> 5;
        tr_tile(W2, g_wf2T, FDIM, CDIM, c_t * 32, r_t * 32);
    }
}

// ----------------------------------------------------------------------------
// fp16 mma.sync GEMM, CTA tile 128x128, 8 warps (2 M x 4 N), warp = 64x32.
// m16n8k16, BK=64, 3-stage cp.async, 110.6KB smem -> 2 CTAs/SM.
// ----------------------------------------------------------------------------
#define GPITCH 72
#define STG_HALVES ((128 + 128) * GPITCH)
#define MG_SMEM    (3 * STG_HALVES * 2)     // 110592 B

template <int MODE>
__global__ void __launch_bounds__(256, 2) mgemm(const float* __restrict__ bias,
                                                const float* __restrict__ resid,
                                                float* __restrict__ outp)
{
    constexpr int K = (MODE == 3) ? 4096 : 1024;
    constexpr int NKIT = K / 64;

    extern __shared__ __half smh[];
    const int tid = threadIdx.x, lane = tid & 31, wid = tid >> 5;
    const int wm = wid & 1, wn = wid >> 1;
    const int m0 = blockIdx.y * 128;
    const int n0 = blockIdx.x * 128;

    const __half* A;
    if      (MODE == 0) A = g_h1;
    else if (MODE == 1) A = g_attn;
    else if (MODE == 2) A = g_h2;
    else                A = g_ff1;

    const __half* B;
    if (MODE == 0) B = (blockIdx.z == 0) ? g_wqT : ((blockIdx.z == 1) ? g_wkT : g_wvT);
    else if (MODE == 1) B = g_wpT;
    else if (MODE == 2) B = g_wf1T;
    else                B = g_wf2T;

    float acc[4][4][4] = {};

    auto load_stage = [&](int j, int s) {
        __half* As = smh + s * STG_HALVES;
        __half* Bs = As + 128 * GPITCH;
#pragma unroll
        for (int i = 0; i < 4; i++) {
            int c = tid + i * 256;
            int row = c >> 3, kc = c & 7;
            cp16(smem_u32(As + row * GPITCH + kc * 8),
                 A + (size_t)(m0 + row) * K + j * 64 + kc * 8);
        }
#pragma unroll
        for (int i = 0; i < 4; i++) {
            int c = tid + i * 256;
            int row = c >> 3, kc = c & 7;
            cp16(smem_u32(Bs + row * GPITCH + kc * 8),
                 B + (size_t)(n0 + row) * K + j * 64 + kc * 8);
        }
        cp_commit();
    };

    const int arow = (lane & 7) + ((lane >> 3) & 1) * 8;
    const int ahalf = (lane >> 4) & 1;
    uint32_t offA[4], offB[2];
#pragma unroll
    for (int mi = 0; mi < 4; mi++)
        offA[mi] = ((wm * 64 + mi * 16 + arow) * GPITCH + ahalf * 8) * 2;
#pragma unroll
    for (int g = 0; g < 2; g++)
        offB[g] = ((wn * 32 + g * 16 + arow) * GPITCH + ahalf * 8) * 2;

    load_stage(0, 0);
    load_stage(1, 1);

    for (int it = 0; it < NKIT; it++) {
        int s = it % 3;
        cp_wait1();
        __syncthreads();
        if (it + 2 < NKIT) load_stage(it + 2, (it + 2) % 3);
        else cp_commit();

        uint32_t AsU = smem_u32(smh + s * STG_HALVES);
        uint32_t BsU = AsU + 128 * GPITCH * 2;

#pragma unroll
        for (int ks = 0; ks < 4; ks++) {
            uint32_t af[4][4], bb[2][4];
#pragma unroll
            for (int mi = 0; mi < 4; mi++) ldsm_x4(af[mi], AsU + offA[mi] + ks * 32);
#pragma unroll
            for (int g = 0; g < 2; g++)  ldsm_x4(bb[g], BsU + offB[g] + ks * 32);
#pragma unroll
            for (int mi = 0; mi < 4; mi++)
#pragma unroll
                for (int g = 0; g < 2; g++) {
                    uint32_t blo[2] = {bb[g][0], bb[g][2]};
                    uint32_t bhi[2] = {bb[g][1], bb[g][3]};
                    mma16(acc[mi][g * 2],     af[mi], blo);
                    mma16(acc[mi][g * 2 + 1], af[mi], bhi);
                }
        }
    }

#pragma unroll
    for (int mi = 0; mi < 4; mi++) {
#pragma unroll
        for (int nj = 0; nj < 4; nj++) {
#pragma unroll
            for (int half = 0; half < 2; half++) {
                int gm = m0 + wm * 64 + mi * 16 + (lane >> 2) + half * 8;
                int gn = n0 + wn * 32 + nj * 8 + (lane & 3) * 2;
                float v0 = acc[mi][nj][half * 2 + 0];
                float v1 = acc[mi][nj][half * 2 + 1];
                if (MODE == 0) {
                    int bb2 = gm >> 11, t = gm & 2047;
                    int h = gn >> 6, d0 = gn & 63;
                    __half* sel = (blockIdx.z == 0) ? g_q : ((blockIdx.z == 1) ? g_kk : g_v);
                    __half* op = sel + ((size_t)((bb2 * 16 + h) * 2048 + t)) * 64 + d0;
                    *(__half2*)op = __floats2half2_rn(v0, v1);
                } else if (MODE == 1) {
                    size_t o = (size_t)gm * 1024 + gn;
                    g_x1[o]     = v0 + bias[gn]     + resid[o];
                    g_x1[o + 1] = v1 + bias[gn + 1] + resid[o + 1];
                } else if (MODE == 2) {
                    size_t o = (size_t)gm * 4096 + gn;
                    *(__half2*)(g_ff1 + o) =
                        __floats2half2_rn(fmaxf(v0 + bias[gn], 0.f),
                                          fmaxf(v1 + bias[gn + 1], 0.f));
                } else {
                    size_t o = (size_t)gm * 1024 + gn;
                    outp[o]     = v0 + bias[gn]     + g_x1[o];
                    outp[o + 1] = v1 + bias[gn + 1] + g_x1[o + 1];
                }
            }
        }
    }
}

// ----------------------------------------------------------------------------
// fp16 tensor-core causal flash attention (V row-major, trans B-frags).
// ----------------------------------------------------------------------------
#define QPITCH 72
#define KPITCH 72
#define VPITCH 72
#define PPITCH 40
#define AT_KOFF (128 * QPITCH)
#define AT_VOFF (AT_KOFF + 2 * 32 * KPITCH)
#define AT_POFF (AT_VOFF + 2 * 32 * VPITCH)
#define AT_SMEM ((AT_POFF + 4 * 32 * PPITCH) * 2)  // 47104 B

__global__ void __launch_bounds__(128) attn_k()
{
    extern __shared__ __half smA[];
    const int tid = threadIdx.x, lane = tid & 31, wid = tid >> 5;
    const int bh = blockIdx.y;
    const int rb = (int)gridDim.x - 1 - (int)blockIdx.x;
    const int R0 = rb * 128;
    const size_t qkbase = (size_t)bh * TLEN * HS;

    uint32_t QsU = smem_u32(smA);
    uint32_t KsU[2], VtU[2];
    KsU[0] = QsU + AT_KOFF * 2;  KsU[1] = KsU[0] + 32 * KPITCH * 2;
    VtU[0] = QsU + AT_VOFF * 2;  VtU[1] = VtU[0] + 32 * VPITCH * 2;
    uint32_t PsU = QsU + (AT_POFF + wid * 32 * PPITCH) * 2;

    {
        const __half* src = g_q + qkbase + (size_t)R0 * 64;
#pragma unroll
        for (int i = 0; i < 8; i++) {
            int c = tid + i * 128;
            int row = c >> 3, ch = c & 7;
            cp16(QsU + (row * QPITCH + ch * 8) * 2, src + row * 64 + ch * 8);
        }
    }
    auto load_tile = [&](int kt, int b) {
        const __half* ks = g_kk + qkbase + (size_t)kt * 32 * 64;
        const __half* vs = g_v  + qkbase + (size_t)kt * 32 * 64;
#pragma unroll
        for (int i = 0; i < 2; i++) {
            int c = tid + i * 128;
            int row = c >> 3, ch = c & 7;
            cp16(KsU[b] + (row * KPITCH + ch * 8) * 2, ks + row * 64 + ch * 8);
            cp16(VtU[b] + (row * VPITCH + ch * 8) * 2, vs + row * 64 + ch * 8);
        }
    };

    const int NT = R0 / 32 + 4;
    const int maskstart = R0 / 32;

    load_tile(0, 0);
    cp_commit();

    const int arow = (lane & 7) + ((lane >> 3) & 1) * 8;
    const int ahalf = (lane >> 4) & 1;
    uint32_t offQ[2], offP[2], offK[2], offV[4];
#pragma unroll
    for (int mi = 0; mi < 2; mi++) {
        offQ[mi] = ((wid * 32 + mi * 16 + arow) * QPITCH + ahalf * 8) * 2;
        offP[mi] = ((mi * 16 + arow) * PPITCH + ahalf * 8) * 2;
    }
#pragma unroll
    for (int g = 0; g < 2; g++) offK[g] = ((g * 16 + arow) * KPITCH + ahalf * 8) * 2;
    const int vk = (lane & 7) + ((lane >> 4) & 1) * 8;
    const int vn = ((lane >> 3) & 1) * 8;
#pragma unroll
    for (int g = 0; g < 4; g++) offV[g] = (vk * VPITCH + g * 16 + vn) * 2;

    uint32_t qf[2][4][4];
    float oacc[2][8][4] = {};
    float m_run[4] = {-1e30f, -1e30f, -1e30f, -1e30f};
    float l_run[4] = {};

    const int srow = lane >> 2;
    const int scol = (lane & 3) * 2;

    for (int it = 0; it < NT; it++) {
        __syncthreads();
        if (it + 1 < NT) load_tile(it + 1, (it + 1) & 1);
        cp_commit();
        cp_wait1();
        __syncthreads();

        if (it == 0) {
            const __half2 sc = __float2half2_rn(0.125f);
#pragma unroll
            for (int mi = 0; mi < 2; mi++)
#pragma unroll
                for (int kt = 0; kt < 4; kt++) {
                    ldsm_x4(qf[mi][kt], QsU + offQ[mi] + kt * 32);
#pragma unroll
                    for (int i = 0; i < 4; i++) {
                        __half2 h = *(__half2*)&qf[mi][kt][i];
                        h = __hmul2(h, sc);
                        qf[mi][kt][i] = *(uint32_t*)&h;
                    }
                }
        }

        const uint32_t Kb = KsU[it & 1], Vb = VtU[it & 1];

        float sacc[2][4][4] = {};
#pragma unroll
        for (int kt = 0; kt < 4; kt++) {
#pragma unroll
            for (int g = 0; g < 2; g++) {
                uint32_t kb[4];
                ldsm_x4(kb, Kb + offK[g] + kt * 32);
                uint32_t blo[2] = {kb[0], kb[2]}, bhi[2] = {kb[1], kb[3]};
#pragma unroll
                for (int mi = 0; mi < 2; mi++) {
                    mma16(sacc[mi][g * 2],     qf[mi][kt], blo);
                    mma16(sacc[mi][g * 2 + 1], qf[mi][kt], bhi);
                }
            }
        }

        if (it >= maskstart) {
            const int colbase = it * 32 + scol;
#pragma unroll
            for (int mi = 0; mi < 2; mi++) {
                const int rowb = R0 + wid * 32 + mi * 16 + srow;
#pragma unroll
                for (int nt = 0; nt < 4; nt++)
#pragma unroll
                    for (int j = 0; j < 4; j++) {
                        int col = colbase + nt * 8 + (j & 1);
                        int row = rowb + 8 * (j >> 1);
                        if (col > row) sacc[mi][nt][j] = -1e30f;
                    }
            }
        }

#pragma unroll
        for (int mi = 0; mi < 2; mi++) {
#pragma unroll
            for (int hf = 0; hf < 2; hf++) {
                const int slot = mi * 2 + hf;
                float vmax = m_run[slot];
#pragma unroll
                for (int nt = 0; nt < 4; nt++) {
                    vmax = fmaxf(vmax, sacc[mi][nt][hf * 2]);
                    vmax = fmaxf(vmax, sacc[mi][nt][hf * 2 + 1]);
                }
                vmax = fmaxf(vmax, __shfl_xor_sync(0xffffffffu, vmax, 1));
                vmax = fmaxf(vmax, __shfl_xor_sync(0xffffffffu, vmax, 2));
                const float mnew = vmax;
                const float scale = __expf(m_run[slot] - mnew);
                float lsum = 0.f;
                const int prow = mi * 16 + srow + 8 * hf;
#pragma unroll
                for (int nt = 0; nt < 4; nt++) {
                    float p0 = __expf(sacc[mi][nt][hf * 2]     - mnew);
                    float p1 = __expf(sacc[mi][nt][hf * 2 + 1] - mnew);
                    lsum += p0 + p1;
                    __half2 ph = __floats2half2_rn(p0, p1);
                    asm volatile("st.shared.u32 [%0], %1;"
                                 :: "r"(PsU + (prow * PPITCH + nt * 8 + scol) * 2),
                                    "r"(*(uint32_t*)&ph) : "memory");
                }
                lsum += __shfl_xor_sync(0xffffffffu, lsum, 1);
                lsum += __shfl_xor_sync(0xffffffffu, lsum, 2);
                l_run[slot] = l_run[slot] * scale + lsum;
                m_run[slot] = mnew;
#pragma unroll
                for (int nt = 0; nt < 8; nt++) {
                    oacc[mi][nt][hf * 2]     *= scale;
                    oacc[mi][nt][hf * 2 + 1] *= scale;
                }
            }
        }

#pragma unroll
        for (int kt = 0; kt < 2; kt++) {
            uint32_t pa[2][4];
#pragma unroll
            for (int mi = 0; mi < 2; mi++) ldsm_x4(pa[mi], PsU + offP[mi] + kt * 32);
#pragma unroll
            for (int g = 0; g < 4; g++) {
                uint32_t vb[4];
                ldsm_x4t(vb, Vb + offV[g] + kt * 16 * VPITCH * 2);
                uint32_t blo[2] = {vb[0], vb[2]}, bhi[2] = {vb[1], vb[3]};
#pragma unroll
                for (int mi = 0; mi < 2; mi++) {
                    mma16(oacc[mi][g * 2],     pa[mi], blo);
                    mma16(oacc[mi][g * 2 + 1], pa[mi], bhi);
                }
            }
        }
    }

    const int b = bh >> 4, h = bh & 15;
#pragma unroll
    for (int mi = 0; mi < 2; mi++) {
#pragma unroll
        for (int hf = 0; hf < 2; hf++) {
            const float inv = 1.f / l_run[mi * 2 + hf];
            const int grow = R0 + wid * 32 + mi * 16 + srow + 8 * hf;
            __half* op = g_attn + ((size_t)(b * 2048 + grow)) * 1024 + h * 64 + scol;
#pragma unroll
            for (int nt = 0; nt < 8; nt++)
                *(__half2*)(op + nt * 8) =
                    __floats2half2_rn(oacc[mi][nt][hf * 2] * inv,
                                      oacc[mi][nt][hf * 2 + 1] * inv);
        }
    }
}

// ----------------------------------------------------------------------------
// Launch: ALL weight converts on background stream; main chain starts with LN1.
//   e1    = conv_qkv done  -> waited before QKV GEMM
//   ejoin = all converts   -> waited before proj GEMM
// ----------------------------------------------------------------------------
extern "C" void kernel_launch(void* const* d_in, const int* in_sizes, int n_in,
                              void* d_out, int out_size)
{
    const float* x     = (const float*)d_in[0];
    const float* Wq    = (const float*)d_in[1];
    const float* Wk    = (const float*)d_in[2];
    const float* Wv    = (const float*)d_in[3];
    const float* Wproj = (const float*)d_in[4];
    const float* bproj = (const float*)d_in[5];
    const float* g1    = (const float*)d_in[6];
    const float* b1    = (const float*)d_in[7];
    const float* g2    = (const float*)d_in[8];
    const float* b2    = (const float*)d_in[9];
    const float* Wff1  = (const float*)d_in[10];
    const float* bff1  = (const float*)d_in[11];
    const float* Wff2  = (const float*)d_in[12];
    const float* bff2  = (const float*)d_in[13];
    float* out = (float*)d_out;

    static cudaStream_t sbg = nullptr;
    static cudaEvent_t  efork = nullptr, e1 = nullptr, ejoin = nullptr;
    if (sbg == nullptr) {
        cudaStreamCreateWithFlags(&sbg, cudaStreamNonBlocking);
        cudaEventCreateWithFlags(&efork, cudaEventDisableTiming);
        cudaEventCreateWithFlags(&e1,    cudaEventDisableTiming);
        cudaEventCreateWithFlags(&ejoin, cudaEventDisableTiming);
        cudaFuncSetAttribute(mgemm<0>, cudaFuncAttributeMaxDynamicSharedMemorySize, MG_SMEM);
        cudaFuncSetAttribute(mgemm<1>, cudaFuncAttributeMaxDynamicSharedMemorySize, MG_SMEM);
        cudaFuncSetAttribute(mgemm<2>, cudaFuncAttributeMaxDynamicSharedMemorySize, MG_SMEM);
        cudaFuncSetAttribute(mgemm<3>, cudaFuncAttributeMaxDynamicSharedMemorySize, MG_SMEM);
        cudaFuncSetAttribute(attn_k,   cudaFuncAttributeMaxDynamicSharedMemorySize, AT_SMEM);
    }

    // fork: all weight converts in background
    cudaEventRecord(efork, 0);
    cudaStreamWaitEvent(sbg, efork, 0);
    conv_qkv<<<dim3(2, 32, 48), 256, 0, sbg>>>(Wq, Wk, Wv);
    cudaEventRecord(e1, sbg);
    conv_wp <<<dim3(32, 32),     256, 0, sbg>>>(Wproj);
    conv_ff <<<dim3(128, 32, 2), 256, 0, sbg>>>(Wff1, Wff2);
    cudaEventRecord(ejoin, sbg);

    // main chain: LN1 overlaps conv_qkv
    ln_k<<<MROWS / 8, 256>>>(0, x, g1, b1);
    cudaStreamWaitEvent(0, e1, 0);      // QKV needs g_wq/wk/wvT
    mgemm<0><<<dim3(CDIM / 128, MROWS / 128, 3), 256, MG_SMEM>>>(nullptr, nullptr, nullptr);
    attn_k<<<dim3(TLEN / 128, NHEAD * 2), 128, AT_SMEM>>>();

    cudaStreamWaitEvent(0, ejoin, 0);   // proj/FFN need g_wpT, g_wf1T, g_wf2T
    mgemm<1><<<dim3(CDIM / 128, MROWS / 128), 256, MG_SMEM>>>(bproj, x, nullptr);
    ln_k<<<MROWS / 8, 256>>>(1, nullptr, g2, b2);
    mgemm<2><<<dim3(FDIM / 128, MROWS / 128), 256, MG_SMEM>>>(bff1, nullptr, nullptr);
    mgemm<3><<<dim3(CDIM / 128, MROWS / 128), 256, MG_SMEM>>>(bff2, nullptr, out);
}

// round 14
// speedup vs baseline: 7.4893x; 1.0633x over previous
#include <cuda_runtime.h>
#include <cuda_fp16.h>
#include <cstdint>
#include <cstddef>

// ----------------------------------------------------------------------------
// B=2, T=2048, C=1024, H=16, hs=64 ; M = B*T = 4096
// Two independent per-batch chains (rows 0-2047 / 2048-4095) on two streams.
// ----------------------------------------------------------------------------
#define MROWS 4096
#define CDIM  1024
#define FDIM  4096
#define TLEN  2048
#define NHEAD 16
#define HS    64
#define MHALF (MROWS / 2)

__device__ __half g_h1[MROWS * CDIM];
__device__ __half g_q [MROWS * CDIM];          // [B,H,T,hs]
__device__ __half g_kk[MROWS * CDIM];
__device__ __half g_v [MROWS * CDIM];          // [B,H,T,hs] row-major
__device__ __half g_attn[MROWS * CDIM];
__device__ float  g_x1[MROWS * CDIM];          // fp32 residual path
__device__ __half g_h2[MROWS * CDIM];
__device__ __half g_ff1[(size_t)MROWS * FDIM];
__device__ __half g_wqT[CDIM * CDIM];          // Bt[n][k]
__device__ __half g_wkT[CDIM * CDIM];
__device__ __half g_wvT[CDIM * CDIM];
__device__ __half g_wpT[CDIM * CDIM];
__device__ __half g_wf1T[(size_t)CDIM * FDIM];
__device__ __half g_wf2T[(size_t)CDIM * FDIM];

// ----------------------------------------------------------------------------
// Helpers
// ----------------------------------------------------------------------------
__device__ __forceinline__ uint32_t smem_u32(const void* p) {
    return (uint32_t)__cvta_generic_to_shared(p);
}
__device__ __forceinline__ void cp16(uint32_t dst, const void* src) {
    asm volatile("cp.async.cg.shared.global [%0], [%1], 16;\n" :: "r"(dst), "l"(src));
}
__device__ __forceinline__ void cp_commit() {
    asm volatile("cp.async.commit_group;\n" ::: "memory");
}
__device__ __forceinline__ void cp_wait1() {
    asm volatile("cp.async.wait_group 1;\n" ::: "memory");
}
__device__ __forceinline__ void mma16(float* d, const uint32_t* a, const uint32_t* b) {
    asm volatile(
        "mma.sync.aligned.m16n8k16.row.col.f32.f16.f16.f32 "
        "{%0,%1,%2,%3},{%4,%5,%6,%7},{%8,%9},{%0,%1,%2,%3};"
        : "+f"(d[0]), "+f"(d[1]), "+f"(d[2]), "+f"(d[3])
        : "r"(a[0]), "r"(a[1]), "r"(a[2]), "r"(a[3]), "r"(b[0]), "r"(b[1]));
}
__device__ __forceinline__ void ldsm_x4(uint32_t* r, uint32_t addr) {
    asm volatile("ldmatrix.sync.aligned.m8n8.x4.shared.b16 {%0,%1,%2,%3}, [%4];"
                 : "=r"(r[0]), "=r"(r[1]), "=r"(r[2]), "=r"(r[3]) : "r"(addr));
}
__device__ __forceinline__ void ldsm_x4t(uint32_t* r, uint32_t addr) {
    asm volatile("ldmatrix.sync.aligned.m8n8.x4.trans.shared.b16 {%0,%1,%2,%3}, [%4];"
                 : "=r"(r[0]), "=r"(r[1]), "=r"(r[2]), "=r"(r[3]) : "r"(addr));
}

// ----------------------------------------------------------------------------
// LayerNorm: warp-per-row (8 rows/block); mbase = first row of this chain
// ----------------------------------------------------------------------------
__global__ void __launch_bounds__(256) ln_k(int mode, int mbase,
                                            const float* __restrict__ x_ext,
                                            const float* __restrict__ g,
                                            const float* __restrict__ b)
{
    const float* in = (mode == 0) ? x_ext : g_x1;
    __half* out     = (mode == 0) ? g_h1  : g_h2;
    const int lane = threadIdx.x & 31;
    const int row = mbase + blockIdx.x * 8 + (threadIdx.x >> 5);
    const size_t base = (size_t)row * CDIM;

    float4 v[8];
    float s = 0.f, s2 = 0.f;
#pragma unroll
    for (int i = 0; i < 8; i++) {
        v[i] = *(const float4*)(in + base + lane * 4 + i * 128);
        s  += v[i].x + v[i].y + v[i].z + v[i].w;
        s2 += v[i].x * v[i].x + v[i].y * v[i].y + v[i].z * v[i].z + v[i].w * v[i].w;
    }
#pragma unroll
    for (int off = 16; off; off >>= 1) {
        s  += __shfl_xor_sync(0xffffffffu, s,  off);
        s2 += __shfl_xor_sync(0xffffffffu, s2, off);
    }
    const float mu = s * (1.f / CDIM);
    const float rstd = rsqrtf(s2 * (1.f / CDIM) - mu * mu + 1e-5f);
#pragma unroll
    for (int i = 0; i < 8; i++) {
        int c = lane * 4 + i * 128;
        float4 gg = *(const float4*)(g + c);
        float4 bb = *(const float4*)(b + c);
        *(__half2*)(out + base + c) =
            __floats2half2_rn((v[i].x - mu) * rstd * gg.x + bb.x,
                              (v[i].y - mu) * rstd * gg.y + bb.y);
        *(__half2*)(out + base + c + 2) =
            __floats2half2_rn((v[i].z - mu) * rstd * gg.z + bb.z,
                              (v[i].w - mu) * rstd * gg.w + bb.w);
    }
}

// ----------------------------------------------------------------------------
// Weight convert+transpose (fp32 [r][c] -> fp16 [c][r]), 32x32 tiles.
// ----------------------------------------------------------------------------
__device__ __forceinline__ void tr_tile(const float* __restrict__ ip,
                                        __half* __restrict__ op,
                                        int R, int Cc, int c0, int r0)
{
    __shared__ float t[32][33];
    int tx = threadIdx.x & 31, ty = threadIdx.x >> 5;
#pragma unroll
    for (int i = 0; i < 32; i += 8)
        t[ty + i][tx] = ip[(size_t)(r0 + ty + i) * Cc + c0 + tx];
    __syncthreads();
#pragma unroll
    for (int i = 0; i < 32; i += 8)
        op[(size_t)(c0 + ty + i) * R + r0 + tx] = __float2half(t[tx][ty + i]);
}

__global__ void __launch_bounds__(256) conv_qkv(const float* __restrict__ Wq,
                                                const float* __restrict__ Wk,
                                                const float* __restrict__ Wv)
{
    int m = blockIdx.z >> 4, batch = blockIdx.z & 15;
    const float* src = (m == 0) ? Wq : ((m == 1) ? Wk : Wv);
    __half* dst = (m == 0) ? g_wqT : ((m == 1) ? g_wkT : g_wvT);
    tr_tile(src + (size_t)batch * CDIM * HS, dst + (size_t)batch * CDIM * HS,
            CDIM, HS, blockIdx.x * 32, blockIdx.y * 32);
}

__global__ void __launch_bounds__(256) conv_wp(const float* __restrict__ Wp)
{
    tr_tile(Wp, g_wpT, CDIM, CDIM, blockIdx.x * 32, blockIdx.y * 32);
}

__global__ void __launch_bounds__(256) conv_ff(const float* __restrict__ W1,
                                               const float* __restrict__ W2)
{
    int id = blockIdx.x * 32 + blockIdx.y;
    if (blockIdx.z == 0) {
        int c_t = id & 127, r_t = id >> 7;
        tr_tile(W1, g_wf1T, CDIM, FDIM, c_t * 32, r_t * 32);
    } else {
        int c_t = id & 31, r_t = id >> 5;
        tr_tile(W2, g_wf2T, FDIM, CDIM, c_t * 32, r_t * 32);
    }
}

// ----------------------------------------------------------------------------
// fp16 mma.sync GEMM, CTA tile 128x128, 8 warps, warp 64x32; 2 CTAs/SM.
// mbase = row offset of this chain's half.
// ----------------------------------------------------------------------------
#define GPITCH 72
#define STG_HALVES ((128 + 128) * GPITCH)
#define MG_SMEM    (3 * STG_HALVES * 2)     // 110592 B

template <int MODE>
__global__ void __launch_bounds__(256, 2) mgemm(int mbase,
                                                const float* __restrict__ bias,
                                                const float* __restrict__ resid,
                                                float* __restrict__ outp)
{
    constexpr int K = (MODE == 3) ? 4096 : 1024;
    constexpr int NKIT = K / 64;

    extern __shared__ __half smh[];
    const int tid = threadIdx.x, lane = tid & 31, wid = tid >> 5;
    const int wm = wid & 1, wn = wid >> 1;
    const int m0 = mbase + blockIdx.y * 128;
    const int n0 = blockIdx.x * 128;

    const __half* A;
    if      (MODE == 0) A = g_h1;
    else if (MODE == 1) A = g_attn;
    else if (MODE == 2) A = g_h2;
    else                A = g_ff1;

    const __half* B;
    if (MODE == 0) B = (blockIdx.z == 0) ? g_wqT : ((blockIdx.z == 1) ? g_wkT : g_wvT);
    else if (MODE == 1) B = g_wpT;
    else if (MODE == 2) B = g_wf1T;
    else                B = g_wf2T;

    float acc[4][4][4] = {};

    auto load_stage = [&](int j, int s) {
        __half* As = smh + s * STG_HALVES;
        __half* Bs = As + 128 * GPITCH;
#pragma unroll
        for (int i = 0; i < 4; i++) {
            int c = tid + i * 256;
            int row = c >> 3, kc = c & 7;
            cp16(smem_u32(As + row * GPITCH + kc * 8),
                 A + (size_t)(m0 + row) * K + j * 64 + kc * 8);
        }
#pragma unroll
        for (int i = 0; i < 4; i++) {
            int c = tid + i * 256;
            int row = c >> 3, kc = c & 7;
            cp16(smem_u32(Bs + row * GPITCH + kc * 8),
                 B + (size_t)(n0 + row) * K + j * 64 + kc * 8);
        }
        cp_commit();
    };

    const int arow = (lane & 7) + ((lane >> 3) & 1) * 8;
    const int ahalf = (lane >> 4) & 1;
    uint32_t offA[4], offB[2];
#pragma unroll
    for (int mi = 0; mi < 4; mi++)
        offA[mi] = ((wm * 64 + mi * 16 + arow) * GPITCH + ahalf * 8) * 2;
#pragma unroll
    for (int g = 0; g < 2; g++)
        offB[g] = ((wn * 32 + g * 16 + arow) * GPITCH + ahalf * 8) * 2;

    load_stage(0, 0);
    load_stage(1, 1);

    for (int it = 0; it < NKIT; it++) {
        int s = it % 3;
        cp_wait1();
        __syncthreads();
        if (it + 2 < NKIT) load_stage(it + 2, (it + 2) % 3);
        else cp_commit();

        uint32_t AsU = smem_u32(smh + s * STG_HALVES);
        uint32_t BsU = AsU + 128 * GPITCH * 2;

#pragma unroll
        for (int ks = 0; ks < 4; ks++) {
            uint32_t af[4][4], bb[2][4];
#pragma unroll
            for (int mi = 0; mi < 4; mi++) ldsm_x4(af[mi], AsU + offA[mi] + ks * 32);
#pragma unroll
            for (int g = 0; g < 2; g++)  ldsm_x4(bb[g], BsU + offB[g] + ks * 32);
#pragma unroll
            for (int mi = 0; mi < 4; mi++)
#pragma unroll
                for (int g = 0; g < 2; g++) {
                    uint32_t blo[2] = {bb[g][0], bb[g][2]};
                    uint32_t bhi[2] = {bb[g][1], bb[g][3]};
                    mma16(acc[mi][g * 2],     af[mi], blo);
                    mma16(acc[mi][g * 2 + 1], af[mi], bhi);
                }
        }
    }

#pragma unroll
    for (int mi = 0; mi < 4; mi++) {
#pragma unroll
        for (int nj = 0; nj < 4; nj++) {
#pragma unroll
            for (int half = 0; half < 2; half++) {
                int gm = m0 + wm * 64 + mi * 16 + (lane >> 2) + half * 8;
                int gn = n0 + wn * 32 + nj * 8 + (lane & 3) * 2;
                float v0 = acc[mi][nj][half * 2 + 0];
                float v1 = acc[mi][nj][half * 2 + 1];
                if (MODE == 0) {
                    int bb2 = gm >> 11, t = gm & 2047;
                    int h = gn >> 6, d0 = gn & 63;
                    __half* sel = (blockIdx.z == 0) ? g_q : ((blockIdx.z == 1) ? g_kk : g_v);
                    __half* op = sel + ((size_t)((bb2 * 16 + h) * 2048 + t)) * 64 + d0;
                    *(__half2*)op = __floats2half2_rn(v0, v1);
                } else if (MODE == 1) {
                    size_t o = (size_t)gm * 1024 + gn;
                    g_x1[o]     = v0 + bias[gn]     + resid[o];
                    g_x1[o + 1] = v1 + bias[gn + 1] + resid[o + 1];
                } else if (MODE == 2) {
                    size_t o = (size_t)gm * 4096 + gn;
                    *(__half2*)(g_ff1 + o) =
                        __floats2half2_rn(fmaxf(v0 + bias[gn], 0.f),
                                          fmaxf(v1 + bias[gn + 1], 0.f));
                } else {
                    size_t o = (size_t)gm * 1024 + gn;
                    outp[o]     = v0 + bias[gn]     + g_x1[o];
                    outp[o + 1] = v1 + bias[gn + 1] + g_x1[o + 1];
                }
            }
        }
    }
}

// ----------------------------------------------------------------------------
// fp16 tensor-core causal flash attention; bhbase selects this chain's batch.
// ----------------------------------------------------------------------------
#define QPITCH 72
#define KPITCH 72
#define VPITCH 72
#define PPITCH 40
#define AT_KOFF (128 * QPITCH)
#define AT_VOFF (AT_KOFF + 2 * 32 * KPITCH)
#define AT_POFF (AT_VOFF + 2 * 32 * VPITCH)
#define AT_SMEM ((AT_POFF + 4 * 32 * PPITCH) * 2)  // 47104 B

__global__ void __launch_bounds__(128) attn_k(int bhbase)
{
    extern __shared__ __half smA[];
    const int tid = threadIdx.x, lane = tid & 31, wid = tid >> 5;
    const int bh = bhbase + blockIdx.y;
    const int rb = (int)gridDim.x - 1 - (int)blockIdx.x;
    const int R0 = rb * 128;
    const size_t qkbase = (size_t)bh * TLEN * HS;

    uint32_t QsU = smem_u32(smA);
    uint32_t KsU[2], VtU[2];
    KsU[0] = QsU + AT_KOFF * 2;  KsU[1] = KsU[0] + 32 * KPITCH * 2;
    VtU[0] = QsU + AT_VOFF * 2;  VtU[1] = VtU[0] + 32 * VPITCH * 2;
    uint32_t PsU = QsU + (AT_POFF + wid * 32 * PPITCH) * 2;

    {
        const __half* src = g_q + qkbase + (size_t)R0 * 64;
#pragma unroll
        for (int i = 0; i < 8; i++) {
            int c = tid + i * 128;
            int row = c >> 3, ch = c & 7;
            cp16(QsU + (row * QPITCH + ch * 8) * 2, src + row * 64 + ch * 8);
        }
    }
    auto load_tile = [&](int kt, int b) {
        const __half* ks = g_kk + qkbase + (size_t)kt * 32 * 64;
        const __half* vs = g_v  + qkbase + (size_t)kt * 32 * 64;
#pragma unroll
        for (int i = 0; i < 2; i++) {
            int c = tid + i * 128;
            int row = c >> 3, ch = c & 7;
            cp16(KsU[b] + (row * KPITCH + ch * 8) * 2, ks + row * 64 + ch * 8);
            cp16(VtU[b] + (row * VPITCH + ch * 8) * 2, vs + row * 64 + ch * 8);
        }
    };

    const int NT = R0 / 32 + 4;
    const int maskstart = R0 / 32;

    load_tile(0, 0);
    cp_commit();

    const int arow = (lane & 7) + ((lane >> 3) & 1) * 8;
    const int ahalf = (lane >> 4) & 1;
    uint32_t offQ[2], offP[2], offK[2], offV[4];
#pragma unroll
    for (int mi = 0; mi < 2; mi++) {
        offQ[mi] = ((wid * 32 + mi * 16 + arow) * QPITCH + ahalf * 8) * 2;
        offP[mi] = ((mi * 16 + arow) * PPITCH + ahalf * 8) * 2;
    }
#pragma unroll
    for (int g = 0; g < 2; g++) offK[g] = ((g * 16 + arow) * KPITCH + ahalf * 8) * 2;
    const int vk = (lane & 7) + ((lane >> 4) & 1) * 8;
    const int vn = ((lane >> 3) & 1) * 8;
#pragma unroll
    for (int g = 0; g < 4; g++) offV[g] = (vk * VPITCH + g * 16 + vn) * 2;

    uint32_t qf[2][4][4];
    float oacc[2][8][4] = {};
    float m_run[4] = {-1e30f, -1e30f, -1e30f, -1e30f};
    float l_run[4] = {};

    const int srow = lane >> 2;
    const int scol = (lane & 3) * 2;

    for (int it = 0; it < NT; it++) {
        __syncthreads();
        if (it + 1 < NT) load_tile(it + 1, (it + 1) & 1);
        cp_commit();
        cp_wait1();
        __syncthreads();

        if (it == 0) {
            const __half2 sc = __float2half2_rn(0.125f);
#pragma unroll
            for (int mi = 0; mi < 2; mi++)
#pragma unroll
                for (int kt = 0; kt < 4; kt++) {
                    ldsm_x4(qf[mi][kt], QsU + offQ[mi] + kt * 32);
#pragma unroll
                    for (int i = 0; i < 4; i++) {
                        __half2 h = *(__half2*)&qf[mi][kt][i];
                        h = __hmul2(h, sc);
                        qf[mi][kt][i] = *(uint32_t*)&h;
                    }
                }
        }

        const uint32_t Kb = KsU[it & 1], Vb = VtU[it & 1];

        float sacc[2][4][4] = {};
#pragma unroll
        for (int kt = 0; kt < 4; kt++) {
#pragma unroll
            for (int g = 0; g < 2; g++) {
                uint32_t kb[4];
                ldsm_x4(kb, Kb + offK[g] + kt * 32);
                uint32_t blo[2] = {kb[0], kb[2]}, bhi[2] = {kb[1], kb[3]};
#pragma unroll
                for (int mi = 0; mi < 2; mi++) {
                    mma16(sacc[mi][g * 2],     qf[mi][kt], blo);
                    mma16(sacc[mi][g * 2 + 1], qf[mi][kt], bhi);
                }
            }
        }

        if (it >= maskstart) {
            const int colbase = it * 32 + scol;
#pragma unroll
            for (int mi = 0; mi < 2; mi++) {
                const int rowb = R0 + wid * 32 + mi * 16 + srow;
#pragma unroll
                for (int nt = 0; nt < 4; nt++)
#pragma unroll
                    for (int j = 0; j < 4; j++) {
                        int col = colbase + nt * 8 + (j & 1);
                        int row = rowb + 8 * (j >> 1);
                        if (col > row) sacc[mi][nt][j] = -1e30f;
                    }
            }
        }

#pragma unroll
        for (int mi = 0; mi < 2; mi++) {
#pragma unroll
            for (int hf = 0; hf < 2; hf++) {
                const int slot = mi * 2 + hf;
                float vmax = m_run[slot];
#pragma unroll
                for (int nt = 0; nt < 4; nt++) {
                    vmax = fmaxf(vmax, sacc[mi][nt][hf * 2]);
                    vmax = fmaxf(vmax, sacc[mi][nt][hf * 2 + 1]);
                }
                vmax = fmaxf(vmax, __shfl_xor_sync(0xffffffffu, vmax, 1));
                vmax = fmaxf(vmax, __shfl_xor_sync(0xffffffffu, vmax, 2));
                const float mnew = vmax;
                const float scale = __expf(m_run[slot] - mnew);
                float lsum = 0.f;
                const int prow = mi * 16 + srow + 8 * hf;
#pragma unroll
                for (int nt = 0; nt < 4; nt++) {
                    float p0 = __expf(sacc[mi][nt][hf * 2]     - mnew);
                    float p1 = __expf(sacc[mi][nt][hf * 2 + 1] - mnew);
                    lsum += p0 + p1;
                    __half2 ph = __floats2half2_rn(p0, p1);
                    asm volatile("st.shared.u32 [%0], %1;"
                                 :: "r"(PsU + (prow * PPITCH + nt * 8 + scol) * 2),
                                    "r"(*(uint32_t*)&ph) : "memory");
                }
                lsum += __shfl_xor_sync(0xffffffffu, lsum, 1);
                lsum += __shfl_xor_sync(0xffffffffu, lsum, 2);
                l_run[slot] = l_run[slot] * scale + lsum;
                m_run[slot] = mnew;
#pragma unroll
                for (int nt = 0; nt < 8; nt++) {
                    oacc[mi][nt][hf * 2]     *= scale;
                    oacc[mi][nt][hf * 2 + 1] *= scale;
                }
            }
        }

#pragma unroll
        for (int kt = 0; kt < 2; kt++) {
            uint32_t pa[2][4];
#pragma unroll
            for (int mi = 0; mi < 2; mi++) ldsm_x4(pa[mi], PsU + offP[mi] + kt * 32);
#pragma unroll
            for (int g = 0; g < 4; g++) {
                uint32_t vb[4];
                ldsm_x4t(vb, Vb + offV[g] + kt * 16 * VPITCH * 2);
                uint32_t blo[2] = {vb[0], vb[2]}, bhi[2] = {vb[1], vb[3]};
#pragma unroll
                for (int mi = 0; mi < 2; mi++) {
                    mma16(oacc[mi][g * 2],     pa[mi], blo);
                    mma16(oacc[mi][g * 2 + 1], pa[mi], bhi);
                }
            }
        }
    }

    const int b = bh >> 4, h = bh & 15;
#pragma unroll
    for (int mi = 0; mi < 2; mi++) {
#pragma unroll
        for (int hf = 0; hf < 2; hf++) {
            const float inv = 1.f / l_run[mi * 2 + hf];
            const int grow = R0 + wid * 32 + mi * 16 + srow + 8 * hf;
            __half* op = g_attn + ((size_t)(b * 2048 + grow)) * 1024 + h * 64 + scol;
#pragma unroll
            for (int nt = 0; nt < 8; nt++)
                *(__half2*)(op + nt * 8) =
                    __floats2half2_rn(oacc[mi][nt][hf * 2] * inv,
                                      oacc[mi][nt][hf * 2 + 1] * inv);
        }
    }
}

// ----------------------------------------------------------------------------
// Launch: two independent per-batch chains (stream 0 = batch 0, sB = batch 1),
// weight converts on sW. Each chain's kernel tails are backfilled by the other.
// ----------------------------------------------------------------------------
extern "C" void kernel_launch(void* const* d_in, const int* in_sizes, int n_in,
                              void* d_out, int out_size)
{
    const float* x     = (const float*)d_in[0];
    const float* Wq    = (const float*)d_in[1];
    const float* Wk    = (const float*)d_in[2];
    const float* Wv    = (const float*)d_in[3];
    const float* Wproj = (const float*)d_in[4];
    const float* bproj = (const float*)d_in[5];
    const float* g1    = (const float*)d_in[6];
    const float* b1    = (const float*)d_in[7];
    const float* g2    = (const float*)d_in[8];
    const float* b2    = (const float*)d_in[9];
    const float* Wff1  = (const float*)d_in[10];
    const float* bff1  = (const float*)d_in[11];
    const float* Wff2  = (const float*)d_in[12];
    const float* bff2  = (const float*)d_in[13];
    float* out = (float*)d_out;

    static cudaStream_t sW = nullptr, sB = nullptr;
    static cudaEvent_t efork = nullptr, e_qkv = nullptr, e_all = nullptr, eB = nullptr;
    if (sW == nullptr) {
        cudaStreamCreateWithFlags(&sW, cudaStreamNonBlocking);
        cudaStreamCreateWithFlags(&sB, cudaStreamNonBlocking);
        cudaEventCreateWithFlags(&efork, cudaEventDisableTiming);
        cudaEventCreateWithFlags(&e_qkv, cudaEventDisableTiming);
        cudaEventCreateWithFlags(&e_all, cudaEventDisableTiming);
        cudaEventCreateWithFlags(&eB,    cudaEventDisableTiming);
        cudaFuncSetAttribute(mgemm<0>, cudaFuncAttributeMaxDynamicSharedMemorySize, MG_SMEM);
        cudaFuncSetAttribute(mgemm<1>, cudaFuncAttributeMaxDynamicSharedMemorySize, MG_SMEM);
        cudaFuncSetAttribute(mgemm<2>, cudaFuncAttributeMaxDynamicSharedMemorySize, MG_SMEM);
        cudaFuncSetAttribute(mgemm<3>, cudaFuncAttributeMaxDynamicSharedMemorySize, MG_SMEM);
        cudaFuncSetAttribute(attn_k,   cudaFuncAttributeMaxDynamicSharedMemorySize, AT_SMEM);
    }

    // fork both auxiliary streams from stream 0
    cudaEventRecord(efork, 0);
    cudaStreamWaitEvent(sW, efork, 0);
    cudaStreamWaitEvent(sB, efork, 0);

    // weight converts (sW)
    conv_qkv<<<dim3(2, 32, 48), 256, 0, sW>>>(Wq, Wk, Wv);
    cudaEventRecord(e_qkv, sW);
    conv_wp <<<dim3(32, 32),     256, 0, sW>>>(Wproj);
    conv_ff <<<dim3(128, 32, 2), 256, 0, sW>>>(Wff1, Wff2);
    cudaEventRecord(e_all, sW);

    const dim3 ggrid(CDIM / 128, MHALF / 128);
    const dim3 ggrid3(CDIM / 128, MHALF / 128, 3);
    const dim3 fgrid(FDIM / 128, MHALF / 128);
    const dim3 agrid(TLEN / 128, NHEAD);

    // ---- chain A: batch 0 (rows 0..2047) on stream 0 ----
    ln_k<<<MHALF / 8, 256>>>(0, 0, x, g1, b1);
    cudaStreamWaitEvent(0, e_qkv, 0);
    mgemm<0><<<ggrid3, 256, MG_SMEM>>>(0, nullptr, nullptr, nullptr);
    attn_k<<<agrid, 128, AT_SMEM>>>(0);
    cudaStreamWaitEvent(0, e_all, 0);
    mgemm<1><<<ggrid, 256, MG_SMEM>>>(0, bproj, x, nullptr);
    ln_k<<<MHALF / 8, 256>>>(1, 0, nullptr, g2, b2);
    mgemm<2><<<fgrid, 256, MG_SMEM>>>(0, bff1, nullptr, nullptr);
    mgemm<3><<<ggrid, 256, MG_SMEM>>>(0, bff2, nullptr, out);

    // ---- chain B: batch 1 (rows 2048..4095) on sB ----
    ln_k<<<MHALF / 8, 256, 0, sB>>>(0, MHALF, x, g1, b1);
    cudaStreamWaitEvent(sB, e_qkv, 0);
    mgemm<0><<<ggrid3, 256, MG_SMEM, sB>>>(MHALF, nullptr, nullptr, nullptr);
    attn_k<<<agrid, 128, AT_SMEM, sB>>>(NHEAD);
    cudaStreamWaitEvent(sB, e_all, 0);
    mgemm<1><<<ggrid, 256, MG_SMEM, sB>>>(MHALF, bproj, x, nullptr);
    ln_k<<<MHALF / 8, 256, 0, sB>>>(1, MHALF, nullptr, g2, b2);
    mgemm<2><<<fgrid, 256, MG_SMEM, sB>>>(MHALF, bff1, nullptr, nullptr);
    mgemm<3><<<ggrid, 256, MG_SMEM, sB>>>(MHALF, bff2, nullptr, out);
    cudaEventRecord(eB, sB);

    // join chain B back into stream 0 (required for capture; makes completion
    // depend on both chains)
    cudaStreamWaitEvent(0, eB, 0);
}